// round 2
// baseline (speedup 1.0000x reference)
#include <cuda_runtime.h>
#include <cuda_bf16.h>
#include <math.h>

// ---------------- problem constants ----------------
#define MAX_N 50000
#define MAX_E 200000
#define H 256
#define ATOM_IN 133
#define BOND_IN 14
#define NUM_TASKS 12
#define NUM_GRAPHS 256
#define DEPTH 3
#define EPS 1e-5f

// ---------------- scratch (device globals; no allocation allowed) ----------------
__device__ float g_a_all[(size_t)MAX_N * (32 + ATOM_IN)];      // [N,165]
__device__ float g_h_all[(size_t)MAX_N * H];                   // [N,256] (reused as atom_out tmp)
__device__ float g_e_all[(size_t)MAX_E * H];                   // [E,256]
__device__ float g_h_e  [(size_t)(2*MAX_E) * H];               // [2E,256]
__device__ float g_bufA [(size_t)(2*MAX_E) * H];               // m_excl
__device__ float g_bufM [(size_t)(2*MAX_E) * H];               // M then h_new (in place)
__device__ float g_GI   [(size_t)(2*MAX_E) * 3 * H];           // [2E,768]
__device__ float g_GH   [(size_t)(2*MAX_E) * 3 * H];           // [2E,768]
__device__ float g_m_in [(size_t)MAX_N * H];                   // segment sums
__device__ float g_WihT [H * 3 * H];                           // [256,768]
__device__ float g_WhhT [H * 3 * H];                           // [256,768]
__device__ float g_hgraph[NUM_GRAPHS * H];

static inline int cdiv(int a, int b) { return (a + b - 1) / b; }

// ---------------- generic tiled SGEMM: C[M,N] = A[M,K] @ B[K,N] ----------------
#define BM 128
#define BN 64
#define BK 16
#define TM 8
#define TN 4

template<bool BIAS, bool RELU, bool ACCUM>
__global__ __launch_bounds__(256) void sgemm_kernel(
    const float* __restrict__ A, const float* __restrict__ B,
    const float* __restrict__ bias, float* __restrict__ C,
    int M, int N, int K)
{
    __shared__ float As[BK][BM + 4];
    __shared__ float Bs[BK][BN];

    const int tid = threadIdx.x;
    const int block_row = blockIdx.y * BM;
    const int block_col = blockIdx.x * BN;
    const int tx = tid % 16;      // column group (TN each)
    const int ty = tid / 16;      // row group (TM each)

    float acc[TM][TN];
    #pragma unroll
    for (int i = 0; i < TM; i++)
        #pragma unroll
        for (int j = 0; j < TN; j++) acc[i][j] = 0.f;

    const int a_k = tid % BK;     // 0..15
    const int a_m = tid / BK;     // 0..15
    const int b_n = tid % BN;     // 0..63
    const int b_k = tid / BN;     // 0..3

    for (int k0 = 0; k0 < K; k0 += BK) {
        #pragma unroll
        for (int i = 0; i < 8; i++) {
            int m  = a_m + i * 16;
            int gr = block_row + m;
            int gk = k0 + a_k;
            As[a_k][m] = (gr < M && gk < K) ? A[(size_t)gr * K + gk] : 0.f;
        }
        #pragma unroll
        for (int i = 0; i < 4; i++) {
            int kk = b_k + i * 4;
            int gk = k0 + kk;
            int gc = block_col + b_n;
            Bs[kk][b_n] = (gk < K && gc < N) ? B[(size_t)gk * N + gc] : 0.f;
        }
        __syncthreads();

        #pragma unroll
        for (int kk = 0; kk < BK; kk++) {
            float a[TM], b[TN];
            #pragma unroll
            for (int i = 0; i < TM; i++) a[i] = As[kk][ty * TM + i];
            #pragma unroll
            for (int j = 0; j < TN; j++) b[j] = Bs[kk][tx * TN + j];
            #pragma unroll
            for (int i = 0; i < TM; i++)
                #pragma unroll
                for (int j = 0; j < TN; j++)
                    acc[i][j] += a[i] * b[j];
        }
        __syncthreads();
    }

    #pragma unroll
    for (int i = 0; i < TM; i++) {
        int gr = block_row + ty * TM + i;
        if (gr >= M) continue;
        #pragma unroll
        for (int j = 0; j < TN; j++) {
            int gc = block_col + tx * TN + j;
            if (gc >= N) continue;
            float v = acc[i][j];
            if (BIAS)  v += bias[gc];
            if (ACCUM) v += C[(size_t)gr * N + gc];
            if (RELU)  v = fmaxf(v, 0.f);
            C[(size_t)gr * N + gc] = v;
        }
    }
}

// ---------------- small helper kernels ----------------

// block reduce over 256 threads
__device__ __forceinline__ float block_sum_256(float v, float* sh) {
    #pragma unroll
    for (int o = 16; o > 0; o >>= 1) v += __shfl_down_sync(0xffffffffu, v, o);
    int warp = threadIdx.x >> 5, lane = threadIdx.x & 31;
    if (lane == 0) sh[warp] = v;
    __syncthreads();
    if (warp == 0) {
        v = (lane < 8) ? sh[lane] : 0.f;
        #pragma unroll
        for (int o = 4; o > 0; o >>= 1) v += __shfl_down_sync(0xffffffffu, v, o);
        if (lane == 0) sh[0] = v;
    }
    __syncthreads();
    float r = sh[0];
    __syncthreads();
    return r;
}

__global__ void build_a_all_kernel(const int* __restrict__ x_z,
                                   const float* __restrict__ x_atom,
                                   const float* __restrict__ embed_z,
                                   float* __restrict__ a_all, int N)
{
    const int AW = 32 + ATOM_IN; // 165
    size_t idx = (size_t)blockIdx.x * blockDim.x + threadIdx.x;
    size_t total = (size_t)N * AW;
    for (; idx < total; idx += (size_t)gridDim.x * blockDim.x) {
        int n = (int)(idx / AW);
        int c = (int)(idx % AW);
        float v;
        if (c < 32) v = embed_z[x_z[n] * 32 + c];
        else        v = x_atom[(size_t)n * ATOM_IN + (c - 32)];
        a_all[idx] = v;
    }
}

// W [3H, H] row-major  ->  WT [H, 3H]
__global__ void transpose_w_kernel(const float* __restrict__ W, float* __restrict__ WT)
{
    int idx = blockIdx.x * blockDim.x + threadIdx.x;
    int total = 3 * H * H;
    if (idx >= total) return;
    int j = idx / H;   // 0..767 row of W
    int k = idx % H;   // 0..255
    WT[k * (3 * H) + j] = W[idx];
}

// h_e[d] = LN(relu(h_all[src_dir[d]] + e_all[d % E]))
__global__ void edge_init_kernel(const int* __restrict__ ei,
                                 const float* __restrict__ h_all,
                                 const float* __restrict__ e_all,
                                 const float* __restrict__ g, const float* __restrict__ be,
                                 float* __restrict__ h_e, int E)
{
    int d = blockIdx.x;
    int c = threadIdx.x;
    int src = ei[d];                      // src_dir[d] == ei[d] for all d in [0,2E)
    int e   = (d < E) ? d : d - E;
    float x = h_all[(size_t)src * H + c] + e_all[(size_t)e * H + c];
    x = fmaxf(x, 0.f);
    __shared__ float sh[8];
    float mu  = block_sum_256(x, sh) * (1.f / H);
    float dx  = x - mu;
    float var = block_sum_256(dx * dx, sh) * (1.f / H);
    float y   = dx * rsqrtf(var + EPS) * g[c] + be[c];
    h_e[(size_t)d * H + c] = y;
}

__global__ void zero_kernel(float* __restrict__ p, size_t n)
{
    size_t i = (size_t)blockIdx.x * blockDim.x + threadIdx.x;
    for (; i < n; i += (size_t)gridDim.x * blockDim.x) p[i] = 0.f;
}

// m_in[dst_dir[d]] += h_e[d]
__global__ void scatter_kernel(const float* __restrict__ h_e, const int* __restrict__ ei,
                               float* __restrict__ m_in, int E)
{
    int d = blockIdx.x;
    int c = threadIdx.x;
    int dst = (d < E) ? ei[E + d] : ei[d - E];
    atomicAdd(&m_in[(size_t)dst * H + c], h_e[(size_t)d * H + c]);
}

// m_excl[d] = m_in[src_dir[d]] - h_e[rev[d]]
__global__ void gather_kernel(const float* __restrict__ m_in, const float* __restrict__ h_e,
                              const int* __restrict__ ei, float* __restrict__ out, int E)
{
    int d = blockIdx.x;
    int c = threadIdx.x;
    int src = ei[d];
    int rv  = (d < E) ? d + E : d - E;
    out[(size_t)d * H + c] = m_in[(size_t)src * H + c] - h_e[(size_t)rv * H + c];
}

// Mbuf = relu(h_e + Mbuf), elementwise (float4)
__global__ void hnew_kernel(const float* __restrict__ h_e, float* __restrict__ Mbuf, size_t n4)
{
    size_t i = (size_t)blockIdx.x * blockDim.x + threadIdx.x;
    const float4* a = (const float4*)h_e;
    float4* b = (float4*)Mbuf;
    for (; i < n4; i += (size_t)gridDim.x * blockDim.x) {
        float4 x = a[i], y = b[i];
        y.x = fmaxf(x.x + y.x, 0.f);
        y.y = fmaxf(x.y + y.y, 0.f);
        y.z = fmaxf(x.z + y.z, 0.f);
        y.w = fmaxf(x.w + y.w, 0.f);
        b[i] = y;
    }
}

__device__ __forceinline__ float sigmoidf_(float x) { return 1.f / (1.f + expf(-x)); }

// GRU combine + LN per directed edge row
__global__ void gru_ln_kernel(const float* __restrict__ GI, const float* __restrict__ GH,
                              const float* __restrict__ h_e_in,
                              const float* __restrict__ g, const float* __restrict__ be,
                              float* __restrict__ h_e_out)
{
    int d = blockIdx.x;
    int j = threadIdx.x;
    size_t base = (size_t)d * (3 * H);
    float gir = GI[base + j], giz = GI[base + H + j], gin = GI[base + 2 * H + j];
    float ghr = GH[base + j], ghz = GH[base + H + j], ghn = GH[base + 2 * H + j];
    float hprev = h_e_in[(size_t)d * H + j];
    float r = sigmoidf_(gir + ghr);
    float z = sigmoidf_(giz + ghz);
    float n = tanhf(gin + r * ghn);
    float h = (1.f - z) * n + z * hprev;
    __shared__ float sh[8];
    float mu  = block_sum_256(h, sh) * (1.f / H);
    float dx  = h - mu;
    float var = block_sum_256(dx * dx, sh) * (1.f / H);
    float y   = dx * rsqrtf(var + EPS) * g[j] + be[j];
    h_e_out[(size_t)d * H + j] = y;
}

// relu + LN per node row, write to out
__global__ void relu_ln_kernel(const float* __restrict__ x,
                               const float* __restrict__ g, const float* __restrict__ be,
                               float* __restrict__ out)
{
    int nrow = blockIdx.x;
    int c = threadIdx.x;
    float v = fmaxf(x[(size_t)nrow * H + c], 0.f);
    __shared__ float sh[8];
    float mu  = block_sum_256(v, sh) * (1.f / H);
    float dx  = v - mu;
    float var = block_sum_256(dx * dx, sh) * (1.f / H);
    out[(size_t)nrow * H + c] = dx * rsqrtf(var + EPS) * g[c] + be[c];
}

// h_graph[batch[n]] += h_atom[n]
__global__ void graph_scatter_kernel(const float* __restrict__ h_atom,
                                     const int* __restrict__ batch,
                                     float* __restrict__ hgraph)
{
    int n = blockIdx.x;
    int c = threadIdx.x;
    int b = batch[n];
    atomicAdd(&hgraph[b * H + c], h_atom[(size_t)n * H + c]);
}

// out[g] = hgraph[g] @ W_read + b_read
__global__ void readout_kernel(const float* __restrict__ hgraph,
                               const float* __restrict__ Wr, const float* __restrict__ br,
                               float* __restrict__ out)
{
    int gph = blockIdx.x;
    int t = threadIdx.x;
    if (t < NUM_TASKS) {
        float s = br[t];
        const float* row = hgraph + gph * H;
        #pragma unroll 8
        for (int k = 0; k < H; k++) s += row[k] * Wr[k * NUM_TASKS + t];
        out[gph * NUM_TASKS + t] = s;
    }
}

// ---------------- host launcher ----------------
static void run_sgemm(const float* A, const float* B, const float* bias, float* C,
                      int M, int N, int K, bool withBias, bool withRelu, bool accum)
{
    dim3 grid(cdiv(N, BN), cdiv(M, BM));
    dim3 block(256);
    if (withBias) {
        if (accum)       sgemm_kernel<true,  false, true ><<<grid, block>>>(A, B, bias, C, M, N, K);
        else if (withRelu) sgemm_kernel<true, true, false><<<grid, block>>>(A, B, bias, C, M, N, K);
        else             sgemm_kernel<true,  false, false><<<grid, block>>>(A, B, bias, C, M, N, K);
    } else {
        if (accum)       sgemm_kernel<false, false, true ><<<grid, block>>>(A, B, bias, C, M, N, K);
        else if (withRelu) sgemm_kernel<false, true, false><<<grid, block>>>(A, B, bias, C, M, N, K);
        else             sgemm_kernel<false, false, false><<<grid, block>>>(A, B, bias, C, M, N, K);
    }
}

extern "C" void kernel_launch(void* const* d_in, const int* in_sizes, int n_in,
                              void* d_out, int out_size)
{
    const int*   x_z        = (const int*)  d_in[0];
    const float* x_atom     = (const float*)d_in[1];
    const int*   ei         = (const int*)  d_in[2];
    const float* edge_attr  = (const float*)d_in[3];
    const int*   batch      = (const int*)  d_in[4];
    const float* embed_z    = (const float*)d_in[5];
    const float* W_atom_in  = (const float*)d_in[6];
    const float* b_atom_in  = (const float*)d_in[7];
    const float* W_bond_in  = (const float*)d_in[8];
    const float* b_bond_in  = (const float*)d_in[9];
    const float* W_msg      = (const float*)d_in[10];
    const float* W_ih       = (const float*)d_in[11];
    const float* b_ih       = (const float*)d_in[12];
    const float* W_hh       = (const float*)d_in[13];
    const float* b_hh       = (const float*)d_in[14];
    const float* W_atom_out = (const float*)d_in[15];
    const float* b_atom_out = (const float*)d_in[16];
    const float* W_read     = (const float*)d_in[17];
    const float* b_read     = (const float*)d_in[18];
    const float* g_e        = (const float*)d_in[19];
    const float* be_e       = (const float*)d_in[20];
    const float* g_a        = (const float*)d_in[21];
    const float* be_a       = (const float*)d_in[22];

    const int N  = in_sizes[0];          // nodes
    const int E  = in_sizes[2] / 2;      // undirected edges
    const int E2 = 2 * E;                // directed edges
    const int AW = 32 + ATOM_IN;         // 165

    float* out       = (float*)d_out;
    float* out_hatom = out + NUM_GRAPHS * NUM_TASKS;
    float* out_he    = out_hatom + (size_t)N * H;

    // scratch addresses
    float *a_all, *h_all, *e_all, *h_e, *bufA, *bufM, *GI, *GH, *m_in, *WihT, *WhhT, *hgraph;
    cudaGetSymbolAddress((void**)&a_all,  g_a_all);
    cudaGetSymbolAddress((void**)&h_all,  g_h_all);
    cudaGetSymbolAddress((void**)&e_all,  g_e_all);
    cudaGetSymbolAddress((void**)&h_e,    g_h_e);
    cudaGetSymbolAddress((void**)&bufA,   g_bufA);
    cudaGetSymbolAddress((void**)&bufM,   g_bufM);
    cudaGetSymbolAddress((void**)&GI,     g_GI);
    cudaGetSymbolAddress((void**)&GH,     g_GH);
    cudaGetSymbolAddress((void**)&m_in,   g_m_in);
    cudaGetSymbolAddress((void**)&WihT,   g_WihT);
    cudaGetSymbolAddress((void**)&WhhT,   g_WhhT);
    cudaGetSymbolAddress((void**)&hgraph, g_hgraph);

    // 1) inputs
    build_a_all_kernel<<<cdiv(N * AW, 256) > 65535 ? 65535 : cdiv(N * AW, 256), 256>>>(
        x_z, x_atom, embed_z, a_all, N);
    transpose_w_kernel<<<cdiv(3 * H * H, 256), 256>>>(W_ih, WihT);
    transpose_w_kernel<<<cdiv(3 * H * H, 256), 256>>>(W_hh, WhhT);

    // 2) h_all = a_all @ W_atom_in + b
    run_sgemm(a_all, W_atom_in, b_atom_in, h_all, N, H, AW, true, false, false);
    // 3) e_all = edge_attr @ W_bond_in + b
    run_sgemm(edge_attr, W_bond_in, b_bond_in, e_all, E, H, BOND_IN, true, false, false);
    // 4) h_e init
    edge_init_kernel<<<E2, H>>>(ei, h_all, e_all, g_e, be_e, h_e, E);

    const size_t heN   = (size_t)E2 * H;
    const size_t minN  = (size_t)N * H;

    // 5) message passing
    for (int depth = 0; depth < DEPTH; depth++) {
        zero_kernel<<<2048, 256>>>(m_in, minN);
        scatter_kernel<<<E2, H>>>(h_e, ei, m_in, E);
        gather_kernel<<<E2, H>>>(m_in, h_e, ei, bufA, E);
        run_sgemm(bufA, W_msg, nullptr, bufM, E2, H, H, false, false, false);   // M = m_excl @ W_msg
        hnew_kernel<<<4096, 256>>>(h_e, bufM, heN / 4);                          // bufM = relu(h_e + M)
        run_sgemm(bufM, WihT, b_ih, GI, E2, 3 * H, H, true, false, false);       // GI
        run_sgemm(h_e,  WhhT, b_hh, GH, E2, 3 * H, H, true, false, false);       // GH
        float* dst = (depth == DEPTH - 1) ? out_he : h_e;
        gru_ln_kernel<<<E2, H>>>(GI, GH, h_e, g_e, be_e, dst);
    }

    // 6) m_to_atom = segment_sum(h_e)
    zero_kernel<<<2048, 256>>>(m_in, minN);
    scatter_kernel<<<E2, H>>>(out_he, ei, m_in, E);

    // 7) h_atom = LN(relu([a_all, m_to_atom] @ W_atom_out + b))
    run_sgemm(a_all, W_atom_out, b_atom_out, h_all, N, H, AW, true, false, false);
    run_sgemm(m_in, W_atom_out + (size_t)AW * H, nullptr, h_all, N, H, H, false, false, true);
    relu_ln_kernel<<<N, H>>>(h_all, g_a, be_a, out_hatom);

    // 8) readout
    zero_kernel<<<64, 256>>>(hgraph, (size_t)NUM_GRAPHS * H);
    graph_scatter_kernel<<<N, H>>>(out_hatom, batch, hgraph);
    readout_kernel<<<NUM_GRAPHS, 32>>>(hgraph, W_read, b_read, out);
}

// round 4
// speedup vs baseline: 2.7273x; 2.7273x over previous
#include <cuda_runtime.h>
#include <cuda_fp16.h>
#include <stdint.h>
#include <cstdint>
#include <math.h>

// ---------------- problem constants ----------------
#define MAX_N 50000
#define MAX_E 200000
#define H 256
#define ATOM_IN 133
#define BOND_IN 14
#define NUM_TASKS 12
#define NUM_GRAPHS 256
#define DEPTH 3
#define EPS 1e-5f

#define AIN_K 192   // 165 padded to mult of 32
#define AO_K  448   // 421 padded to mult of 32
#define GRU_K 512
#define GRU_N 1024

// ---------------- scratch (device globals; no allocation allowed) ----------------
__device__ float  g_h_all[(size_t)MAX_N * H];
__device__ float  g_e_all[(size_t)MAX_E * H];
__device__ float  g_h_e  [(size_t)(2*MAX_E) * H];
__device__ float  g_G    [(size_t)(2*MAX_E) * GRU_N];        // 1.64 GB
__device__ float  g_m_in [(size_t)MAX_N * H];
__device__ float  g_hgraph[NUM_GRAPHS * H];
__device__ float  g_biascat[GRU_N];
__device__ __half g_a16  [(size_t)MAX_N * AIN_K];
__device__ __half g_aao  [(size_t)MAX_N * AO_K];
__device__ __half g_acat [(size_t)(2*MAX_E) * GRU_K];        // [h_new | h_e] fp16
__device__ __half g_mex16[(size_t)(2*MAX_E) * H];
__device__ __half g_wain [AIN_K * H];
__device__ __half g_wmsg [H * H];
__device__ __half g_wao  [AO_K * H];
__device__ __half g_bcat [GRU_K * GRU_N];

static inline int cdiv(int a, int b) { return (a + b - 1) / b; }

// ---------------- tensor-core HGEMM:  C[M,N] = A[M,K]fp16 @ B[K,N]fp16 ----------------
#define GBM 128
#define GBN 128
#define GBK 32
#define SPAD 8

__device__ __forceinline__ void ldsm_x4(uint32_t& r0, uint32_t& r1, uint32_t& r2, uint32_t& r3, uint32_t addr) {
    asm volatile("ldmatrix.sync.aligned.m8n8.x4.shared.b16 {%0,%1,%2,%3}, [%4];\n"
                 : "=r"(r0), "=r"(r1), "=r"(r2), "=r"(r3) : "r"(addr));
}
__device__ __forceinline__ void ldsm_x4t(uint32_t& r0, uint32_t& r1, uint32_t& r2, uint32_t& r3, uint32_t addr) {
    asm volatile("ldmatrix.sync.aligned.m8n8.x4.trans.shared.b16 {%0,%1,%2,%3}, [%4];\n"
                 : "=r"(r0), "=r"(r1), "=r"(r2), "=r"(r3) : "r"(addr));
}
__device__ __forceinline__ void mma_16816(float* d, const uint32_t* a, const uint32_t* b) {
    asm volatile("mma.sync.aligned.m16n8k16.row.col.f32.f16.f16.f32 "
                 "{%0,%1,%2,%3}, {%4,%5,%6,%7}, {%8,%9}, {%0,%1,%2,%3};\n"
                 : "+f"(d[0]), "+f"(d[1]), "+f"(d[2]), "+f"(d[3])
                 : "r"(a[0]), "r"(a[1]), "r"(a[2]), "r"(a[3]), "r"(b[0]), "r"(b[1]));
}
#define CP_ASYNC16(dst, src) asm volatile("cp.async.cg.shared.global [%0], [%1], 16;\n" :: "r"(dst), "l"(src))
#define CP_COMMIT()          asm volatile("cp.async.commit_group;\n")
#define CP_WAIT0()           asm volatile("cp.async.wait_group 0;\n")

// async-load one (GBM x GBK) A tile + (GBK x GBN) B tile into stage s
__device__ __forceinline__ void hgemm_load_tile(
    const __half* __restrict__ A, const __half* __restrict__ B,
    __half (*As)[GBM][GBK + SPAD], __half (*Bs)[GBK][GBN + SPAD],
    int kt, int s, int bm, int bn, int M, int N, int K,
    int ar, int ac, int br, int bc)
{
    const int k0 = kt * GBK;
    #pragma unroll
    for (int i = 0; i < 2; i++) {
        int r  = ar + i * 64;
        int gr = bm + r; if (gr >= M) gr = M - 1;   // clamp (rows past M never stored)
        const __half* src = A + (size_t)gr * K + k0 + ac;
        uint32_t dst = (uint32_t)__cvta_generic_to_shared(&As[s][r][ac]);
        CP_ASYNC16(dst, src);
    }
    #pragma unroll
    for (int i = 0; i < 2; i++) {
        int r = br + i * 16;
        const __half* src = B + (size_t)(k0 + r) * N + bn + bc;
        uint32_t dst = (uint32_t)__cvta_generic_to_shared(&Bs[s][r][bc]);
        CP_ASYNC16(dst, src);
    }
}

// EPI = 0: outF[row*ldOut+col] = acc + bias[col]                       (fp32 out)
// EPI = 1: outH[row*ldOut+col] = half(relu(acc + aux[row*H+col]))      (msg GEMM, fp16 out into Acat)
template<int EPI>
__global__ __launch_bounds__(256, 2) void hgemm_kernel(
    const __half* __restrict__ A, const __half* __restrict__ B,
    const float* __restrict__ bias,
    float* __restrict__ outF, __half* __restrict__ outH,
    const float* __restrict__ aux,
    int M, int N, int K, int ldOut)
{
    __shared__ __align__(16) __half As[2][GBM][GBK + SPAD];
    __shared__ __align__(16) __half Bs[2][GBK][GBN + SPAD];

    const int tid  = threadIdx.x;
    const int lane = tid & 31;
    const int warp = tid >> 5;
    const int wm   = warp & 3;          // 4 warps along M (32 rows each)
    const int wn   = warp >> 2;         // 2 warps along N (64 cols each)
    const int bm   = blockIdx.y * GBM;
    const int bn   = blockIdx.x * GBN;

    float acc[2][8][4];
    #pragma unroll
    for (int i = 0; i < 2; i++)
        #pragma unroll
        for (int j = 0; j < 8; j++)
            #pragma unroll
            for (int k = 0; k < 4; k++) acc[i][j][k] = 0.f;

    const int ar = tid >> 2;            // 0..63
    const int ac = (tid & 3) << 3;      // 0,8,16,24
    const int br = tid >> 4;            // 0..15
    const int bc = (tid & 15) << 3;     // 0..120

    const int KT = K / GBK;

    hgemm_load_tile(A, B, As, Bs, 0, 0, bm, bn, M, N, K, ar, ac, br, bc);
    CP_COMMIT();

    for (int kt = 0; kt < KT; kt++) {
        CP_WAIT0();
        __syncthreads();
        const int s = kt & 1;
        if (kt + 1 < KT) {
            hgemm_load_tile(A, B, As, Bs, kt + 1, (kt + 1) & 1, bm, bn, M, N, K, ar, ac, br, bc);
            CP_COMMIT();
        }

        #pragma unroll
        for (int ks = 0; ks < 2; ks++) {
            const int k0 = ks * 16;
            uint32_t af[2][4];
            #pragma unroll
            for (int mi = 0; mi < 2; mi++) {
                int row = wm * 32 + mi * 16 + (lane & 15);
                int col = k0 + ((lane >> 4) << 3);
                uint32_t ad = (uint32_t)__cvta_generic_to_shared(&As[s][row][col]);
                ldsm_x4(af[mi][0], af[mi][1], af[mi][2], af[mi][3], ad);
            }
            uint32_t bf[8][2];
            #pragma unroll
            for (int nq = 0; nq < 4; nq++) {
                int row = k0 + (lane & 15);
                int col = wn * 64 + nq * 16 + ((lane >> 4) << 3);
                uint32_t bd = (uint32_t)__cvta_generic_to_shared(&Bs[s][row][col]);
                ldsm_x4t(bf[nq*2][0], bf[nq*2][1], bf[nq*2+1][0], bf[nq*2+1][1], bd);
            }
            #pragma unroll
            for (int mi = 0; mi < 2; mi++)
                #pragma unroll
                for (int nj = 0; nj < 8; nj++)
                    mma_16816(acc[mi][nj], af[mi], bf[nj]);
        }
        __syncthreads();
    }

    // epilogue
    const int r0 = bm + wm * 32 + (lane >> 2);
    const int c0 = bn + wn * 64 + ((lane & 3) << 1);
    #pragma unroll
    for (int mi = 0; mi < 2; mi++) {
        #pragma unroll
        for (int nj = 0; nj < 8; nj++) {
            const int col = c0 + nj * 8;
            #pragma unroll
            for (int hh = 0; hh < 2; hh++) {
                const int row = r0 + mi * 16 + hh * 8;
                if (row >= M) continue;
                float v0 = acc[mi][nj][hh * 2 + 0];
                float v1 = acc[mi][nj][hh * 2 + 1];
                if (EPI == 0) {
                    v0 += bias[col];
                    v1 += bias[col + 1];
                    outF[(size_t)row * ldOut + col]     = v0;
                    outF[(size_t)row * ldOut + col + 1] = v1;
                } else {
                    v0 = fmaxf(v0 + aux[(size_t)row * H + col],     0.f);
                    v1 = fmaxf(v1 + aux[(size_t)row * H + col + 1], 0.f);
                    outH[(size_t)row * ldOut + col]     = __float2half(v0);
                    outH[(size_t)row * ldOut + col + 1] = __float2half(v1);
                }
            }
        }
    }
}

// ---------------- helpers ----------------
__device__ __forceinline__ float block_sum_256(float v, float* sh) {
    #pragma unroll
    for (int o = 16; o > 0; o >>= 1) v += __shfl_down_sync(0xffffffffu, v, o);
    int warp = threadIdx.x >> 5, lane = threadIdx.x & 31;
    if (lane == 0) sh[warp] = v;
    __syncthreads();
    if (warp == 0) {
        v = (lane < 8) ? sh[lane] : 0.f;
        #pragma unroll
        for (int o = 4; o > 0; o >>= 1) v += __shfl_down_sync(0xffffffffu, v, o);
        if (lane == 0) sh[0] = v;
    }
    __syncthreads();
    float r = sh[0];
    __syncthreads();
    return r;
}

__device__ __forceinline__ float sigmoidf_(float x) { return 1.f / (1.f + expf(-x)); }

// a16 [N,192] and Aao cols 0..164 + zero pad cols 421..447
__global__ void build_a16_kernel(const int* __restrict__ xz, const float* __restrict__ xa,
                                 const float* __restrict__ emb,
                                 __half* __restrict__ a16, __half* __restrict__ aao, int N)
{
    size_t idx = (size_t)blockIdx.x * blockDim.x + threadIdx.x;
    size_t total = (size_t)N * AO_K;
    for (; idx < total; idx += (size_t)gridDim.x * blockDim.x) {
        int n = (int)(idx / AO_K);
        int c = (int)(idx % AO_K);
        if (c < AIN_K) {
            float v = (c < 32) ? emb[xz[n] * 32 + c]
                    : (c < 165) ? xa[(size_t)n * ATOM_IN + (c - 32)] : 0.f;
            __half h = __float2half(v);
            a16[(size_t)n * AIN_K + c] = h;
            if (c < 165) aao[(size_t)n * AO_K + c] = h;
        } else if (c >= 421) {
            aao[idx] = __float2half(0.f);
        }
    }
}

__global__ void build_wain16(const float* __restrict__ W, __half* __restrict__ O) {
    int idx = blockIdx.x * blockDim.x + threadIdx.x;
    if (idx >= AIN_K * H) return;
    int k = idx / H, c = idx % H;
    O[idx] = __float2half(k < 165 ? W[k * H + c] : 0.f);
}
__global__ void build_wmsg16(const float* __restrict__ W, __half* __restrict__ O) {
    int idx = blockIdx.x * blockDim.x + threadIdx.x;
    if (idx < H * H) O[idx] = __float2half(W[idx]);
}
__global__ void build_wao16(const float* __restrict__ W, __half* __restrict__ O) {
    int idx = blockIdx.x * blockDim.x + threadIdx.x;
    if (idx >= AO_K * H) return;
    int k = idx / H, c = idx % H;
    O[idx] = __float2half(k < 421 ? W[k * H + c] : 0.f);
}
// Bcat [512,1024]: cols 0..511 = summed r,z gates; 512..767 = gi_n; 768..1023 = gh_n
__global__ void build_bcat_kernel(const float* __restrict__ Wih, const float* __restrict__ Whh,
                                  const float* __restrict__ bih, const float* __restrict__ bhh,
                                  __half* __restrict__ Bc, float* __restrict__ bc)
{
    int idx = blockIdx.x * blockDim.x + threadIdx.x;
    if (idx >= GRU_K * GRU_N) return;
    int k = idx / GRU_N, j = idx % GRU_N;
    float v = 0.f;
    if (j < 512)      v = (k < 256) ? Wih[j * H + k] : Whh[j * H + (k - 256)];
    else if (j < 768) { if (k < 256) v = Wih[j * H + k]; }
    else              { if (k >= 256) v = Whh[(j - 256) * H + (k - 256)]; }
    Bc[idx] = __float2half(v);
    if (k == 0)
        bc[j] = (j < 512) ? bih[j] + bhh[j] : ((j < 768) ? bih[j] : bhh[j - 256]);
}

// e_all = edge_attr @ W_bond_in + b   (K=14, memory-bound)
__global__ void bond_kernel(const float* __restrict__ ea, const float* __restrict__ W,
                            const float* __restrict__ b, float* __restrict__ out, int E)
{
    int e = blockIdx.x, c = threadIdx.x;
    __shared__ float row[16];
    if (c < BOND_IN) row[c] = ea[(size_t)e * BOND_IN + c];
    __syncthreads();
    float s = b[c];
    #pragma unroll
    for (int k = 0; k < BOND_IN; k++) s += row[k] * W[k * H + c];
    out[(size_t)e * H + c] = s;
}

// h_e[d] = LN(relu(h_all[src_dir[d]] + e_all[d%E])), also fp16 copy into Acat cols 256..511
__global__ void edge_init_kernel(const int* __restrict__ ei, const float* __restrict__ h_all,
                                 const float* __restrict__ e_all,
                                 const float* __restrict__ g, const float* __restrict__ be,
                                 float* __restrict__ h_e, __half* __restrict__ acat, int E)
{
    int d = blockIdx.x, c = threadIdx.x;
    int src = ei[d];
    int e = (d < E) ? d : d - E;
    float x = fmaxf(h_all[(size_t)src * H + c] + e_all[(size_t)e * H + c], 0.f);
    __shared__ float sh[8];
    float mu  = block_sum_256(x, sh) * (1.f / H);
    float dx  = x - mu;
    float var = block_sum_256(dx * dx, sh) * (1.f / H);
    float y   = dx * rsqrtf(var + EPS) * g[c] + be[c];
    h_e[(size_t)d * H + c] = y;
    acat[(size_t)d * GRU_K + H + c] = __float2half(y);
}

__global__ void zero_kernel(float* __restrict__ p, size_t n) {
    size_t i = (size_t)blockIdx.x * blockDim.x + threadIdx.x;
    for (; i < n; i += (size_t)gridDim.x * blockDim.x) p[i] = 0.f;
}

__global__ void scatter_kernel(const float* __restrict__ h_e, const int* __restrict__ ei,
                               float* __restrict__ m_in, int E)
{
    int d = blockIdx.x, c = threadIdx.x;
    int dst = (d < E) ? ei[E + d] : ei[d - E];
    atomicAdd(&m_in[(size_t)dst * H + c], h_e[(size_t)d * H + c]);
}

// m_excl fp16 = m_in[src_dir[d]] - h_e[rev[d]]
__global__ void gather_kernel(const float* __restrict__ m_in, const float* __restrict__ h_e,
                              const int* __restrict__ ei, __half* __restrict__ out16, int E)
{
    int d = blockIdx.x, c = threadIdx.x;
    int src = ei[d];
    int rv  = (d < E) ? d + E : d - E;
    out16[(size_t)d * H + c] = __float2half(m_in[(size_t)src * H + c] - h_e[(size_t)rv * H + c]);
}

// GRU combine from fused G[2E,1024] + LN
template<bool W16>
__global__ void gru_ln_kernel(const float* __restrict__ G, const float* __restrict__ h_e_in,
                              const float* __restrict__ g, const float* __restrict__ be,
                              float* __restrict__ h_e_out, __half* __restrict__ acat)
{
    int d = blockIdx.x, j = threadIdx.x;
    size_t base = (size_t)d * GRU_N;
    float r = sigmoidf_(G[base + j]);
    float z = sigmoidf_(G[base + 256 + j]);
    float n = tanhf(G[base + 512 + j] + r * G[base + 768 + j]);
    float hprev = h_e_in[(size_t)d * H + j];
    float h = (1.f - z) * n + z * hprev;
    __shared__ float sh[8];
    float mu  = block_sum_256(h, sh) * (1.f / H);
    float dx  = h - mu;
    float var = block_sum_256(dx * dx, sh) * (1.f / H);
    float y   = dx * rsqrtf(var + EPS) * g[j] + be[j];
    h_e_out[(size_t)d * H + j] = y;
    if (W16) acat[(size_t)d * GRU_K + H + j] = __float2half(y);
}

// m_in -> Aao cols 165..420 (fp16)
__global__ void convert_min_kernel(const float* __restrict__ m_in, __half* __restrict__ aao, int N)
{
    size_t idx = (size_t)blockIdx.x * blockDim.x + threadIdx.x;
    size_t total = (size_t)N * H;
    for (; idx < total; idx += (size_t)gridDim.x * blockDim.x) {
        int n = (int)(idx / H), c = (int)(idx % H);
        aao[(size_t)n * AO_K + 165 + c] = __float2half(m_in[idx]);
    }
}

__global__ void relu_ln_kernel(const float* __restrict__ x,
                               const float* __restrict__ g, const float* __restrict__ be,
                               float* __restrict__ out)
{
    int nrow = blockIdx.x, c = threadIdx.x;
    float v = fmaxf(x[(size_t)nrow * H + c], 0.f);
    __shared__ float sh[8];
    float mu  = block_sum_256(v, sh) * (1.f / H);
    float dx  = v - mu;
    float var = block_sum_256(dx * dx, sh) * (1.f / H);
    out[(size_t)nrow * H + c] = dx * rsqrtf(var + EPS) * g[c] + be[c];
}

__global__ void graph_scatter_kernel(const float* __restrict__ h_atom, const int* __restrict__ batch,
                                     float* __restrict__ hgraph)
{
    int n = blockIdx.x, c = threadIdx.x;
    atomicAdd(&hgraph[batch[n] * H + c], h_atom[(size_t)n * H + c]);
}

__global__ void readout_kernel(const float* __restrict__ hgraph, const float* __restrict__ Wr,
                               const float* __restrict__ br, float* __restrict__ out)
{
    int gph = blockIdx.x, t = threadIdx.x;
    if (t < NUM_TASKS) {
        float s = br[t];
        const float* row = hgraph + gph * H;
        #pragma unroll 8
        for (int k = 0; k < H; k++) s += row[k] * Wr[k * NUM_TASKS + t];
        out[gph * NUM_TASKS + t] = s;
    }
}

// ---------------- host launcher ----------------
extern "C" void kernel_launch(void* const* d_in, const int* in_sizes, int n_in,
                              void* d_out, int out_size)
{
    const int*   x_z        = (const int*)  d_in[0];
    const float* x_atom     = (const float*)d_in[1];
    const int*   ei         = (const int*)  d_in[2];
    const float* edge_attr  = (const float*)d_in[3];
    const int*   batch      = (const int*)  d_in[4];
    const float* embed_z    = (const float*)d_in[5];
    const float* W_atom_in  = (const float*)d_in[6];
    const float* b_atom_in  = (const float*)d_in[7];
    const float* W_bond_in  = (const float*)d_in[8];
    const float* b_bond_in  = (const float*)d_in[9];
    const float* W_msg      = (const float*)d_in[10];
    const float* W_ih       = (const float*)d_in[11];
    const float* b_ih       = (const float*)d_in[12];
    const float* W_hh       = (const float*)d_in[13];
    const float* b_hh       = (const float*)d_in[14];
    const float* W_atom_out = (const float*)d_in[15];
    const float* b_atom_out = (const float*)d_in[16];
    const float* W_read     = (const float*)d_in[17];
    const float* b_read     = (const float*)d_in[18];
    const float* g_e        = (const float*)d_in[19];
    const float* be_e       = (const float*)d_in[20];
    const float* g_a        = (const float*)d_in[21];
    const float* be_a       = (const float*)d_in[22];

    const int N  = in_sizes[0];
    const int E  = in_sizes[2] / 2;
    const int E2 = 2 * E;

    float* out       = (float*)d_out;
    float* out_hatom = out + NUM_GRAPHS * NUM_TASKS;
    float* out_he    = out_hatom + (size_t)N * H;

    float  *h_all, *e_all, *h_e, *G, *m_in, *hgraph, *biascat;
    __half *a16, *aao, *acat, *mex16, *wain, *wmsg, *wao, *bcat;
    cudaGetSymbolAddress((void**)&h_all,   g_h_all);
    cudaGetSymbolAddress((void**)&e_all,   g_e_all);
    cudaGetSymbolAddress((void**)&h_e,     g_h_e);
    cudaGetSymbolAddress((void**)&G,       g_G);
    cudaGetSymbolAddress((void**)&m_in,    g_m_in);
    cudaGetSymbolAddress((void**)&hgraph,  g_hgraph);
    cudaGetSymbolAddress((void**)&biascat, g_biascat);
    cudaGetSymbolAddress((void**)&a16,     g_a16);
    cudaGetSymbolAddress((void**)&aao,     g_aao);
    cudaGetSymbolAddress((void**)&acat,    g_acat);
    cudaGetSymbolAddress((void**)&mex16,   g_mex16);
    cudaGetSymbolAddress((void**)&wain,    g_wain);
    cudaGetSymbolAddress((void**)&wmsg,    g_wmsg);
    cudaGetSymbolAddress((void**)&wao,     g_wao);
    cudaGetSymbolAddress((void**)&bcat,    g_bcat);

    // weight prep (fp16 + padding)
    build_a16_kernel<<<4096, 256>>>(x_z, x_atom, embed_z, a16, aao, N);
    build_wain16<<<cdiv(AIN_K * H, 256), 256>>>(W_atom_in, wain);
    build_wmsg16<<<cdiv(H * H, 256), 256>>>(W_msg, wmsg);
    build_wao16<<<cdiv(AO_K * H, 256), 256>>>(W_atom_out, wao);
    build_bcat_kernel<<<cdiv(GRU_K * GRU_N, 256), 256>>>(W_ih, W_hh, b_ih, b_hh, bcat, biascat);

    // h_all = a_all @ W_atom_in + b
    hgemm_kernel<0><<<dim3(H / GBN, cdiv(N, GBM)), 256>>>(
        a16, wain, b_atom_in, h_all, nullptr, nullptr, N, H, AIN_K, H);
    // e_all
    bond_kernel<<<E, H>>>(edge_attr, W_bond_in, b_bond_in, e_all, E);
    // h_e init (+ fp16 copy into Acat)
    edge_init_kernel<<<E2, H>>>(ei, h_all, e_all, g_e, be_e, h_e, acat, E);

    const size_t minN = (size_t)N * H;

    for (int depth = 0; depth < DEPTH; depth++) {
        zero_kernel<<<2048, 256>>>(m_in, minN);
        scatter_kernel<<<E2, H>>>(h_e, ei, m_in, E);
        gather_kernel<<<E2, H>>>(m_in, h_e, ei, mex16, E);
        // h_new = relu(h_e + m_excl @ W_msg)  -> Acat cols 0..255 (fp16)
        hgemm_kernel<1><<<dim3(H / GBN, cdiv(E2, GBM)), 256>>>(
            mex16, wmsg, nullptr, nullptr, acat, h_e, E2, H, H, GRU_K);
        // fused GRU gates: G = [h_new | h_e] @ Bcat + biascat
        hgemm_kernel<0><<<dim3(GRU_N / GBN, cdiv(E2, GBM)), 256>>>(
            acat, bcat, biascat, G, nullptr, nullptr, E2, GRU_N, GRU_K, GRU_N);
        float* dst = (depth == DEPTH - 1) ? out_he : h_e;
        if (depth < DEPTH - 1)
            gru_ln_kernel<true><<<E2, H>>>(G, h_e, g_e, be_e, dst, acat);
        else
            gru_ln_kernel<false><<<E2, H>>>(G, h_e, g_e, be_e, dst, acat);
    }

    // m_to_atom
    zero_kernel<<<2048, 256>>>(m_in, minN);
    scatter_kernel<<<E2, H>>>(out_he, ei, m_in, E);
    convert_min_kernel<<<2048, 256>>>(m_in, aao, N);

    // h_atom = LN(relu([a_all | m_to_atom] @ W_atom_out + b))
    hgemm_kernel<0><<<dim3(H / GBN, cdiv(N, GBM)), 256>>>(
        aao, wao, b_atom_out, h_all, nullptr, nullptr, N, H, AO_K, H);
    relu_ln_kernel<<<N, H>>>(h_all, g_a, be_a, out_hatom);

    // readout
    zero_kernel<<<64, 256>>>(hgraph, (size_t)NUM_GRAPHS * H);
    graph_scatter_kernel<<<N, H>>>(out_hatom, batch, hgraph);
    readout_kernel<<<NUM_GRAPHS, 32>>>(hgraph, W_read, b_read, out);
}

// round 6
// speedup vs baseline: 2.8097x; 1.0302x over previous
#include <cuda_runtime.h>
#include <cuda_fp16.h>
#include <stdint.h>
#include <cstdint>
#include <math.h>

// ---------------- problem constants ----------------
#define MAX_N 50000
#define MAX_E 200000
#define H 256
#define ATOM_IN 133
#define BOND_IN 14
#define NUM_TASKS 12
#define NUM_GRAPHS 256
#define DEPTH 3
#define EPS 1e-5f

#define AIN_K 192   // 165 padded to mult of 32
#define AO_K  448   // 421 padded to mult of 32
#define ACAT_W 512  // [h_new | h_e] row width
#define RZ_N  512   // interleaved (r_j, z_j)

// ---------------- scratch (device globals; no allocation allowed) ----------------
__device__ float  g_h_all[(size_t)MAX_N * H];
__device__ float  g_e_all[(size_t)MAX_E * H];
__device__ float  g_h_e  [(size_t)(2*MAX_E) * H];
__device__ float  g_hpre [(size_t)(2*MAX_E) * H];
__device__ float  g_m_in [(size_t)MAX_N * H];
__device__ float  g_hgraph[NUM_GRAPHS * H];
__device__ float  g_rzbias[RZ_N];
__device__ float  g_nbias [RZ_N];
__device__ __half g_a16  [(size_t)MAX_N * AIN_K];
__device__ __half g_aao  [(size_t)MAX_N * AO_K];
__device__ __half g_acat [(size_t)(2*MAX_E) * ACAT_W];   // [h_new | h_e] fp16
__device__ __half g_mex16[(size_t)(2*MAX_E) * H];
__device__ __half g_Gn   [(size_t)(2*MAX_E) * RZ_N];     // interleaved (gin_j, ghn_j) fp16
__device__ __half g_wain [AIN_K * H];
__device__ __half g_wmsg [H * H];
__device__ __half g_wao  [AO_K * H];
__device__ __half g_brz  [ACAT_W * RZ_N];                // [512,512]
__device__ __half g_bgin [H * H];
__device__ __half g_bghn [H * H];

static inline int cdiv(int a, int b) { return (a + b - 1) / b; }

#define CP_ASYNC16(dst, src) asm volatile("cp.async.cg.shared.global [%0], [%1], 16;\n" :: "r"(dst), "l"(src))
#define CP_COMMIT()          asm volatile("cp.async.commit_group;\n")
#define CP_WAIT0()           asm volatile("cp.async.wait_group 0;\n")

// ---------------- mma.sync HGEMM ----------------
#define GBM 128
#define GBN 128
#define GBK 32
#define SPAD 8

__device__ __forceinline__ void ldsm_x4(uint32_t& r0, uint32_t& r1, uint32_t& r2, uint32_t& r3, uint32_t addr) {
    asm volatile("ldmatrix.sync.aligned.m8n8.x4.shared.b16 {%0,%1,%2,%3}, [%4];\n"
                 : "=r"(r0), "=r"(r1), "=r"(r2), "=r"(r3) : "r"(addr));
}
__device__ __forceinline__ void ldsm_x4t(uint32_t& r0, uint32_t& r1, uint32_t& r2, uint32_t& r3, uint32_t addr) {
    asm volatile("ldmatrix.sync.aligned.m8n8.x4.trans.shared.b16 {%0,%1,%2,%3}, [%4];\n"
                 : "=r"(r0), "=r"(r1), "=r"(r2), "=r"(r3) : "r"(addr));
}
__device__ __forceinline__ void mma_16816(float* d, const uint32_t* a, const uint32_t* b) {
    asm volatile("mma.sync.aligned.m16n8k16.row.col.f32.f16.f16.f32 "
                 "{%0,%1,%2,%3}, {%4,%5,%6,%7}, {%8,%9}, {%0,%1,%2,%3};\n"
                 : "+f"(d[0]), "+f"(d[1]), "+f"(d[2]), "+f"(d[3])
                 : "r"(a[0]), "r"(a[1]), "r"(a[2]), "r"(a[3]), "r"(b[0]), "r"(b[1]));
}

__device__ __forceinline__ void hgemm_load_tile(
    const __half* __restrict__ A, const __half* __restrict__ B,
    __half (*As)[GBM][GBK + SPAD], __half (*Bs)[GBK][GBN + SPAD],
    int kt, int s, int bm, int bn, int M, int N, int K, int ldA,
    int ar, int ac, int br, int bc)
{
    const int k0 = kt * GBK;
    #pragma unroll
    for (int i = 0; i < 2; i++) {
        int r  = ar + i * 64;
        int gr = bm + r; if (gr >= M) gr = M - 1;   // clamp (rows past M never stored)
        const __half* src = A + (size_t)gr * ldA + k0 + ac;
        uint32_t dst = (uint32_t)__cvta_generic_to_shared(&As[s][r][ac]);
        CP_ASYNC16(dst, src);
    }
    #pragma unroll
    for (int i = 0; i < 2; i++) {
        int r = br + i * 16;
        const __half* src = B + (size_t)(k0 + r) * N + bn + bc;
        uint32_t dst = (uint32_t)__cvta_generic_to_shared(&Bs[s][r][bc]);
        CP_ASYNC16(dst, src);
    }
}

__device__ __forceinline__ float sigmoidf_(float x) { return 1.f / (1.f + expf(-x)); }

// EPI 0: outF[row*ldOut+col] = acc + bias[col]                   (fp32)
// EPI 1: outH[row*ldOut+col] = half(relu(acc + aux[row*H+col]))  (msg -> acat h_new)
// EPI 2: outH[row*ldOut+2*col+colOff] = half(acc)                (gin/ghn -> Gn interleaved)
// EPI 3: fused GRU: r,z from acc pair; gin,ghn from auxH; hprev from aux; write outF[row*H+j]
template<int EPI>
__global__ __launch_bounds__(256, 2) void hgemm_kernel(
    const __half* __restrict__ A, const __half* __restrict__ B,
    const float* __restrict__ bias, const float* __restrict__ bias2,
    float* __restrict__ outF, __half* __restrict__ outH,
    const float* __restrict__ aux, const __half* __restrict__ auxH,
    int M, int N, int K, int ldA, int ldOut, int colOff)
{
    __shared__ __align__(16) __half As[2][GBM][GBK + SPAD];
    __shared__ __align__(16) __half Bs[2][GBK][GBN + SPAD];

    const int tid  = threadIdx.x;
    const int lane = tid & 31;
    const int warp = tid >> 5;
    const int wm   = warp & 3;
    const int wn   = warp >> 2;
    const int bm   = blockIdx.y * GBM;
    const int bn   = blockIdx.x * GBN;

    float acc[2][8][4];
    #pragma unroll
    for (int i = 0; i < 2; i++)
        #pragma unroll
        for (int j = 0; j < 8; j++)
            #pragma unroll
            for (int k = 0; k < 4; k++) acc[i][j][k] = 0.f;

    const int ar = tid >> 2;
    const int ac = (tid & 3) << 3;
    const int br = tid >> 4;
    const int bc = (tid & 15) << 3;
    const int KT = K / GBK;

    hgemm_load_tile(A, B, As, Bs, 0, 0, bm, bn, M, N, K, ldA, ar, ac, br, bc);
    CP_COMMIT();

    for (int kt = 0; kt < KT; kt++) {
        CP_WAIT0();
        __syncthreads();
        const int s = kt & 1;
        if (kt + 1 < KT) {
            hgemm_load_tile(A, B, As, Bs, kt + 1, (kt + 1) & 1, bm, bn, M, N, K, ldA, ar, ac, br, bc);
            CP_COMMIT();
        }
        #pragma unroll
        for (int ks = 0; ks < 2; ks++) {
            const int k0 = ks * 16;
            uint32_t af[2][4];
            #pragma unroll
            for (int mi = 0; mi < 2; mi++) {
                int row = wm * 32 + mi * 16 + (lane & 15);
                int col = k0 + ((lane >> 4) << 3);
                uint32_t ad = (uint32_t)__cvta_generic_to_shared(&As[s][row][col]);
                ldsm_x4(af[mi][0], af[mi][1], af[mi][2], af[mi][3], ad);
            }
            uint32_t bf[8][2];
            #pragma unroll
            for (int nq = 0; nq < 4; nq++) {
                int row = k0 + (lane & 15);
                int col = wn * 64 + nq * 16 + ((lane >> 4) << 3);
                uint32_t bd = (uint32_t)__cvta_generic_to_shared(&Bs[s][row][col]);
                ldsm_x4t(bf[nq*2][0], bf[nq*2][1], bf[nq*2+1][0], bf[nq*2+1][1], bd);
            }
            #pragma unroll
            for (int mi = 0; mi < 2; mi++)
                #pragma unroll
                for (int nj = 0; nj < 8; nj++)
                    mma_16816(acc[mi][nj], af[mi], bf[nj]);
        }
        __syncthreads();
    }

    const int r0 = bm + wm * 32 + (lane >> 2);
    const int c0 = bn + wn * 64 + ((lane & 3) << 1);
    #pragma unroll
    for (int mi = 0; mi < 2; mi++) {
        #pragma unroll
        for (int nj = 0; nj < 8; nj++) {
            const int col = c0 + nj * 8;
            #pragma unroll
            for (int hh = 0; hh < 2; hh++) {
                const int row = r0 + mi * 16 + hh * 8;
                if (row >= M) continue;
                float v0 = acc[mi][nj][hh * 2 + 0];
                float v1 = acc[mi][nj][hh * 2 + 1];
                if (EPI == 0) {
                    outF[(size_t)row * ldOut + col]     = v0 + bias[col];
                    outF[(size_t)row * ldOut + col + 1] = v1 + bias[col + 1];
                } else if (EPI == 1) {
                    v0 = fmaxf(v0 + aux[(size_t)row * H + col],     0.f);
                    v1 = fmaxf(v1 + aux[(size_t)row * H + col + 1], 0.f);
                    outH[(size_t)row * ldOut + col]     = __float2half(v0);
                    outH[(size_t)row * ldOut + col + 1] = __float2half(v1);
                } else if (EPI == 2) {
                    outH[(size_t)row * ldOut + 2 * col + colOff]       = __float2half(v0);
                    outH[(size_t)row * ldOut + 2 * (col + 1) + colOff] = __float2half(v1);
                } else {
                    // col even: (r_j, z_j) with j = col>>1
                    float r = sigmoidf_(v0 + bias[col]);
                    float z = sigmoidf_(v1 + bias[col + 1]);
                    __half2 gh2 = *(const __half2*)(auxH + (size_t)row * ldOut + col);
                    float gin = __low2float(gh2)  + bias2[col];
                    float ghn = __high2float(gh2) + bias2[col + 1];
                    float n = tanhf(gin + r * ghn);
                    int j = col >> 1;
                    float hp = aux[(size_t)row * H + j];
                    outF[(size_t)row * H + j] = (1.f - z) * n + z * hp;
                }
            }
        }
    }
}

// ---------------- helpers ----------------
__device__ __forceinline__ float block_sum_256(float v, float* sh) {
    #pragma unroll
    for (int o = 16; o > 0; o >>= 1) v += __shfl_down_sync(0xffffffffu, v, o);
    int warp = threadIdx.x >> 5, lane = threadIdx.x & 31;
    if (lane == 0) sh[warp] = v;
    __syncthreads();
    if (warp == 0) {
        v = (lane < 8) ? sh[lane] : 0.f;
        #pragma unroll
        for (int o = 4; o > 0; o >>= 1) v += __shfl_down_sync(0xffffffffu, v, o);
        if (lane == 0) sh[0] = v;
    }
    __syncthreads();
    float r = sh[0];
    __syncthreads();
    return r;
}

__global__ void build_a16_kernel(const int* __restrict__ xz, const float* __restrict__ xa,
                                 const float* __restrict__ emb,
                                 __half* __restrict__ a16, __half* __restrict__ aao, int N)
{
    size_t idx = (size_t)blockIdx.x * blockDim.x + threadIdx.x;
    size_t total = (size_t)N * AO_K;
    for (; idx < total; idx += (size_t)gridDim.x * blockDim.x) {
        int n = (int)(idx / AO_K);
        int c = (int)(idx % AO_K);
        if (c < AIN_K) {
            float v = (c < 32) ? emb[xz[n] * 32 + c]
                    : (c < 165) ? xa[(size_t)n * ATOM_IN + (c - 32)] : 0.f;
            __half h = __float2half(v);
            a16[(size_t)n * AIN_K + c] = h;
            if (c < 165) aao[(size_t)n * AO_K + c] = h;
        } else if (c >= 421) {
            aao[idx] = __float2half(0.f);
        }
    }
}

__global__ void build_wain16(const float* __restrict__ W, __half* __restrict__ O) {
    int idx = blockIdx.x * blockDim.x + threadIdx.x;
    if (idx >= AIN_K * H) return;
    int k = idx / H, c = idx % H;
    O[idx] = __float2half(k < 165 ? W[k * H + c] : 0.f);
}
__global__ void build_wmsg16(const float* __restrict__ W, __half* __restrict__ O) {
    int idx = blockIdx.x * blockDim.x + threadIdx.x;
    if (idx < H * H) O[idx] = __float2half(W[idx]);
}
__global__ void build_wao16(const float* __restrict__ W, __half* __restrict__ O) {
    int idx = blockIdx.x * blockDim.x + threadIdx.x;
    if (idx >= AO_K * H) return;
    int k = idx / H, c = idx % H;
    O[idx] = __float2half(k < 421 ? W[k * H + c] : 0.f);
}

// brz [512,512]: col 2j -> r_j weights, col 2j+1 -> z_j weights; rows k<256 from Wih, k>=256 from Whh
__global__ void build_brz_kernel(const float* __restrict__ Wih, const float* __restrict__ Whh,
                                 const float* __restrict__ bih, const float* __restrict__ bhh,
                                 __half* __restrict__ Brz, float* __restrict__ rzb)
{
    int idx = blockIdx.x * blockDim.x + threadIdx.x;
    if (idx >= ACAT_W * RZ_N) return;
    int k = idx / RZ_N, c = idx % RZ_N;
    int j = c >> 1;
    int gateRow = (c & 1) ? (256 + j) : j;     // r at 2j, z at 2j+1
    float v = (k < 256) ? Wih[gateRow * H + k] : Whh[gateRow * H + (k - 256)];
    Brz[idx] = __float2half(v);
    if (k == 0) rzb[c] = bih[gateRow] + bhh[gateRow];
}
// bgin [256,256]: B[k][j] = Wih[512+j][k]; nbias[2j] = bih[512+j]
__global__ void build_bgin_kernel(const float* __restrict__ Wih, const float* __restrict__ bih,
                                  __half* __restrict__ Bg, float* __restrict__ nb)
{
    int idx = blockIdx.x * blockDim.x + threadIdx.x;
    if (idx >= H * H) return;
    int k = idx / H, j = idx % H;
    Bg[idx] = __float2half(Wih[(512 + j) * H + k]);
    if (k == 0) nb[2 * j] = bih[512 + j];
}
// bghn [256,256]: B[k][j] = Whh[512+j][k]; nbias[2j+1] = bhh[512+j]
__global__ void build_bghn_kernel(const float* __restrict__ Whh, const float* __restrict__ bhh,
                                  __half* __restrict__ Bg, float* __restrict__ nb)
{
    int idx = blockIdx.x * blockDim.x + threadIdx.x;
    if (idx >= H * H) return;
    int k = idx / H, j = idx % H;
    Bg[idx] = __float2half(Whh[(512 + j) * H + k]);
    if (k == 0) nb[2 * j + 1] = bhh[512 + j];
}

__global__ void bond_kernel(const float* __restrict__ ea, const float* __restrict__ W,
                            const float* __restrict__ b, float* __restrict__ out, int E)
{
    int e = blockIdx.x, c = threadIdx.x;
    __shared__ float row[16];
    if (c < BOND_IN) row[c] = ea[(size_t)e * BOND_IN + c];
    __syncthreads();
    float s = b[c];
    #pragma unroll
    for (int k = 0; k < BOND_IN; k++) s += row[k] * W[k * H + c];
    out[(size_t)e * H + c] = s;
}

// h_e[d] = LN(relu(h_all[src]+e_all)); fp16 copy into acat cols 256..511; scatter into m_in
__global__ void edge_init_kernel(const int* __restrict__ ei, const float* __restrict__ h_all,
                                 const float* __restrict__ e_all,
                                 const float* __restrict__ g, const float* __restrict__ be,
                                 float* __restrict__ h_e, __half* __restrict__ acat,
                                 float* __restrict__ m_in, int E)
{
    int d = blockIdx.x, c = threadIdx.x;
    int src = ei[d];
    int e = (d < E) ? d : d - E;
    float x = fmaxf(h_all[(size_t)src * H + c] + e_all[(size_t)e * H + c], 0.f);
    __shared__ float sh[8];
    float mu  = block_sum_256(x, sh) * (1.f / H);
    float dx  = x - mu;
    float var = block_sum_256(dx * dx, sh) * (1.f / H);
    float y   = dx * rsqrtf(var + EPS) * g[c] + be[c];
    h_e[(size_t)d * H + c] = y;
    acat[(size_t)d * ACAT_W + H + c] = __float2half(y);
    int dst = (d < E) ? ei[E + d] : ei[d - E];
    atomicAdd(&m_in[(size_t)dst * H + c], y);
}

__global__ void zero_kernel(float* __restrict__ p, size_t n) {
    size_t i = (size_t)blockIdx.x * blockDim.x + threadIdx.x;
    for (; i < n; i += (size_t)gridDim.x * blockDim.x) p[i] = 0.f;
}

__global__ void gather_kernel(const float* __restrict__ m_in, const float* __restrict__ h_e,
                              const int* __restrict__ ei, __half* __restrict__ out16, int E)
{
    int d = blockIdx.x, c = threadIdx.x;
    int src = ei[d];
    int rv  = (d < E) ? d + E : d - E;
    out16[(size_t)d * H + c] = __float2half(m_in[(size_t)src * H + c] - h_e[(size_t)rv * H + c]);
}

// LN of GRU output + optional acat fp16 copy + scatter into m_in
template<bool W16>
__global__ void ln_scatter_kernel(const float* __restrict__ x, const int* __restrict__ ei,
                                  const float* __restrict__ g, const float* __restrict__ be,
                                  float* __restrict__ outp, __half* __restrict__ acat,
                                  float* __restrict__ m_in, int E)
{
    int d = blockIdx.x, c = threadIdx.x;
    float v = x[(size_t)d * H + c];
    __shared__ float sh[8];
    float mu  = block_sum_256(v, sh) * (1.f / H);
    float dx  = v - mu;
    float var = block_sum_256(dx * dx, sh) * (1.f / H);
    float y   = dx * rsqrtf(var + EPS) * g[c] + be[c];
    outp[(size_t)d * H + c] = y;
    if (W16) acat[(size_t)d * ACAT_W + H + c] = __float2half(y);
    int dst = (d < E) ? ei[E + d] : ei[d - E];
    atomicAdd(&m_in[(size_t)dst * H + c], y);
}

__global__ void convert_min_kernel(const float* __restrict__ m_in, __half* __restrict__ aao, int N)
{
    size_t idx = (size_t)blockIdx.x * blockDim.x + threadIdx.x;
    size_t total = (size_t)N * H;
    for (; idx < total; idx += (size_t)gridDim.x * blockDim.x) {
        int n = (int)(idx / H), c = (int)(idx % H);
        aao[(size_t)n * AO_K + 165 + c] = __float2half(m_in[idx]);
    }
}

__global__ void relu_ln_kernel(const float* __restrict__ x,
                               const float* __restrict__ g, const float* __restrict__ be,
                               float* __restrict__ out)
{
    int nrow = blockIdx.x, c = threadIdx.x;
    float v = fmaxf(x[(size_t)nrow * H + c], 0.f);
    __shared__ float sh[8];
    float mu  = block_sum_256(v, sh) * (1.f / H);
    float dx  = v - mu;
    float var = block_sum_256(dx * dx, sh) * (1.f / H);
    out[(size_t)nrow * H + c] = dx * rsqrtf(var + EPS) * g[c] + be[c];
}

__global__ void graph_scatter_kernel(const float* __restrict__ h_atom, const int* __restrict__ batch,
                                     float* __restrict__ hgraph)
{
    int n = blockIdx.x, c = threadIdx.x;
    atomicAdd(&hgraph[batch[n] * H + c], h_atom[(size_t)n * H + c]);
}

__global__ void readout_kernel(const float* __restrict__ hgraph, const float* __restrict__ Wr,
                               const float* __restrict__ br, float* __restrict__ out)
{
    int gph = blockIdx.x, t = threadIdx.x;
    if (t < NUM_TASKS) {
        float s = br[t];
        const float* row = hgraph + gph * H;
        #pragma unroll 8
        for (int k = 0; k < H; k++) s += row[k] * Wr[k * NUM_TASKS + t];
        out[gph * NUM_TASKS + t] = s;
    }
}

// ---------------- host launcher ----------------
extern "C" void kernel_launch(void* const* d_in, const int* in_sizes, int n_in,
                              void* d_out, int out_size)
{
    const int*   x_z        = (const int*)  d_in[0];
    const float* x_atom     = (const float*)d_in[1];
    const int*   ei         = (const int*)  d_in[2];
    const float* edge_attr  = (const float*)d_in[3];
    const int*   batch      = (const int*)  d_in[4];
    const float* embed_z    = (const float*)d_in[5];
    const float* W_atom_in  = (const float*)d_in[6];
    const float* b_atom_in  = (const float*)d_in[7];
    const float* W_bond_in  = (const float*)d_in[8];
    const float* b_bond_in  = (const float*)d_in[9];
    const float* W_msg      = (const float*)d_in[10];
    const float* W_ih       = (const float*)d_in[11];
    const float* b_ih       = (const float*)d_in[12];
    const float* W_hh       = (const float*)d_in[13];
    const float* b_hh       = (const float*)d_in[14];
    const float* W_atom_out = (const float*)d_in[15];
    const float* b_atom_out = (const float*)d_in[16];
    const float* W_read     = (const float*)d_in[17];
    const float* b_read     = (const float*)d_in[18];
    const float* g_e        = (const float*)d_in[19];
    const float* be_e       = (const float*)d_in[20];
    const float* g_a        = (const float*)d_in[21];
    const float* be_a       = (const float*)d_in[22];

    const int N  = in_sizes[0];
    const int E  = in_sizes[2] / 2;
    const int E2 = 2 * E;

    float* out       = (float*)d_out;
    float* out_hatom = out + NUM_GRAPHS * NUM_TASKS;
    float* out_he    = out_hatom + (size_t)N * H;

    float  *h_all, *e_all, *h_e, *hpre, *m_in, *hgraph, *rzbias, *nbias;
    __half *a16, *aao, *acat, *mex16, *Gn, *wain, *wmsg, *wao, *brz, *bgin, *bghn;
    cudaGetSymbolAddress((void**)&h_all,  g_h_all);
    cudaGetSymbolAddress((void**)&e_all,  g_e_all);
    cudaGetSymbolAddress((void**)&h_e,    g_h_e);
    cudaGetSymbolAddress((void**)&hpre,   g_hpre);
    cudaGetSymbolAddress((void**)&m_in,   g_m_in);
    cudaGetSymbolAddress((void**)&hgraph, g_hgraph);
    cudaGetSymbolAddress((void**)&rzbias, g_rzbias);
    cudaGetSymbolAddress((void**)&nbias,  g_nbias);
    cudaGetSymbolAddress((void**)&a16,    g_a16);
    cudaGetSymbolAddress((void**)&aao,    g_aao);
    cudaGetSymbolAddress((void**)&acat,   g_acat);
    cudaGetSymbolAddress((void**)&mex16,  g_mex16);
    cudaGetSymbolAddress((void**)&Gn,     g_Gn);
    cudaGetSymbolAddress((void**)&wain,   g_wain);
    cudaGetSymbolAddress((void**)&wmsg,   g_wmsg);
    cudaGetSymbolAddress((void**)&wao,    g_wao);
    cudaGetSymbolAddress((void**)&brz,    g_brz);
    cudaGetSymbolAddress((void**)&bgin,   g_bgin);
    cudaGetSymbolAddress((void**)&bghn,   g_bghn);

    const size_t minN = (size_t)N * H;

    // prep
    zero_kernel<<<2048, 256>>>(m_in, minN);
    build_a16_kernel<<<4096, 256>>>(x_z, x_atom, embed_z, a16, aao, N);
    build_wain16<<<cdiv(AIN_K * H, 256), 256>>>(W_atom_in, wain);
    build_wmsg16<<<cdiv(H * H, 256), 256>>>(W_msg, wmsg);
    build_wao16<<<cdiv(AO_K * H, 256), 256>>>(W_atom_out, wao);
    build_brz_kernel<<<cdiv(ACAT_W * RZ_N, 256), 256>>>(W_ih, W_hh, b_ih, b_hh, brz, rzbias);
    build_bgin_kernel<<<cdiv(H * H, 256), 256>>>(W_ih, b_ih, bgin, nbias);
    build_bghn_kernel<<<cdiv(H * H, 256), 256>>>(W_hh, b_hh, bghn, nbias);

    // h_all = a_all @ W_atom_in + b
    hgemm_kernel<0><<<dim3(cdiv(H, GBN), cdiv(N, GBM)), 256>>>(
        a16, wain, b_atom_in, nullptr, h_all, nullptr, nullptr, nullptr,
        N, H, AIN_K, AIN_K, H, 0);
    bond_kernel<<<E, H>>>(edge_attr, W_bond_in, b_bond_in, e_all, E);
    // h_e init (LN) + acat copy + scatter into m_in
    edge_init_kernel<<<E2, H>>>(ei, h_all, e_all, g_e, be_e, h_e, acat, m_in, E);

    for (int depth = 0; depth < DEPTH; depth++) {
        // m_excl -> fp16
        gather_kernel<<<E2, H>>>(m_in, h_e, ei, mex16, E);
        // h_new = relu(h_e + m_excl @ W_msg) -> acat cols 0..255
        hgemm_kernel<1><<<dim3(cdiv(H, GBN), cdiv(E2, GBM)), 256>>>(
            mex16, wmsg, nullptr, nullptr, nullptr, acat, h_e, nullptr,
            E2, H, H, H, ACAT_W, 0);
        // gin = h_new @ Wih_n^T -> Gn even slots
        hgemm_kernel<2><<<dim3(cdiv(H, GBN), cdiv(E2, GBM)), 256>>>(
            acat, bgin, nullptr, nullptr, nullptr, Gn, nullptr, nullptr,
            E2, H, H, ACAT_W, RZ_N, 0);
        // ghn = h_e @ Whh_n^T -> Gn odd slots
        hgemm_kernel<2><<<dim3(cdiv(H, GBN), cdiv(E2, GBM)), 256>>>(
            acat + H, bghn, nullptr, nullptr, nullptr, Gn, nullptr, nullptr,
            E2, H, H, ACAT_W, RZ_N, 1);
        // zero m_in for the next scatter (after gather already consumed it)
        zero_kernel<<<2048, 256>>>(m_in, minN);
        // rz GEMM + fused GRU -> hpre
        hgemm_kernel<3><<<dim3(cdiv(RZ_N, GBN), cdiv(E2, GBM)), 256>>>(
            acat, brz, rzbias, nbias, hpre, nullptr, h_e, Gn,
            E2, RZ_N, ACAT_W, ACAT_W, RZ_N, 0);
        // LN + scatter (+acat copy except last depth)
        float* dst = (depth == DEPTH - 1) ? out_he : h_e;
        if (depth < DEPTH - 1)
            ln_scatter_kernel<true><<<E2, H>>>(hpre, ei, g_e, be_e, dst, acat, m_in, E);
        else
            ln_scatter_kernel<false><<<E2, H>>>(hpre, ei, g_e, be_e, dst, acat, m_in, E);
    }

    // m_to_atom already accumulated in m_in by the last ln_scatter
    convert_min_kernel<<<2048, 256>>>(m_in, aao, N);

    // h_atom = LN(relu([a_all | m_to_atom] @ W_atom_out + b))
    hgemm_kernel<0><<<dim3(cdiv(H, GBN), cdiv(N, GBM)), 256>>>(
        aao, wao, b_atom_out, nullptr, h_all, nullptr, nullptr, nullptr,
        N, H, AO_K, AO_K, H, 0);
    relu_ln_kernel<<<N, H>>>(h_all, g_a, be_a, out_hatom);

    // readout
    zero_kernel<<<64, 256>>>(hgraph, (size_t)NUM_GRAPHS * H);
    graph_scatter_kernel<<<N, H>>>(out_hatom, batch, hgraph);
    readout_kernel<<<NUM_GRAPHS, 32>>>(hgraph, W_read, b_read, out);
}

// round 9
// speedup vs baseline: 2.9707x; 1.0573x over previous
#include <cuda_runtime.h>
#include <cuda_fp16.h>
#include <stdint.h>
#include <cstdint>
#include <math.h>

// ---------------- problem constants ----------------
#define MAX_N 50000
#define MAX_E 200000
#define H 256
#define ATOM_IN 133
#define BOND_IN 14
#define NUM_TASKS 12
#define NUM_GRAPHS 256
#define DEPTH 3
#define EPS 1e-5f

#define AIN_K 192
#define AO_K  448
#define ACAT_W 512
#define RZ_N  512

// ---------------- scratch ----------------
__device__ float  g_h_all[(size_t)MAX_N * H];
__device__ float  g_e_all[(size_t)MAX_E * H];
__device__ float  g_h_e  [(size_t)(2*MAX_E) * H];
__device__ float  g_hpre [(size_t)(2*MAX_E) * H];
__device__ float  g_m_in [(size_t)MAX_N * H];
__device__ float  g_hgraph[NUM_GRAPHS * H];
__device__ float  g_rzbias[RZ_N];
__device__ float  g_nbias [RZ_N];
__device__ __half g_a16  [(size_t)MAX_N * AIN_K];
__device__ __half g_aao  [(size_t)MAX_N * AO_K];
__device__ __half g_acat [(size_t)(2*MAX_E) * ACAT_W];
__device__ __half g_mex16[(size_t)(2*MAX_E) * H];
__device__ __half g_Gn   [(size_t)(2*MAX_E) * RZ_N];
__device__ __half g_wain [AIN_K * H];
__device__ __half g_wmsg [H * H];
__device__ __half g_wao  [AO_K * H];
__device__ __half g_brz  [ACAT_W * RZ_N];
__device__ __half g_bgin [H * H];
__device__ __half g_bghn [H * H];

static inline int cdiv(int a, int b) { return (a + b - 1) / b; }

#define CP_ASYNC16(dst, src) asm volatile("cp.async.cg.shared.global [%0], [%1], 16;\n" :: "r"(dst), "l"(src))
#define CP_COMMIT()          asm volatile("cp.async.commit_group;\n")
#define CP_WAIT1()           asm volatile("cp.async.wait_group 1;\n")

// ---------------- mma.sync HGEMM, 3-stage cp.async pipeline ----------------
#define GBM 128
#define GBN 128
#define GBK 32
#define SPAD 8
#define STAGES 3
#define A_STG (GBM * (GBK + SPAD))     // halves per A stage: 5120
#define B_STG (GBK * (GBN + SPAD))     // halves per B stage: 4352
#define GEMM_SMEM (STAGES * (A_STG + B_STG) * 2)   // 56832 bytes

__device__ __forceinline__ void ldsm_x4(uint32_t& r0, uint32_t& r1, uint32_t& r2, uint32_t& r3, uint32_t addr) {
    asm volatile("ldmatrix.sync.aligned.m8n8.x4.shared.b16 {%0,%1,%2,%3}, [%4];\n"
                 : "=r"(r0), "=r"(r1), "=r"(r2), "=r"(r3) : "r"(addr));
}
__device__ __forceinline__ void ldsm_x4t(uint32_t& r0, uint32_t& r1, uint32_t& r2, uint32_t& r3, uint32_t addr) {
    asm volatile("ldmatrix.sync.aligned.m8n8.x4.trans.shared.b16 {%0,%1,%2,%3}, [%4];\n"
                 : "=r"(r0), "=r"(r1), "=r"(r2), "=r"(r3) : "r"(addr));
}
__device__ __forceinline__ void mma_16816(float* d, const uint32_t* a, const uint32_t* b) {
    asm volatile("mma.sync.aligned.m16n8k16.row.col.f32.f16.f16.f32 "
                 "{%0,%1,%2,%3}, {%4,%5,%6,%7}, {%8,%9}, {%0,%1,%2,%3};\n"
                 : "+f"(d[0]), "+f"(d[1]), "+f"(d[2]), "+f"(d[3])
                 : "r"(a[0]), "r"(a[1]), "r"(a[2]), "r"(a[3]), "r"(b[0]), "r"(b[1]));
}

__device__ __forceinline__ void hgemm_load_tile(
    const __half* __restrict__ A, const __half* __restrict__ B,
    __half* smA, __half* smB,
    int kt, int s, int bm, int bn, int M, int N, int K, int ldA,
    int ar, int ac, int br, int bc)
{
    const int k0 = kt * GBK;
    __half* as = smA + s * A_STG;
    __half* bs = smB + s * B_STG;
    #pragma unroll
    for (int i = 0; i < 2; i++) {
        int r  = ar + i * 64;
        int gr = bm + r; if (gr >= M) gr = M - 1;
        const __half* src = A + (size_t)gr * ldA + k0 + ac;
        uint32_t dst = (uint32_t)__cvta_generic_to_shared(as + r * (GBK + SPAD) + ac);
        CP_ASYNC16(dst, src);
    }
    #pragma unroll
    for (int i = 0; i < 2; i++) {
        int r = br + i * 16;
        const __half* src = B + (size_t)(k0 + r) * N + bn + bc;
        uint32_t dst = (uint32_t)__cvta_generic_to_shared(bs + r * (GBN + SPAD) + bc);
        CP_ASYNC16(dst, src);
    }
}

__device__ __forceinline__ float sigmoidf_(float x) { return 1.f / (1.f + expf(-x)); }

// EPI 0: outF = acc + bias[col]
// EPI 1: outH = half(relu(acc + aux[row*H+col]))          (msg -> acat h_new)
// EPI 2: outH[row*ldOut + 2*col + colOff] = half(acc)     (gin/ghn -> Gn interleaved)
// EPI 3: fused GRU (r,z in acc pair; gin,ghn in auxH; hprev in aux) -> outF[row*H + j]
template<int EPI>
__global__ __launch_bounds__(256, 2) void hgemm_kernel(
    const __half* __restrict__ A, const __half* __restrict__ B,
    const float* __restrict__ bias, const float* __restrict__ bias2,
    float* __restrict__ outF, __half* __restrict__ outH,
    const float* __restrict__ aux, const __half* __restrict__ auxH,
    int M, int N, int K, int ldA, int ldOut, int colOff)
{
    extern __shared__ __align__(16) __half sm[];
    __half* smA = sm;
    __half* smB = sm + STAGES * A_STG;

    const int tid  = threadIdx.x;
    const int lane = tid & 31;
    const int warp = tid >> 5;
    const int wm   = warp & 3;
    const int wn   = warp >> 2;
    const int bm   = blockIdx.y * GBM;
    const int bn   = blockIdx.x * GBN;

    float acc[2][8][4];
    #pragma unroll
    for (int i = 0; i < 2; i++)
        #pragma unroll
        for (int j = 0; j < 8; j++)
            #pragma unroll
            for (int k = 0; k < 4; k++) acc[i][j][k] = 0.f;

    const int ar = tid >> 2;
    const int ac = (tid & 3) << 3;
    const int br = tid >> 4;
    const int bc = (tid & 15) << 3;
    const int KT = K / GBK;

    #pragma unroll
    for (int p = 0; p < STAGES - 1; p++) {
        if (p < KT) {
            hgemm_load_tile(A, B, smA, smB, p, p, bm, bn, M, N, K, ldA, ar, ac, br, bc);
        }
        CP_COMMIT();   // commit even if empty to keep group accounting simple
    }

    for (int kt = 0; kt < KT; kt++) {
        CP_WAIT1();
        __syncthreads();
        const int s = kt % STAGES;
        if (kt + STAGES - 1 < KT) {
            hgemm_load_tile(A, B, smA, smB, kt + STAGES - 1, (kt + STAGES - 1) % STAGES,
                            bm, bn, M, N, K, ldA, ar, ac, br, bc);
        }
        CP_COMMIT();

        __half* as = smA + s * A_STG;
        __half* bs = smB + s * B_STG;
        #pragma unroll
        for (int ks = 0; ks < 2; ks++) {
            const int k0 = ks * 16;
            uint32_t af[2][4];
            #pragma unroll
            for (int mi = 0; mi < 2; mi++) {
                int row = wm * 32 + mi * 16 + (lane & 15);
                int col = k0 + ((lane >> 4) << 3);
                uint32_t ad = (uint32_t)__cvta_generic_to_shared(as + row * (GBK + SPAD) + col);
                ldsm_x4(af[mi][0], af[mi][1], af[mi][2], af[mi][3], ad);
            }
            uint32_t bf[8][2];
            #pragma unroll
            for (int nq = 0; nq < 4; nq++) {
                int row = k0 + (lane & 15);
                int col = wn * 64 + nq * 16 + ((lane >> 4) << 3);
                uint32_t bd = (uint32_t)__cvta_generic_to_shared(bs + row * (GBN + SPAD) + col);
                ldsm_x4t(bf[nq*2][0], bf[nq*2][1], bf[nq*2+1][0], bf[nq*2+1][1], bd);
            }
            #pragma unroll
            for (int mi = 0; mi < 2; mi++)
                #pragma unroll
                for (int nj = 0; nj < 8; nj++)
                    mma_16816(acc[mi][nj], af[mi], bf[nj]);
        }
        __syncthreads();
    }

    const int r0 = bm + wm * 32 + (lane >> 2);
    const int c0 = bn + wn * 64 + ((lane & 3) << 1);
    #pragma unroll
    for (int mi = 0; mi < 2; mi++) {
        #pragma unroll
        for (int nj = 0; nj < 8; nj++) {
            const int col = c0 + nj * 8;
            #pragma unroll
            for (int hh = 0; hh < 2; hh++) {
                const int row = r0 + mi * 16 + hh * 8;
                if (row >= M) continue;
                float v0 = acc[mi][nj][hh * 2 + 0];
                float v1 = acc[mi][nj][hh * 2 + 1];
                if (EPI == 0) {
                    outF[(size_t)row * ldOut + col]     = v0 + bias[col];
                    outF[(size_t)row * ldOut + col + 1] = v1 + bias[col + 1];
                } else if (EPI == 1) {
                    v0 = fmaxf(v0 + aux[(size_t)row * H + col],     0.f);
                    v1 = fmaxf(v1 + aux[(size_t)row * H + col + 1], 0.f);
                    outH[(size_t)row * ldOut + col]     = __float2half(v0);
                    outH[(size_t)row * ldOut + col + 1] = __float2half(v1);
                } else if (EPI == 2) {
                    outH[(size_t)row * ldOut + 2 * col + colOff]       = __float2half(v0);
                    outH[(size_t)row * ldOut + 2 * (col + 1) + colOff] = __float2half(v1);
                } else {
                    float r = sigmoidf_(v0 + bias[col]);
                    float z = sigmoidf_(v1 + bias[col + 1]);
                    __half2 gh2 = *(const __half2*)(auxH + (size_t)row * ldOut + col);
                    float gin = __low2float(gh2)  + bias2[col];
                    float ghn = __high2float(gh2) + bias2[col + 1];
                    float n = tanhf(gin + r * ghn);
                    int j = col >> 1;
                    float hp = aux[(size_t)row * H + j];
                    outF[(size_t)row * H + j] = (1.f - z) * n + z * hp;
                }
            }
        }
    }
}

// ---------------- warp-per-row helpers (H=256: lane covers 8 cols) ----------------

__device__ __forceinline__ void warp_ln_8(float* v, int lane,
                                          const float* __restrict__ g,
                                          const float* __restrict__ be,
                                          float* y)
{
    float sum = 0.f, sq = 0.f;
    #pragma unroll
    for (int i = 0; i < 8; i++) { sum += v[i]; sq += v[i] * v[i]; }
    #pragma unroll
    for (int o = 16; o > 0; o >>= 1) {
        sum += __shfl_xor_sync(0xffffffffu, sum, o);
        sq  += __shfl_xor_sync(0xffffffffu, sq,  o);
    }
    float mu = sum * (1.f / H);
    float var = sq * (1.f / H) - mu * mu;
    float rs = rsqrtf(var + EPS);
    const float4* g4  = (const float4*)(g  + lane * 8);
    const float4* be4 = (const float4*)(be + lane * 8);
    float4 ga = g4[0], gb = g4[1], ba = be4[0], bb = be4[1];
    y[0] = (v[0] - mu) * rs * ga.x + ba.x;
    y[1] = (v[1] - mu) * rs * ga.y + ba.y;
    y[2] = (v[2] - mu) * rs * ga.z + ba.z;
    y[3] = (v[3] - mu) * rs * ga.w + ba.w;
    y[4] = (v[4] - mu) * rs * gb.x + bb.x;
    y[5] = (v[5] - mu) * rs * gb.y + bb.y;
    y[6] = (v[6] - mu) * rs * gb.z + bb.z;
    y[7] = (v[7] - mu) * rs * gb.w + bb.w;
}

__device__ __forceinline__ void store_half8(__half* p, const float* y) {
    __half2 h0 = __floats2half2_rn(y[0], y[1]);
    __half2 h1 = __floats2half2_rn(y[2], y[3]);
    __half2 h2 = __floats2half2_rn(y[4], y[5]);
    __half2 h3 = __floats2half2_rn(y[6], y[7]);
    uint4 u;
    u.x = *(uint32_t*)&h0; u.y = *(uint32_t*)&h1;
    u.z = *(uint32_t*)&h2; u.w = *(uint32_t*)&h3;
    *(uint4*)p = u;
}

// h_e init: LN(relu(h_all[src]+e_all)) + acat copy + scatter
__global__ void edge_init_kernel(const int* __restrict__ ei, const float* __restrict__ h_all,
                                 const float* __restrict__ e_all,
                                 const float* __restrict__ g, const float* __restrict__ be,
                                 float* __restrict__ h_e, __half* __restrict__ acat,
                                 float* __restrict__ m_in, int E)
{
    int d = blockIdx.x * 8 + (threadIdx.x >> 5);
    if (d >= 2 * E) return;
    int lane = threadIdx.x & 31;
    int src = ei[d];
    int e = (d < E) ? d : d - E;
    const float4* ha = (const float4*)(h_all + (size_t)src * H + lane * 8);
    const float4* ea = (const float4*)(e_all + (size_t)e * H + lane * 8);
    float4 a0 = ha[0], a1 = ha[1], b0 = ea[0], b1 = ea[1];
    float v[8] = {
        fmaxf(a0.x + b0.x, 0.f), fmaxf(a0.y + b0.y, 0.f),
        fmaxf(a0.z + b0.z, 0.f), fmaxf(a0.w + b0.w, 0.f),
        fmaxf(a1.x + b1.x, 0.f), fmaxf(a1.y + b1.y, 0.f),
        fmaxf(a1.z + b1.z, 0.f), fmaxf(a1.w + b1.w, 0.f) };
    float y[8];
    warp_ln_8(v, lane, g, be, y);
    float4* he4 = (float4*)(h_e + (size_t)d * H + lane * 8);
    he4[0] = make_float4(y[0], y[1], y[2], y[3]);
    he4[1] = make_float4(y[4], y[5], y[6], y[7]);
    store_half8(acat + (size_t)d * ACAT_W + H + lane * 8, y);
    int dst = (d < E) ? ei[E + d] : ei[d - E];
    float* mb = m_in + (size_t)dst * H + lane * 8;
    #pragma unroll
    for (int i = 0; i < 8; i++) atomicAdd(mb + i, y[i]);
}

// LN of GRU output + optional acat copy + scatter
template<bool W16>
__global__ void ln_scatter_kernel(const float* __restrict__ x, const int* __restrict__ ei,
                                  const float* __restrict__ g, const float* __restrict__ be,
                                  float* __restrict__ outp, __half* __restrict__ acat,
                                  float* __restrict__ m_in, int E)
{
    int d = blockIdx.x * 8 + (threadIdx.x >> 5);
    if (d >= 2 * E) return;
    int lane = threadIdx.x & 31;
    const float4* xr = (const float4*)(x + (size_t)d * H + lane * 8);
    float4 x0 = xr[0], x1 = xr[1];
    float v[8] = {x0.x, x0.y, x0.z, x0.w, x1.x, x1.y, x1.z, x1.w};
    float y[8];
    warp_ln_8(v, lane, g, be, y);
    float4* o4 = (float4*)(outp + (size_t)d * H + lane * 8);
    o4[0] = make_float4(y[0], y[1], y[2], y[3]);
    o4[1] = make_float4(y[4], y[5], y[6], y[7]);
    if (W16) store_half8(acat + (size_t)d * ACAT_W + H + lane * 8, y);
    int dst = (d < E) ? ei[E + d] : ei[d - E];
    float* mb = m_in + (size_t)dst * H + lane * 8;
    #pragma unroll
    for (int i = 0; i < 8; i++) atomicAdd(mb + i, y[i]);
}

// mex16[d] = half(m_in[src[d]] - h_e[rev[d]])
__global__ void gather_kernel(const float* __restrict__ m_in, const float* __restrict__ h_e,
                              const int* __restrict__ ei, __half* __restrict__ out16, int E)
{
    int d = blockIdx.x * 8 + (threadIdx.x >> 5);
    if (d >= 2 * E) return;
    int lane = threadIdx.x & 31;
    int src = ei[d];
    int rv  = (d < E) ? d + E : d - E;
    const float4* ma = (const float4*)(m_in + (size_t)src * H + lane * 8);
    const float4* hb = (const float4*)(h_e + (size_t)rv * H + lane * 8);
    float4 m0 = ma[0], m1 = ma[1], h0 = hb[0], h1 = hb[1];
    float y[8] = {m0.x - h0.x, m0.y - h0.y, m0.z - h0.z, m0.w - h0.w,
                  m1.x - h1.x, m1.y - h1.y, m1.z - h1.z, m1.w - h1.w};
    store_half8(out16 + (size_t)d * H + lane * 8, y);
}

// h_atom = LN(relu(x)) -> out; also atomicAdd into hgraph[batch[n]]
__global__ void relu_ln_graph_kernel(const float* __restrict__ x, const int* __restrict__ batch,
                                     const float* __restrict__ g, const float* __restrict__ be,
                                     float* __restrict__ out, float* __restrict__ hgraph, int N)
{
    int n = blockIdx.x * 8 + (threadIdx.x >> 5);
    if (n >= N) return;
    int lane = threadIdx.x & 31;
    const float4* xr = (const float4*)(x + (size_t)n * H + lane * 8);
    float4 x0 = xr[0], x1 = xr[1];
    float v[8] = {fmaxf(x0.x, 0.f), fmaxf(x0.y, 0.f), fmaxf(x0.z, 0.f), fmaxf(x0.w, 0.f),
                  fmaxf(x1.x, 0.f), fmaxf(x1.y, 0.f), fmaxf(x1.z, 0.f), fmaxf(x1.w, 0.f)};
    float y[8];
    warp_ln_8(v, lane, g, be, y);
    float4* o4 = (float4*)(out + (size_t)n * H + lane * 8);
    o4[0] = make_float4(y[0], y[1], y[2], y[3]);
    o4[1] = make_float4(y[4], y[5], y[6], y[7]);
    float* hb = hgraph + (size_t)batch[n] * H + lane * 8;
    #pragma unroll
    for (int i = 0; i < 8; i++) atomicAdd(hb + i, y[i]);
}

// ---------------- prep / misc ----------------
__global__ void build_a16_kernel(const int* __restrict__ xz, const float* __restrict__ xa,
                                 const float* __restrict__ emb,
                                 __half* __restrict__ a16, __half* __restrict__ aao, int N)
{
    size_t idx = (size_t)blockIdx.x * blockDim.x + threadIdx.x;
    size_t total = (size_t)N * AO_K;
    for (; idx < total; idx += (size_t)gridDim.x * blockDim.x) {
        int n = (int)(idx / AO_K);
        int c = (int)(idx % AO_K);
        if (c < AIN_K) {
            float v = (c < 32) ? emb[xz[n] * 32 + c]
                    : (c < 165) ? xa[(size_t)n * ATOM_IN + (c - 32)] : 0.f;
            __half h = __float2half(v);
            a16[(size_t)n * AIN_K + c] = h;
            if (c < 165) aao[(size_t)n * AO_K + c] = h;
        } else if (c >= 421) {
            aao[idx] = __float2half(0.f);
        }
    }
}

__global__ void build_wain16(const float* __restrict__ W, __half* __restrict__ O) {
    int idx = blockIdx.x * blockDim.x + threadIdx.x;
    if (idx >= AIN_K * H) return;
    int k = idx / H, c = idx % H;
    O[idx] = __float2half(k < 165 ? W[k * H + c] : 0.f);
}
__global__ void build_wmsg16(const float* __restrict__ W, __half* __restrict__ O) {
    int idx = blockIdx.x * blockDim.x + threadIdx.x;
    if (idx < H * H) O[idx] = __float2half(W[idx]);
}
__global__ void build_wao16(const float* __restrict__ W, __half* __restrict__ O) {
    int idx = blockIdx.x * blockDim.x + threadIdx.x;
    if (idx >= AO_K * H) return;
    int k = idx / H, c = idx % H;
    O[idx] = __float2half(k < 421 ? W[k * H + c] : 0.f);
}

__global__ void build_brz_kernel(const float* __restrict__ Wih, const float* __restrict__ Whh,
                                 const float* __restrict__ bih, const float* __restrict__ bhh,
                                 __half* __restrict__ Brz, float* __restrict__ rzb)
{
    int idx = blockIdx.x * blockDim.x + threadIdx.x;
    if (idx >= ACAT_W * RZ_N) return;
    int k = idx / RZ_N, c = idx % RZ_N;
    int j = c >> 1;
    int gateRow = (c & 1) ? (256 + j) : j;
    float v = (k < 256) ? Wih[gateRow * H + k] : Whh[gateRow * H + (k - 256)];
    Brz[idx] = __float2half(v);
    if (k == 0) rzb[c] = bih[gateRow] + bhh[gateRow];
}
__global__ void build_bgin_kernel(const float* __restrict__ Wih, const float* __restrict__ bih,
                                  __half* __restrict__ Bg, float* __restrict__ nb)
{
    int idx = blockIdx.x * blockDim.x + threadIdx.x;
    if (idx >= H * H) return;
    int k = idx / H, j = idx % H;
    Bg[idx] = __float2half(Wih[(512 + j) * H + k]);
    if (k == 0) nb[2 * j] = bih[512 + j];
}
__global__ void build_bghn_kernel(const float* __restrict__ Whh, const float* __restrict__ bhh,
                                  __half* __restrict__ Bg, float* __restrict__ nb)
{
    int idx = blockIdx.x * blockDim.x + threadIdx.x;
    if (idx >= H * H) return;
    int k = idx / H, j = idx % H;
    Bg[idx] = __float2half(Whh[(512 + j) * H + k]);
    if (k == 0) nb[2 * j + 1] = bhh[512 + j];
}

__global__ void bond_kernel(const float* __restrict__ ea, const float* __restrict__ W,
                            const float* __restrict__ b, float* __restrict__ out, int E)
{
    int e = blockIdx.x, c = threadIdx.x;
    __shared__ float row[16];
    if (c < BOND_IN) row[c] = ea[(size_t)e * BOND_IN + c];
    __syncthreads();
    float s = b[c];
    #pragma unroll
    for (int k = 0; k < BOND_IN; k++) s += row[k] * W[k * H + c];
    out[(size_t)e * H + c] = s;
}

__global__ void zero_kernel(float4* __restrict__ p, size_t n4) {
    size_t i = (size_t)blockIdx.x * blockDim.x + threadIdx.x;
    for (; i < n4; i += (size_t)gridDim.x * blockDim.x)
        p[i] = make_float4(0.f, 0.f, 0.f, 0.f);
}

__global__ void convert_min_kernel(const float* __restrict__ m_in, __half* __restrict__ aao, int N)
{
    size_t idx = (size_t)blockIdx.x * blockDim.x + threadIdx.x;
    size_t total = (size_t)N * H;
    for (; idx < total; idx += (size_t)gridDim.x * blockDim.x) {
        int n = (int)(idx / H), c = (int)(idx % H);
        aao[(size_t)n * AO_K + 165 + c] = __float2half(m_in[idx]);
    }
}

__global__ void readout_kernel(const float* __restrict__ hgraph, const float* __restrict__ Wr,
                               const float* __restrict__ br, float* __restrict__ out)
{
    int gph = blockIdx.x, t = threadIdx.x;
    if (t < NUM_TASKS) {
        float s = br[t];
        const float* row = hgraph + gph * H;
        #pragma unroll 8
        for (int k = 0; k < H; k++) s += row[k] * Wr[k * NUM_TASKS + t];
        out[gph * NUM_TASKS + t] = s;
    }
}

// ---------------- host launcher ----------------
extern "C" void kernel_launch(void* const* d_in, const int* in_sizes, int n_in,
                              void* d_out, int out_size)
{
    const int*   x_z        = (const int*)  d_in[0];
    const float* x_atom     = (const float*)d_in[1];
    const int*   ei         = (const int*)  d_in[2];
    const float* edge_attr  = (const float*)d_in[3];
    const int*   batch      = (const int*)  d_in[4];
    const float* embed_z    = (const float*)d_in[5];
    const float* W_atom_in  = (const float*)d_in[6];
    const float* b_atom_in  = (const float*)d_in[7];
    const float* W_bond_in  = (const float*)d_in[8];
    const float* b_bond_in  = (const float*)d_in[9];
    const float* W_msg      = (const float*)d_in[10];
    const float* W_ih       = (const float*)d_in[11];
    const float* b_ih       = (const float*)d_in[12];
    const float* W_hh       = (const float*)d_in[13];
    const float* b_hh       = (const float*)d_in[14];
    const float* W_atom_out = (const float*)d_in[15];
    const float* b_atom_out = (const float*)d_in[16];
    const float* W_read     = (const float*)d_in[17];
    const float* b_read     = (const float*)d_in[18];
    const float* g_e        = (const float*)d_in[19];
    const float* be_e       = (const float*)d_in[20];
    const float* g_a        = (const float*)d_in[21];
    const float* be_a       = (const float*)d_in[22];

    const int N  = in_sizes[0];
    const int E  = in_sizes[2] / 2;
    const int E2 = 2 * E;

    float* out       = (float*)d_out;
    float* out_hatom = out + NUM_GRAPHS * NUM_TASKS;
    float* out_he    = out_hatom + (size_t)N * H;

    float  *h_all, *e_all, *h_e, *hpre, *m_in, *hgraph, *rzbias, *nbias;
    __half *a16, *aao, *acat, *mex16, *Gn, *wain, *wmsg, *wao, *brz, *bgin, *bghn;
    cudaGetSymbolAddress((void**)&h_all,  g_h_all);
    cudaGetSymbolAddress((void**)&e_all,  g_e_all);
    cudaGetSymbolAddress((void**)&h_e,    g_h_e);
    cudaGetSymbolAddress((void**)&hpre,   g_hpre);
    cudaGetSymbolAddress((void**)&m_in,   g_m_in);
    cudaGetSymbolAddress((void**)&hgraph, g_hgraph);
    cudaGetSymbolAddress((void**)&rzbias, g_rzbias);
    cudaGetSymbolAddress((void**)&nbias,  g_nbias);
    cudaGetSymbolAddress((void**)&a16,    g_a16);
    cudaGetSymbolAddress((void**)&aao,    g_aao);
    cudaGetSymbolAddress((void**)&acat,   g_acat);
    cudaGetSymbolAddress((void**)&mex16,  g_mex16);
    cudaGetSymbolAddress((void**)&Gn,     g_Gn);
    cudaGetSymbolAddress((void**)&wain,   g_wain);
    cudaGetSymbolAddress((void**)&wmsg,   g_wmsg);
    cudaGetSymbolAddress((void**)&wao,    g_wao);
    cudaGetSymbolAddress((void**)&brz,    g_brz);
    cudaGetSymbolAddress((void**)&bgin,   g_bgin);
    cudaGetSymbolAddress((void**)&bghn,   g_bghn);

    cudaFuncSetAttribute(hgemm_kernel<0>, cudaFuncAttributeMaxDynamicSharedMemorySize, GEMM_SMEM);
    cudaFuncSetAttribute(hgemm_kernel<1>, cudaFuncAttributeMaxDynamicSharedMemorySize, GEMM_SMEM);
    cudaFuncSetAttribute(hgemm_kernel<2>, cudaFuncAttributeMaxDynamicSharedMemorySize, GEMM_SMEM);
    cudaFuncSetAttribute(hgemm_kernel<3>, cudaFuncAttributeMaxDynamicSharedMemorySize, GEMM_SMEM);

    const size_t minN4 = (size_t)N * H / 4;

    // prep
    zero_kernel<<<1024, 256>>>((float4*)m_in, minN4);
    build_a16_kernel<<<4096, 256>>>(x_z, x_atom, embed_z, a16, aao, N);
    build_wain16<<<cdiv(AIN_K * H, 256), 256>>>(W_atom_in, wain);
    build_wmsg16<<<cdiv(H * H, 256), 256>>>(W_msg, wmsg);
    build_wao16<<<cdiv(AO_K * H, 256), 256>>>(W_atom_out, wao);
    build_brz_kernel<<<cdiv(ACAT_W * RZ_N, 256), 256>>>(W_ih, W_hh, b_ih, b_hh, brz, rzbias);
    build_bgin_kernel<<<cdiv(H * H, 256), 256>>>(W_ih, b_ih, bgin, nbias);
    build_bghn_kernel<<<cdiv(H * H, 256), 256>>>(W_hh, b_hh, bghn, nbias);

    // h_all = a_all @ W_atom_in + b
    hgemm_kernel<0><<<dim3(cdiv(H, GBN), cdiv(N, GBM)), 256, GEMM_SMEM>>>(
        a16, wain, b_atom_in, nullptr, h_all, nullptr, nullptr, nullptr,
        N, H, AIN_K, AIN_K, H, 0);
    bond_kernel<<<E, H>>>(edge_attr, W_bond_in, b_bond_in, e_all, E);
    edge_init_kernel<<<cdiv(E2, 8), 256>>>(ei, h_all, e_all, g_e, be_e, h_e, acat, m_in, E);

    for (int depth = 0; depth < DEPTH; depth++) {
        gather_kernel<<<cdiv(E2, 8), 256>>>(m_in, h_e, ei, mex16, E);
        // h_new = relu(h_e + m_excl @ W_msg) -> acat cols 0..255
        hgemm_kernel<1><<<dim3(cdiv(H, GBN), cdiv(E2, GBM)), 256, GEMM_SMEM>>>(
            mex16, wmsg, nullptr, nullptr, nullptr, acat, h_e, nullptr,
            E2, H, H, H, ACAT_W, 0);
        // gin / ghn -> Gn interleaved
        hgemm_kernel<2><<<dim3(cdiv(H, GBN), cdiv(E2, GBM)), 256, GEMM_SMEM>>>(
            acat, bgin, nullptr, nullptr, nullptr, Gn, nullptr, nullptr,
            E2, H, H, ACAT_W, RZ_N, 0);
        hgemm_kernel<2><<<dim3(cdiv(H, GBN), cdiv(E2, GBM)), 256, GEMM_SMEM>>>(
            acat + H, bghn, nullptr, nullptr, nullptr, Gn, nullptr, nullptr,
            E2, H, H, ACAT_W, RZ_N, 1);
        zero_kernel<<<1024, 256>>>((float4*)m_in, minN4);
        // rz GEMM + fused GRU -> hpre
        hgemm_kernel<3><<<dim3(cdiv(RZ_N, GBN), cdiv(E2, GBM)), 256, GEMM_SMEM>>>(
            acat, brz, rzbias, nbias, hpre, nullptr, h_e, Gn,
            E2, RZ_N, ACAT_W, ACAT_W, RZ_N, 0);
        // LN + scatter (+acat copy except last depth)
        float* dst = (depth == DEPTH - 1) ? out_he : h_e;
        if (depth < DEPTH - 1)
            ln_scatter_kernel<true><<<cdiv(E2, 8), 256>>>(hpre, ei, g_e, be_e, dst, acat, m_in, E);
        else
            ln_scatter_kernel<false><<<cdiv(E2, 8), 256>>>(hpre, ei, g_e, be_e, dst, acat, m_in, E);
    }

    // m_to_atom accumulated by last ln_scatter
    convert_min_kernel<<<2048, 256>>>(m_in, aao, N);

    // h_atom = LN(relu([a_all | m_to_atom] @ W_atom_out + b)); readout sum fused
    hgemm_kernel<0><<<dim3(cdiv(H, GBN), cdiv(N, GBM)), 256, GEMM_SMEM>>>(
        aao, wao, b_atom_out, nullptr, h_all, nullptr, nullptr, nullptr,
        N, H, AO_K, AO_K, H, 0);
    zero_kernel<<<64, 256>>>((float4*)hgraph, (size_t)NUM_GRAPHS * H / 4);
    relu_ln_graph_kernel<<<cdiv(N, 8), 256>>>(h_all, batch, g_a, be_a, out_hatom, hgraph, N);
    readout_kernel<<<NUM_GRAPHS, 32>>>(hgraph, W_read, b_read, out);
}

// round 10
// speedup vs baseline: 3.8477x; 1.2952x over previous
#include <cuda_runtime.h>
#include <cuda_fp16.h>
#include <stdint.h>
#include <cstdint>
#include <math.h>

// ---------------- problem constants ----------------
#define MAX_N 50000
#define MAX_E 200000
#define H 256
#define ATOM_IN 133
#define BOND_IN 14
#define NUM_TASKS 12
#define NUM_GRAPHS 256
#define DEPTH 3
#define EPS 1e-5f

#define AIN_K 192
#define AO_K  448
#define ACAT_W 512
#define RZ_N  512

// ---------------- scratch ----------------
__device__ float  g_h_all[(size_t)MAX_N * H];
__device__ float  g_h_e  [(size_t)(2*MAX_E) * H];
__device__ float  g_hpre [(size_t)(2*MAX_E) * H];
__device__ float  g_m_in [(size_t)MAX_N * H];
__device__ float  g_hgraph[NUM_GRAPHS * H];
__device__ float  g_rzbias[RZ_N];
__device__ float  g_nbias [RZ_N];
__device__ __half g_a16  [(size_t)MAX_N * AIN_K];
__device__ __half g_aao  [(size_t)MAX_N * AO_K];
__device__ __half g_acat [(size_t)(2*MAX_E) * ACAT_W];
__device__ __half g_mex16[(size_t)(2*MAX_E) * H];
__device__ __half g_Gn   [(size_t)(2*MAX_E) * RZ_N];     // [gin(256) | ghn(256)] blocked
__device__ __half g_wain [AIN_K * H];
__device__ __half g_wmsg [H * H];
__device__ __half g_wao  [AO_K * H];
__device__ __half g_brz  [ACAT_W * RZ_N];
__device__ __half g_bgin [H * H];
__device__ __half g_bghn [H * H];

static inline int cdiv(int a, int b) { return (a + b - 1) / b; }

#define CP_ASYNC16(dst, src) asm volatile("cp.async.cg.shared.global [%0], [%1], 16;\n" :: "r"(dst), "l"(src))
#define CP_COMMIT()          asm volatile("cp.async.commit_group;\n")
#define CP_WAIT2()           asm volatile("cp.async.wait_group 2;\n")

// vector fp32 reduction (sm_90+): 4 adds in one L2 atomic op
__device__ __forceinline__ void red_add_v4(float* p, float a, float b, float c, float d) {
    asm volatile("red.global.v4.f32.add [%0], {%1,%2,%3,%4};"
                 :: "l"(p), "f"(a), "f"(b), "f"(c), "f"(d) : "memory");
}

// ---------------- mma.sync HGEMM, 4-stage cp.async pipeline ----------------
#define GBM 128
#define GBN 128
#define GBK 32
#define SPAD 8
#define STAGES 4
#define A_STG (GBM * (GBK + SPAD))
#define B_STG (GBK * (GBN + SPAD))
#define GEMM_SMEM (STAGES * (A_STG + B_STG) * 2)   // 75776 bytes

__device__ __forceinline__ void ldsm_x4(uint32_t& r0, uint32_t& r1, uint32_t& r2, uint32_t& r3, uint32_t addr) {
    asm volatile("ldmatrix.sync.aligned.m8n8.x4.shared.b16 {%0,%1,%2,%3}, [%4];\n"
                 : "=r"(r0), "=r"(r1), "=r"(r2), "=r"(r3) : "r"(addr));
}
__device__ __forceinline__ void ldsm_x4t(uint32_t& r0, uint32_t& r1, uint32_t& r2, uint32_t& r3, uint32_t addr) {
    asm volatile("ldmatrix.sync.aligned.m8n8.x4.trans.shared.b16 {%0,%1,%2,%3}, [%4];\n"
                 : "=r"(r0), "=r"(r1), "=r"(r2), "=r"(r3) : "r"(addr));
}
__device__ __forceinline__ void mma_16816(float* d, const uint32_t* a, const uint32_t* b) {
    asm volatile("mma.sync.aligned.m16n8k16.row.col.f32.f16.f16.f32 "
                 "{%0,%1,%2,%3}, {%4,%5,%6,%7}, {%8,%9}, {%0,%1,%2,%3};\n"
                 : "+f"(d[0]), "+f"(d[1]), "+f"(d[2]), "+f"(d[3])
                 : "r"(a[0]), "r"(a[1]), "r"(a[2]), "r"(a[3]), "r"(b[0]), "r"(b[1]));
}

__device__ __forceinline__ void hgemm_load_tile(
    const __half* __restrict__ A, const __half* __restrict__ B,
    __half* smA, __half* smB,
    int kt, int s, int bm, int bn, int M, int N, int K, int ldA,
    int ar, int ac, int br, int bc)
{
    const int k0 = kt * GBK;
    __half* as = smA + s * A_STG;
    __half* bs = smB + s * B_STG;
    #pragma unroll
    for (int i = 0; i < 2; i++) {
        int r  = ar + i * 64;
        int gr = bm + r; if (gr >= M) gr = M - 1;
        const __half* src = A + (size_t)gr * ldA + k0 + ac;
        uint32_t dst = (uint32_t)__cvta_generic_to_shared(as + r * (GBK + SPAD) + ac);
        CP_ASYNC16(dst, src);
    }
    #pragma unroll
    for (int i = 0; i < 2; i++) {
        int r = br + i * 16;
        const __half* src = B + (size_t)(k0 + r) * N + bn + bc;
        uint32_t dst = (uint32_t)__cvta_generic_to_shared(bs + r * (GBN + SPAD) + bc);
        CP_ASYNC16(dst, src);
    }
}

__device__ __forceinline__ float sigmoidf_(float x) { return 1.f / (1.f + expf(-x)); }

// EPI 0: outF = acc + bias[col]
// EPI 1: outH = half(relu(acc + aux[row*H+col]))           (msg -> acat h_new)
// EPI 2: outH[row*ldOut + colOff + col] = half2(v0,v1)     (gin/ghn -> Gn blocked)
// EPI 3: fused GRU (r,z in acc pair; gin,ghn in auxH blocked; hprev in aux) -> outF[row*H + j]
template<int EPI>
__global__ __launch_bounds__(256, 2) void hgemm_kernel(
    const __half* __restrict__ A, const __half* __restrict__ B,
    const float* __restrict__ bias, const float* __restrict__ bias2,
    float* __restrict__ outF, __half* __restrict__ outH,
    const float* __restrict__ aux, const __half* __restrict__ auxH,
    int M, int N, int K, int ldA, int ldOut, int colOff)
{
    extern __shared__ __align__(16) __half sm[];
    __half* smA = sm;
    __half* smB = sm + STAGES * A_STG;

    const int tid  = threadIdx.x;
    const int lane = tid & 31;
    const int warp = tid >> 5;
    const int wm   = warp & 3;
    const int wn   = warp >> 2;
    const int bm   = blockIdx.y * GBM;
    const int bn   = blockIdx.x * GBN;

    float acc[2][8][4];
    #pragma unroll
    for (int i = 0; i < 2; i++)
        #pragma unroll
        for (int j = 0; j < 8; j++)
            #pragma unroll
            for (int k = 0; k < 4; k++) acc[i][j][k] = 0.f;

    const int ar = tid >> 2;
    const int ac = (tid & 3) << 3;
    const int br = tid >> 4;
    const int bc = (tid & 15) << 3;
    const int KT = K / GBK;

    #pragma unroll
    for (int p = 0; p < STAGES - 1; p++) {
        if (p < KT) {
            hgemm_load_tile(A, B, smA, smB, p, p, bm, bn, M, N, K, ldA, ar, ac, br, bc);
        }
        CP_COMMIT();
    }

    for (int kt = 0; kt < KT; kt++) {
        CP_WAIT2();
        __syncthreads();
        const int s = kt % STAGES;
        if (kt + STAGES - 1 < KT) {
            hgemm_load_tile(A, B, smA, smB, kt + STAGES - 1, (kt + STAGES - 1) % STAGES,
                            bm, bn, M, N, K, ldA, ar, ac, br, bc);
        }
        CP_COMMIT();

        __half* as = smA + s * A_STG;
        __half* bs = smB + s * B_STG;
        #pragma unroll
        for (int ks = 0; ks < 2; ks++) {
            const int k0 = ks * 16;
            uint32_t af[2][4];
            #pragma unroll
            for (int mi = 0; mi < 2; mi++) {
                int row = wm * 32 + mi * 16 + (lane & 15);
                int col = k0 + ((lane >> 4) << 3);
                uint32_t ad = (uint32_t)__cvta_generic_to_shared(as + row * (GBK + SPAD) + col);
                ldsm_x4(af[mi][0], af[mi][1], af[mi][2], af[mi][3], ad);
            }
            uint32_t bf[8][2];
            #pragma unroll
            for (int nq = 0; nq < 4; nq++) {
                int row = k0 + (lane & 15);
                int col = wn * 64 + nq * 16 + ((lane >> 4) << 3);
                uint32_t bd = (uint32_t)__cvta_generic_to_shared(bs + row * (GBN + SPAD) + col);
                ldsm_x4t(bf[nq*2][0], bf[nq*2][1], bf[nq*2+1][0], bf[nq*2+1][1], bd);
            }
            #pragma unroll
            for (int mi = 0; mi < 2; mi++)
                #pragma unroll
                for (int nj = 0; nj < 8; nj++)
                    mma_16816(acc[mi][nj], af[mi], bf[nj]);
        }
        __syncthreads();
    }

    const int r0 = bm + wm * 32 + (lane >> 2);
    const int c0 = bn + wn * 64 + ((lane & 3) << 1);
    #pragma unroll
    for (int mi = 0; mi < 2; mi++) {
        #pragma unroll
        for (int nj = 0; nj < 8; nj++) {
            const int col = c0 + nj * 8;
            #pragma unroll
            for (int hh = 0; hh < 2; hh++) {
                const int row = r0 + mi * 16 + hh * 8;
                if (row >= M) continue;
                float v0 = acc[mi][nj][hh * 2 + 0];
                float v1 = acc[mi][nj][hh * 2 + 1];
                if (EPI == 0) {
                    outF[(size_t)row * ldOut + col]     = v0 + bias[col];
                    outF[(size_t)row * ldOut + col + 1] = v1 + bias[col + 1];
                } else if (EPI == 1) {
                    v0 = fmaxf(v0 + aux[(size_t)row * H + col],     0.f);
                    v1 = fmaxf(v1 + aux[(size_t)row * H + col + 1], 0.f);
                    outH[(size_t)row * ldOut + col]     = __float2half(v0);
                    outH[(size_t)row * ldOut + col + 1] = __float2half(v1);
                } else if (EPI == 2) {
                    __half2 hv = __floats2half2_rn(v0, v1);
                    *(__half2*)(outH + (size_t)row * ldOut + colOff + col) = hv;
                } else {
                    float r = sigmoidf_(v0 + bias[col]);
                    float z = sigmoidf_(v1 + bias[col + 1]);
                    int j = col >> 1;
                    float gin = __half2float(auxH[(size_t)row * ldOut + j])       + bias2[j];
                    float ghn = __half2float(auxH[(size_t)row * ldOut + 256 + j]) + bias2[256 + j];
                    float n = tanhf(gin + r * ghn);
                    float hp = aux[(size_t)row * H + j];
                    outF[(size_t)row * H + j] = (1.f - z) * n + z * hp;
                }
            }
        }
    }
}

// ---------------- warp-per-row helpers ----------------

__device__ __forceinline__ void warp_ln_8(float* v, int lane,
                                          const float* __restrict__ g,
                                          const float* __restrict__ be,
                                          float* y)
{
    float sum = 0.f, sq = 0.f;
    #pragma unroll
    for (int i = 0; i < 8; i++) { sum += v[i]; sq += v[i] * v[i]; }
    #pragma unroll
    for (int o = 16; o > 0; o >>= 1) {
        sum += __shfl_xor_sync(0xffffffffu, sum, o);
        sq  += __shfl_xor_sync(0xffffffffu, sq,  o);
    }
    float mu = sum * (1.f / H);
    float var = sq * (1.f / H) - mu * mu;
    float rs = rsqrtf(var + EPS);
    const float4* g4  = (const float4*)(g  + lane * 8);
    const float4* be4 = (const float4*)(be + lane * 8);
    float4 ga = g4[0], gb = g4[1], ba = be4[0], bb = be4[1];
    y[0] = (v[0] - mu) * rs * ga.x + ba.x;
    y[1] = (v[1] - mu) * rs * ga.y + ba.y;
    y[2] = (v[2] - mu) * rs * ga.z + ba.z;
    y[3] = (v[3] - mu) * rs * ga.w + ba.w;
    y[4] = (v[4] - mu) * rs * gb.x + bb.x;
    y[5] = (v[5] - mu) * rs * gb.y + bb.y;
    y[6] = (v[6] - mu) * rs * gb.z + bb.z;
    y[7] = (v[7] - mu) * rs * gb.w + bb.w;
}

__device__ __forceinline__ void store_half8(__half* p, const float* y) {
    __half2 h0 = __floats2half2_rn(y[0], y[1]);
    __half2 h1 = __floats2half2_rn(y[2], y[3]);
    __half2 h2 = __floats2half2_rn(y[4], y[5]);
    __half2 h3 = __floats2half2_rn(y[6], y[7]);
    uint4 u;
    u.x = *(uint32_t*)&h0; u.y = *(uint32_t*)&h1;
    u.z = *(uint32_t*)&h2; u.w = *(uint32_t*)&h3;
    *(uint4*)p = u;
}

// h_e init: LN(relu(h_all[src] + edge_attr@W_bond + b_bond)) + acat copy + vector scatter
__global__ void edge_init_kernel(const int* __restrict__ ei, const float* __restrict__ h_all,
                                 const float* __restrict__ eattr, const float* __restrict__ Wb,
                                 const float* __restrict__ bb_,
                                 const float* __restrict__ g, const float* __restrict__ be,
                                 float* __restrict__ h_e, __half* __restrict__ acat,
                                 float* __restrict__ m_in, int E)
{
    int d = blockIdx.x * 8 + (threadIdx.x >> 5);
    if (d >= 2 * E) return;
    int lane = threadIdx.x & 31;
    int src = ei[d];
    int e = (d < E) ? d : d - E;

    // bond projection for this row (K=14, L1-resident weights)
    float ew[14];
    const float* er = eattr + (size_t)e * BOND_IN;
    #pragma unroll
    for (int k = 0; k < BOND_IN; k++) ew[k] = er[k];
    float ev[8];
    {
        const float4* b4 = (const float4*)(bb_ + lane * 8);
        float4 e0 = b4[0], e1 = b4[1];
        ev[0]=e0.x; ev[1]=e0.y; ev[2]=e0.z; ev[3]=e0.w;
        ev[4]=e1.x; ev[5]=e1.y; ev[6]=e1.z; ev[7]=e1.w;
    }
    #pragma unroll
    for (int k = 0; k < BOND_IN; k++) {
        const float4* w4 = (const float4*)(Wb + k * H + lane * 8);
        float4 w0 = w4[0], w1 = w4[1];
        ev[0] += ew[k]*w0.x; ev[1] += ew[k]*w0.y; ev[2] += ew[k]*w0.z; ev[3] += ew[k]*w0.w;
        ev[4] += ew[k]*w1.x; ev[5] += ew[k]*w1.y; ev[6] += ew[k]*w1.z; ev[7] += ew[k]*w1.w;
    }

    const float4* ha = (const float4*)(h_all + (size_t)src * H + lane * 8);
    float4 a0 = ha[0], a1 = ha[1];
    float v[8] = {
        fmaxf(a0.x + ev[0], 0.f), fmaxf(a0.y + ev[1], 0.f),
        fmaxf(a0.z + ev[2], 0.f), fmaxf(a0.w + ev[3], 0.f),
        fmaxf(a1.x + ev[4], 0.f), fmaxf(a1.y + ev[5], 0.f),
        fmaxf(a1.z + ev[6], 0.f), fmaxf(a1.w + ev[7], 0.f) };
    float y[8];
    warp_ln_8(v, lane, g, be, y);
    float4* he4 = (float4*)(h_e + (size_t)d * H + lane * 8);
    he4[0] = make_float4(y[0], y[1], y[2], y[3]);
    he4[1] = make_float4(y[4], y[5], y[6], y[7]);
    store_half8(acat + (size_t)d * ACAT_W + H + lane * 8, y);
    int dst = (d < E) ? ei[E + d] : ei[d - E];
    float* mb = m_in + (size_t)dst * H + lane * 8;
    red_add_v4(mb,     y[0], y[1], y[2], y[3]);
    red_add_v4(mb + 4, y[4], y[5], y[6], y[7]);
}

// LN of GRU output + optional acat copy + vector scatter
template<bool W16>
__global__ void ln_scatter_kernel(const float* __restrict__ x, const int* __restrict__ ei,
                                  const float* __restrict__ g, const float* __restrict__ be,
                                  float* __restrict__ outp, __half* __restrict__ acat,
                                  float* __restrict__ m_in, int E)
{
    int d = blockIdx.x * 8 + (threadIdx.x >> 5);
    if (d >= 2 * E) return;
    int lane = threadIdx.x & 31;
    const float4* xr = (const float4*)(x + (size_t)d * H + lane * 8);
    float4 x0 = xr[0], x1 = xr[1];
    float v[8] = {x0.x, x0.y, x0.z, x0.w, x1.x, x1.y, x1.z, x1.w};
    float y[8];
    warp_ln_8(v, lane, g, be, y);
    float4* o4 = (float4*)(outp + (size_t)d * H + lane * 8);
    o4[0] = make_float4(y[0], y[1], y[2], y[3]);
    o4[1] = make_float4(y[4], y[5], y[6], y[7]);
    if (W16) store_half8(acat + (size_t)d * ACAT_W + H + lane * 8, y);
    int dst = (d < E) ? ei[E + d] : ei[d - E];
    float* mb = m_in + (size_t)dst * H + lane * 8;
    red_add_v4(mb,     y[0], y[1], y[2], y[3]);
    red_add_v4(mb + 4, y[4], y[5], y[6], y[7]);
}

// mex16[d] = half(m_in[src[d]] - h_e[rev[d]])
__global__ void gather_kernel(const float* __restrict__ m_in, const float* __restrict__ h_e,
                              const int* __restrict__ ei, __half* __restrict__ out16, int E)
{
    int d = blockIdx.x * 8 + (threadIdx.x >> 5);
    if (d >= 2 * E) return;
    int lane = threadIdx.x & 31;
    int src = ei[d];
    int rv  = (d < E) ? d + E : d - E;
    const float4* ma = (const float4*)(m_in + (size_t)src * H + lane * 8);
    const float4* hb = (const float4*)(h_e + (size_t)rv * H + lane * 8);
    float4 m0 = ma[0], m1 = ma[1], h0 = hb[0], h1 = hb[1];
    float y[8] = {m0.x - h0.x, m0.y - h0.y, m0.z - h0.z, m0.w - h0.w,
                  m1.x - h1.x, m1.y - h1.y, m1.z - h1.z, m1.w - h1.w};
    store_half8(out16 + (size_t)d * H + lane * 8, y);
}

// h_atom = LN(relu(x)) -> out; vector atomic into hgraph[batch[n]]
__global__ void relu_ln_graph_kernel(const float* __restrict__ x, const int* __restrict__ batch,
                                     const float* __restrict__ g, const float* __restrict__ be,
                                     float* __restrict__ out, float* __restrict__ hgraph, int N)
{
    int n = blockIdx.x * 8 + (threadIdx.x >> 5);
    if (n >= N) return;
    int lane = threadIdx.x & 31;
    const float4* xr = (const float4*)(x + (size_t)n * H + lane * 8);
    float4 x0 = xr[0], x1 = xr[1];
    float v[8] = {fmaxf(x0.x, 0.f), fmaxf(x0.y, 0.f), fmaxf(x0.z, 0.f), fmaxf(x0.w, 0.f),
                  fmaxf(x1.x, 0.f), fmaxf(x1.y, 0.f), fmaxf(x1.z, 0.f), fmaxf(x1.w, 0.f)};
    float y[8];
    warp_ln_8(v, lane, g, be, y);
    float4* o4 = (float4*)(out + (size_t)n * H + lane * 8);
    o4[0] = make_float4(y[0], y[1], y[2], y[3]);
    o4[1] = make_float4(y[4], y[5], y[6], y[7]);
    float* hb = hgraph + (size_t)batch[n] * H + lane * 8;
    red_add_v4(hb,     y[0], y[1], y[2], y[3]);
    red_add_v4(hb + 4, y[4], y[5], y[6], y[7]);
}

// ---------------- prep / misc ----------------
__global__ void build_a16_kernel(const int* __restrict__ xz, const float* __restrict__ xa,
                                 const float* __restrict__ emb,
                                 __half* __restrict__ a16, __half* __restrict__ aao, int N)
{
    size_t idx = (size_t)blockIdx.x * blockDim.x + threadIdx.x;
    size_t total = (size_t)N * AO_K;
    for (; idx < total; idx += (size_t)gridDim.x * blockDim.x) {
        int n = (int)(idx / AO_K);
        int c = (int)(idx % AO_K);
        if (c < AIN_K) {
            float v = (c < 32) ? emb[xz[n] * 32 + c]
                    : (c < 165) ? xa[(size_t)n * ATOM_IN + (c - 32)] : 0.f;
            __half h = __float2half(v);
            a16[(size_t)n * AIN_K + c] = h;
            if (c < 165) aao[(size_t)n * AO_K + c] = h;
        } else if (c >= 421) {
            aao[idx] = __float2half(0.f);
        }
    }
}

__global__ void build_wain16(const float* __restrict__ W, __half* __restrict__ O) {
    int idx = blockIdx.x * blockDim.x + threadIdx.x;
    if (idx >= AIN_K * H) return;
    int k = idx / H, c = idx % H;
    O[idx] = __float2half(k < 165 ? W[k * H + c] : 0.f);
}
__global__ void build_wmsg16(const float* __restrict__ W, __half* __restrict__ O) {
    int idx = blockIdx.x * blockDim.x + threadIdx.x;
    if (idx < H * H) O[idx] = __float2half(W[idx]);
}
__global__ void build_wao16(const float* __restrict__ W, __half* __restrict__ O) {
    int idx = blockIdx.x * blockDim.x + threadIdx.x;
    if (idx >= AO_K * H) return;
    int k = idx / H, c = idx % H;
    O[idx] = __float2half(k < 421 ? W[k * H + c] : 0.f);
}

__global__ void build_brz_kernel(const float* __restrict__ Wih, const float* __restrict__ Whh,
                                 const float* __restrict__ bih, const float* __restrict__ bhh,
                                 __half* __restrict__ Brz, float* __restrict__ rzb)
{
    int idx = blockIdx.x * blockDim.x + threadIdx.x;
    if (idx >= ACAT_W * RZ_N) return;
    int k = idx / RZ_N, c = idx % RZ_N;
    int j = c >> 1;
    int gateRow = (c & 1) ? (256 + j) : j;
    float v = (k < 256) ? Wih[gateRow * H + k] : Whh[gateRow * H + (k - 256)];
    Brz[idx] = __float2half(v);
    if (k == 0) rzb[c] = bih[gateRow] + bhh[gateRow];
}
__global__ void build_bgin_kernel(const float* __restrict__ Wih, const float* __restrict__ bih,
                                  __half* __restrict__ Bg, float* __restrict__ nb)
{
    int idx = blockIdx.x * blockDim.x + threadIdx.x;
    if (idx >= H * H) return;
    int k = idx / H, j = idx % H;
    Bg[idx] = __float2half(Wih[(512 + j) * H + k]);
    if (k == 0) nb[j] = bih[512 + j];
}
__global__ void build_bghn_kernel(const float* __restrict__ Whh, const float* __restrict__ bhh,
                                  __half* __restrict__ Bg, float* __restrict__ nb)
{
    int idx = blockIdx.x * blockDim.x + threadIdx.x;
    if (idx >= H * H) return;
    int k = idx / H, j = idx % H;
    Bg[idx] = __float2half(Whh[(512 + j) * H + k]);
    if (k == 0) nb[256 + j] = bhh[512 + j];
}

__global__ void zero_kernel(float4* __restrict__ p, size_t n4) {
    size_t i = (size_t)blockIdx.x * blockDim.x + threadIdx.x;
    for (; i < n4; i += (size_t)gridDim.x * blockDim.x)
        p[i] = make_float4(0.f, 0.f, 0.f, 0.f);
}

__global__ void convert_min_kernel(const float* __restrict__ m_in, __half* __restrict__ aao, int N)
{
    size_t idx = (size_t)blockIdx.x * blockDim.x + threadIdx.x;
    size_t total = (size_t)N * H;
    for (; idx < total; idx += (size_t)gridDim.x * blockDim.x) {
        int n = (int)(idx / H), c = (int)(idx % H);
        aao[(size_t)n * AO_K + 165 + c] = __float2half(m_in[idx]);
    }
}

__global__ void readout_kernel(const float* __restrict__ hgraph, const float* __restrict__ Wr,
                               const float* __restrict__ br, float* __restrict__ out)
{
    int gph = blockIdx.x, t = threadIdx.x;
    if (t < NUM_TASKS) {
        float s = br[t];
        const float* row = hgraph + gph * H;
        #pragma unroll 8
        for (int k = 0; k < H; k++) s += row[k] * Wr[k * NUM_TASKS + t];
        out[gph * NUM_TASKS + t] = s;
    }
}

// ---------------- host launcher ----------------
extern "C" void kernel_launch(void* const* d_in, const int* in_sizes, int n_in,
                              void* d_out, int out_size)
{
    const int*   x_z        = (const int*)  d_in[0];
    const float* x_atom     = (const float*)d_in[1];
    const int*   ei         = (const int*)  d_in[2];
    const float* edge_attr  = (const float*)d_in[3];
    const int*   batch      = (const int*)  d_in[4];
    const float* embed_z    = (const float*)d_in[5];
    const float* W_atom_in  = (const float*)d_in[6];
    const float* b_atom_in  = (const float*)d_in[7];
    const float* W_bond_in  = (const float*)d_in[8];
    const float* b_bond_in  = (const float*)d_in[9];
    const float* W_msg      = (const float*)d_in[10];
    const float* W_ih       = (const float*)d_in[11];
    const float* b_ih       = (const float*)d_in[12];
    const float* W_hh       = (const float*)d_in[13];
    const float* b_hh       = (const float*)d_in[14];
    const float* W_atom_out = (const float*)d_in[15];
    const float* b_atom_out = (const float*)d_in[16];
    const float* W_read     = (const float*)d_in[17];
    const float* b_read     = (const float*)d_in[18];
    const float* g_e        = (const float*)d_in[19];
    const float* be_e       = (const float*)d_in[20];
    const float* g_a        = (const float*)d_in[21];
    const float* be_a       = (const float*)d_in[22];

    const int N  = in_sizes[0];
    const int E  = in_sizes[2] / 2;
    const int E2 = 2 * E;

    float* out       = (float*)d_out;
    float* out_hatom = out + NUM_GRAPHS * NUM_TASKS;
    float* out_he    = out_hatom + (size_t)N * H;

    float  *h_all, *h_e, *hpre, *m_in, *hgraph, *rzbias, *nbias;
    __half *a16, *aao, *acat, *mex16, *Gn, *wain, *wmsg, *wao, *brz, *bgin, *bghn;
    cudaGetSymbolAddress((void**)&h_all,  g_h_all);
    cudaGetSymbolAddress((void**)&h_e,    g_h_e);
    cudaGetSymbolAddress((void**)&hpre,   g_hpre);
    cudaGetSymbolAddress((void**)&m_in,   g_m_in);
    cudaGetSymbolAddress((void**)&hgraph, g_hgraph);
    cudaGetSymbolAddress((void**)&rzbias, g_rzbias);
    cudaGetSymbolAddress((void**)&nbias,  g_nbias);
    cudaGetSymbolAddress((void**)&a16,    g_a16);
    cudaGetSymbolAddress((void**)&aao,    g_aao);
    cudaGetSymbolAddress((void**)&acat,   g_acat);
    cudaGetSymbolAddress((void**)&mex16,  g_mex16);
    cudaGetSymbolAddress((void**)&Gn,     g_Gn);
    cudaGetSymbolAddress((void**)&wain,   g_wain);
    cudaGetSymbolAddress((void**)&wmsg,   g_wmsg);
    cudaGetSymbolAddress((void**)&wao,    g_wao);
    cudaGetSymbolAddress((void**)&brz,    g_brz);
    cudaGetSymbolAddress((void**)&bgin,   g_bgin);
    cudaGetSymbolAddress((void**)&bghn,   g_bghn);

    cudaFuncSetAttribute(hgemm_kernel<0>, cudaFuncAttributeMaxDynamicSharedMemorySize, GEMM_SMEM);
    cudaFuncSetAttribute(hgemm_kernel<1>, cudaFuncAttributeMaxDynamicSharedMemorySize, GEMM_SMEM);
    cudaFuncSetAttribute(hgemm_kernel<2>, cudaFuncAttributeMaxDynamicSharedMemorySize, GEMM_SMEM);
    cudaFuncSetAttribute(hgemm_kernel<3>, cudaFuncAttributeMaxDynamicSharedMemorySize, GEMM_SMEM);

    const size_t minN4 = (size_t)N * H / 4;

    // prep
    zero_kernel<<<1024, 256>>>((float4*)m_in, minN4);
    build_a16_kernel<<<4096, 256>>>(x_z, x_atom, embed_z, a16, aao, N);
    build_wain16<<<cdiv(AIN_K * H, 256), 256>>>(W_atom_in, wain);
    build_wmsg16<<<cdiv(H * H, 256), 256>>>(W_msg, wmsg);
    build_wao16<<<cdiv(AO_K * H, 256), 256>>>(W_atom_out, wao);
    build_brz_kernel<<<cdiv(ACAT_W * RZ_N, 256), 256>>>(W_ih, W_hh, b_ih, b_hh, brz, rzbias);
    build_bgin_kernel<<<cdiv(H * H, 256), 256>>>(W_ih, b_ih, bgin, nbias);
    build_bghn_kernel<<<cdiv(H * H, 256), 256>>>(W_hh, b_hh, bghn, nbias);

    // h_all = a_all @ W_atom_in + b
    hgemm_kernel<0><<<dim3(cdiv(H, GBN), cdiv(N, GBM)), 256, GEMM_SMEM>>>(
        a16, wain, b_atom_in, nullptr, h_all, nullptr, nullptr, nullptr,
        N, H, AIN_K, AIN_K, H, 0);
    // h_e init (bond fused) + acat copy + scatter
    edge_init_kernel<<<cdiv(E2, 8), 256>>>(ei, h_all, edge_attr, W_bond_in, b_bond_in,
                                           g_e, be_e, h_e, acat, m_in, E);

    for (int depth = 0; depth < DEPTH; depth++) {
        gather_kernel<<<cdiv(E2, 8), 256>>>(m_in, h_e, ei, mex16, E);
        // h_new = relu(h_e + m_excl @ W_msg) -> acat cols 0..255
        hgemm_kernel<1><<<dim3(cdiv(H, GBN), cdiv(E2, GBM)), 256, GEMM_SMEM>>>(
            mex16, wmsg, nullptr, nullptr, nullptr, acat, h_e, nullptr,
            E2, H, H, H, ACAT_W, 0);
        // gin / ghn -> Gn blocked [gin | ghn]
        hgemm_kernel<2><<<dim3(cdiv(H, GBN), cdiv(E2, GBM)), 256, GEMM_SMEM>>>(
            acat, bgin, nullptr, nullptr, nullptr, Gn, nullptr, nullptr,
            E2, H, H, ACAT_W, RZ_N, 0);
        hgemm_kernel<2><<<dim3(cdiv(H, GBN), cdiv(E2, GBM)), 256, GEMM_SMEM>>>(
            acat + H, bghn, nullptr, nullptr, nullptr, Gn, nullptr, nullptr,
            E2, H, H, ACAT_W, RZ_N, 256);
        zero_kernel<<<1024, 256>>>((float4*)m_in, minN4);
        // rz GEMM + fused GRU -> hpre
        hgemm_kernel<3><<<dim3(cdiv(RZ_N, GBN), cdiv(E2, GBM)), 256, GEMM_SMEM>>>(
            acat, brz, rzbias, nbias, hpre, nullptr, h_e, Gn,
            E2, RZ_N, ACAT_W, ACAT_W, RZ_N, 0);
        // LN + scatter (+acat copy except last depth)
        float* dst = (depth == DEPTH - 1) ? out_he : h_e;
        if (depth < DEPTH - 1)
            ln_scatter_kernel<true><<<cdiv(E2, 8), 256>>>(hpre, ei, g_e, be_e, dst, acat, m_in, E);
        else
            ln_scatter_kernel<false><<<cdiv(E2, 8), 256>>>(hpre, ei, g_e, be_e, dst, acat, m_in, E);
    }

    // m_to_atom accumulated by last ln_scatter
    convert_min_kernel<<<2048, 256>>>(m_in, aao, N);

    // h_atom = LN(relu([a_all | m_to_atom] @ W_atom_out + b))
    hgemm_kernel<0><<<dim3(cdiv(H, GBN), cdiv(N, GBM)), 256, GEMM_SMEM>>>(
        aao, wao, b_atom_out, nullptr, h_all, nullptr, nullptr, nullptr,
        N, H, AO_K, AO_K, H, 0);
    zero_kernel<<<64, 256>>>((float4*)hgraph, (size_t)NUM_GRAPHS * H / 4);
    relu_ln_graph_kernel<<<cdiv(N, 8), 256>>>(h_all, batch, g_a, be_a, out_hatom, hgraph, N);
    readout_kernel<<<NUM_GRAPHS, 32>>>(hgraph, W_read, b_read, out);
}

// round 12
// speedup vs baseline: 4.2594x; 1.1070x over previous
#include <cuda_runtime.h>
#include <cuda_fp16.h>
#include <stdint.h>
#include <cstdint>
#include <math.h>

// ---------------- problem constants ----------------
#define MAX_N 50000
#define MAX_E 200000
#define H 256
#define ATOM_IN 133
#define BOND_IN 14
#define NUM_TASKS 12
#define NUM_GRAPHS 256
#define DEPTH 3
#define EPS 1e-5f

#define AIN_K 192
#define AO_K  448
#define ACAT_W 512
#define RZ_N  512

// ---------------- scratch ----------------
__device__ float  g_h_all[(size_t)MAX_N * H];
__device__ float  g_hpre [(size_t)(2*MAX_E) * H];
__device__ float  g_m_in [(size_t)MAX_N * H];
__device__ float  g_hgraph[NUM_GRAPHS * H];
__device__ float  g_rzbias[RZ_N];
__device__ float  g_nbias [RZ_N];
__device__ __half g_a16  [(size_t)MAX_N * AIN_K];
__device__ __half g_aao  [(size_t)MAX_N * AO_K];
__device__ __half g_acat [(size_t)(2*MAX_E) * ACAT_W];   // [h_new | h_e] fp16
__device__ __half g_Gn   [(size_t)(2*MAX_E) * RZ_N];     // [gin(256) | ghn(256)] blocked
__device__ __half g_wain [AIN_K * H];
__device__ __half g_wmsg [H * H];
__device__ __half g_wao  [AO_K * H];
__device__ __half g_brz  [ACAT_W * RZ_N];
__device__ __half g_bgin [H * H];
__device__ __half g_bghn [H * H];

static inline int cdiv(int a, int b) { return (a + b - 1) / b; }

#define CP_ASYNC16(dst, src) asm volatile("cp.async.cg.shared.global [%0], [%1], 16;\n" :: "r"(dst), "l"(src))
#define CP_COMMIT()          asm volatile("cp.async.commit_group;\n")
#define CP_WAIT2()           asm volatile("cp.async.wait_group 2;\n")

__device__ __forceinline__ void red_add_v4(float* p, float a, float b, float c, float d) {
    asm volatile("red.global.v4.f32.add [%0], {%1,%2,%3,%4};"
                 :: "l"(p), "f"(a), "f"(b), "f"(c), "f"(d) : "memory");
}

// ---------------- mma.sync HGEMM core pieces ----------------
#define GBM 128
#define GBN 128
#define GBK 32
#define SPAD 8
#define STAGES 4
#define A_STG (GBM * (GBK + SPAD))
#define B_STG (GBK * (GBN + SPAD))
#define GEMM_SMEM (STAGES * (A_STG + B_STG) * 2)              // 75776
#define MSG_SMEM  ((2 * A_STG + STAGES * B_STG) * 2)          // 55296

__device__ __forceinline__ void ldsm_x4(uint32_t& r0, uint32_t& r1, uint32_t& r2, uint32_t& r3, uint32_t addr) {
    asm volatile("ldmatrix.sync.aligned.m8n8.x4.shared.b16 {%0,%1,%2,%3}, [%4];\n"
                 : "=r"(r0), "=r"(r1), "=r"(r2), "=r"(r3) : "r"(addr));
}
__device__ __forceinline__ void ldsm_x4t(uint32_t& r0, uint32_t& r1, uint32_t& r2, uint32_t& r3, uint32_t addr) {
    asm volatile("ldmatrix.sync.aligned.m8n8.x4.trans.shared.b16 {%0,%1,%2,%3}, [%4];\n"
                 : "=r"(r0), "=r"(r1), "=r"(r2), "=r"(r3) : "r"(addr));
}
__device__ __forceinline__ void mma_16816(float* d, const uint32_t* a, const uint32_t* b) {
    asm volatile("mma.sync.aligned.m16n8k16.row.col.f32.f16.f16.f32 "
                 "{%0,%1,%2,%3}, {%4,%5,%6,%7}, {%8,%9}, {%0,%1,%2,%3};\n"
                 : "+f"(d[0]), "+f"(d[1]), "+f"(d[2]), "+f"(d[3])
                 : "r"(a[0]), "r"(a[1]), "r"(a[2]), "r"(a[3]), "r"(b[0]), "r"(b[1]));
}

// compute one 32-K tile from smem stages (shared by both GEMM kernels)
__device__ __forceinline__ void tile_mma(const __half* as, const __half* bs,
                                         int lane, int wm, int wn, float acc[2][8][4])
{
    #pragma unroll
    for (int ks = 0; ks < 2; ks++) {
        const int k0 = ks * 16;
        uint32_t af[2][4];
        #pragma unroll
        for (int mi = 0; mi < 2; mi++) {
            int row = wm * 32 + mi * 16 + (lane & 15);
            int col = k0 + ((lane >> 4) << 3);
            uint32_t ad = (uint32_t)__cvta_generic_to_shared(as + row * (GBK + SPAD) + col);
            ldsm_x4(af[mi][0], af[mi][1], af[mi][2], af[mi][3], ad);
        }
        uint32_t bf[8][2];
        #pragma unroll
        for (int nq = 0; nq < 4; nq++) {
            int row = k0 + (lane & 15);
            int col = wn * 64 + nq * 16 + ((lane >> 4) << 3);
            uint32_t bd = (uint32_t)__cvta_generic_to_shared(bs + row * (GBN + SPAD) + col);
            ldsm_x4t(bf[nq*2][0], bf[nq*2][1], bf[nq*2+1][0], bf[nq*2+1][1], bd);
        }
        #pragma unroll
        for (int mi = 0; mi < 2; mi++)
            #pragma unroll
            for (int nj = 0; nj < 8; nj++)
                mma_16816(acc[mi][nj], af[mi], bf[nj]);
    }
}

__device__ __forceinline__ float sigmoidf_(float x) { return 1.f / (1.f + expf(-x)); }

// ---------------- generic HGEMM (EPI 0/2/3) ----------------
// EPI 0: outF = acc + bias[col]
// EPI 2: outH[row*ldOut + colOff + col] = half2(v0,v1)   (gin/ghn -> Gn blocked)
// EPI 3: fused GRU: r,z = acc pair; gin,ghn from auxH (Gn); hp from auxH2 (acat fp16) -> outF[row*H+j]
template<int EPI>
__global__ __launch_bounds__(256, 2) void hgemm_kernel(
    const __half* __restrict__ A, const __half* __restrict__ B,
    const float* __restrict__ bias, const float* __restrict__ bias2,
    float* __restrict__ outF, __half* __restrict__ outH,
    const __half* __restrict__ auxH, const __half* __restrict__ auxH2,
    int M, int N, int K, int ldA, int ldOut, int colOff)
{
    extern __shared__ __align__(16) __half sm[];
    __half* smA = sm;
    __half* smB = sm + STAGES * A_STG;

    const int tid  = threadIdx.x;
    const int lane = tid & 31;
    const int warp = tid >> 5;
    const int wm   = warp & 3;
    const int wn   = warp >> 2;
    const int bm   = blockIdx.y * GBM;
    const int bn   = blockIdx.x * GBN;

    float acc[2][8][4];
    #pragma unroll
    for (int i = 0; i < 2; i++)
        #pragma unroll
        for (int j = 0; j < 8; j++)
            #pragma unroll
            for (int k = 0; k < 4; k++) acc[i][j][k] = 0.f;

    const int ar = tid >> 2;
    const int ac = (tid & 3) << 3;
    const int br = tid >> 4;
    const int bc = (tid & 15) << 3;
    const int KT = K / GBK;

    auto load_tile = [&](int kt, int s) {
        const int k0 = kt * GBK;
        __half* as = smA + s * A_STG;
        __half* bs = smB + s * B_STG;
        #pragma unroll
        for (int i = 0; i < 2; i++) {
            int r  = ar + i * 64;
            int gr = bm + r; if (gr >= M) gr = M - 1;
            const __half* src = A + (size_t)gr * ldA + k0 + ac;
            uint32_t dst = (uint32_t)__cvta_generic_to_shared(as + r * (GBK + SPAD) + ac);
            CP_ASYNC16(dst, src);
        }
        #pragma unroll
        for (int i = 0; i < 2; i++) {
            int r = br + i * 16;
            const __half* src = B + (size_t)(k0 + r) * N + bn + bc;
            uint32_t dst = (uint32_t)__cvta_generic_to_shared(bs + r * (GBN + SPAD) + bc);
            CP_ASYNC16(dst, src);
        }
    };

    #pragma unroll
    for (int p = 0; p < STAGES - 1; p++) {
        if (p < KT) load_tile(p, p);
        CP_COMMIT();
    }

    for (int kt = 0; kt < KT; kt++) {
        CP_WAIT2();
        __syncthreads();
        const int s = kt % STAGES;
        if (kt + STAGES - 1 < KT) load_tile(kt + STAGES - 1, (kt + STAGES - 1) % STAGES);
        CP_COMMIT();
        tile_mma(smA + s * A_STG, smB + s * B_STG, lane, wm, wn, acc);
        __syncthreads();
    }

    const int r0 = bm + wm * 32 + (lane >> 2);
    const int c0 = bn + wn * 64 + ((lane & 3) << 1);
    #pragma unroll
    for (int mi = 0; mi < 2; mi++) {
        #pragma unroll
        for (int nj = 0; nj < 8; nj++) {
            const int col = c0 + nj * 8;
            #pragma unroll
            for (int hh = 0; hh < 2; hh++) {
                const int row = r0 + mi * 16 + hh * 8;
                if (row >= M) continue;
                float v0 = acc[mi][nj][hh * 2 + 0];
                float v1 = acc[mi][nj][hh * 2 + 1];
                if (EPI == 0) {
                    outF[(size_t)row * ldOut + col]     = v0 + bias[col];
                    outF[(size_t)row * ldOut + col + 1] = v1 + bias[col + 1];
                } else if (EPI == 2) {
                    __half2 hv = __floats2half2_rn(v0, v1);
                    *(__half2*)(outH + (size_t)row * ldOut + colOff + col) = hv;
                } else {
                    float r = sigmoidf_(v0 + bias[col]);
                    float z = sigmoidf_(v1 + bias[col + 1]);
                    int j = col >> 1;
                    float gin = __half2float(auxH[(size_t)row * ldOut + j])       + bias2[j];
                    float ghn = __half2float(auxH[(size_t)row * ldOut + 256 + j]) + bias2[256 + j];
                    float n = tanhf(gin + r * ghn);
                    float hp = __half2float(auxH2[(size_t)row * ACAT_W + H + j]);
                    outF[(size_t)row * H + j] = (1.f - z) * n + z * hp;
                }
            }
        }
    }
}

// ---------------- fused gather + msg GEMM ----------------
// A[d][k] = m_in[src[d]][k] - h_e16[rev[d]][k]   (built in-kernel)
// C = A @ W_msg ; epilogue: acat[row][col] = half(relu(C + h_e16[row][col]))
__global__ __launch_bounds__(256, 2) void msg_gemm_kernel(
    const float* __restrict__ m_in, const __half* __restrict__ Bw,
    const int* __restrict__ ei, __half* __restrict__ acat, int E)
{
    extern __shared__ __align__(16) __half sm[];
    __half* smA = sm;                    // 2 stages
    __half* smB = sm + 2 * A_STG;        // STAGES stages
    const int E2 = 2 * E;

    const int tid  = threadIdx.x;
    const int lane = tid & 31;
    const int warp = tid >> 5;
    const int wm   = warp & 3;
    const int wn   = warp >> 2;
    const int bm   = blockIdx.y * GBM;
    const int bn   = blockIdx.x * GBN;

    // A producer: thread covers row pr, 16 cols at pc within each 32-col k-tile
    const int pr = tid >> 1;
    const int pc = (tid & 1) * 16;
    int dd = bm + pr; if (dd >= E2) dd = E2 - 1;
    const int src = ei[dd];
    const int rv  = (dd < E) ? dd + E : dd - E;
    const float*  mrow  = m_in + (size_t)src * H;
    const __half* herow = acat + (size_t)rv * ACAT_W + H;

    const int br = tid >> 4;
    const int bc = (tid & 15) << 3;
    const int KT = H / GBK;   // 8

    float4 am[4]; uint4 ah[2];
    auto loadA = [&](int kt) {
        const int c0 = kt * GBK + pc;
        am[0] = *(const float4*)(mrow + c0);
        am[1] = *(const float4*)(mrow + c0 + 4);
        am[2] = *(const float4*)(mrow + c0 + 8);
        am[3] = *(const float4*)(mrow + c0 + 12);
        ah[0] = *(const uint4*)(herow + c0);
        ah[1] = *(const uint4*)(herow + c0 + 8);
    };
    auto stsA = [&](int s) {
        __half hx[16];
        const __half* hp = (const __half*)ah;
        #pragma unroll
        for (int i = 0; i < 4; i++) {
            const float* mf = (const float*)&am[i];
            #pragma unroll
            for (int j = 0; j < 4; j++)
                hx[i*4 + j] = __float2half(mf[j] - __half2float(hp[i*4 + j]));
        }
        __half* dst = smA + s * A_STG + pr * (GBK + SPAD) + pc;
        *(uint4*)dst       = *(const uint4*)hx;
        *(uint4*)(dst + 8) = *(const uint4*)(hx + 8);
    };
    auto loadB = [&](int kt, int s) {
        const int k0 = kt * GBK;
        __half* bs = smB + s * B_STG;
        #pragma unroll
        for (int i = 0; i < 2; i++) {
            int r = br + i * 16;
            const __half* srcp = Bw + (size_t)(k0 + r) * H + bn + bc;
            uint32_t dst = (uint32_t)__cvta_generic_to_shared(bs + r * (GBN + SPAD) + bc);
            CP_ASYNC16(dst, srcp);
        }
    };

    float acc[2][8][4];
    #pragma unroll
    for (int i = 0; i < 2; i++)
        #pragma unroll
        for (int j = 0; j < 8; j++)
            #pragma unroll
            for (int k = 0; k < 4; k++) acc[i][j][k] = 0.f;

    loadA(0);
    #pragma unroll
    for (int p = 0; p < STAGES - 1; p++) {
        if (p < KT) loadB(p, p);
        CP_COMMIT();
    }

    for (int kt = 0; kt < KT; kt++) {
        stsA(kt & 1);
        if (kt + 1 < KT) loadA(kt + 1);
        CP_WAIT2();
        __syncthreads();
        if (kt + STAGES - 1 < KT) loadB(kt + STAGES - 1, (kt + STAGES - 1) % STAGES);
        CP_COMMIT();
        tile_mma(smA + (kt & 1) * A_STG, smB + (kt % STAGES) * B_STG, lane, wm, wn, acc);
        __syncthreads();
    }

    const int r0 = bm + wm * 32 + (lane >> 2);
    const int c0 = bn + wn * 64 + ((lane & 3) << 1);
    #pragma unroll
    for (int mi = 0; mi < 2; mi++) {
        #pragma unroll
        for (int nj = 0; nj < 8; nj++) {
            const int col = c0 + nj * 8;
            #pragma unroll
            for (int hh = 0; hh < 2; hh++) {
                const int row = r0 + mi * 16 + hh * 8;
                if (row >= E2) continue;
                __half2 he2 = *(const __half2*)(acat + (size_t)row * ACAT_W + H + col);
                float v0 = fmaxf(acc[mi][nj][hh*2+0] + __low2float(he2),  0.f);
                float v1 = fmaxf(acc[mi][nj][hh*2+1] + __high2float(he2), 0.f);
                *(__half2*)(acat + (size_t)row * ACAT_W + col) = __floats2half2_rn(v0, v1);
            }
        }
    }
}

// ---------------- warp-per-row helpers ----------------

__device__ __forceinline__ void warp_ln_8(float* v, int lane,
                                          const float* __restrict__ g,
                                          const float* __restrict__ be,
                                          float* y)
{
    float sum = 0.f, sq = 0.f;
    #pragma unroll
    for (int i = 0; i < 8; i++) { sum += v[i]; sq += v[i] * v[i]; }
    #pragma unroll
    for (int o = 16; o > 0; o >>= 1) {
        sum += __shfl_xor_sync(0xffffffffu, sum, o);
        sq  += __shfl_xor_sync(0xffffffffu, sq,  o);
    }
    float mu = sum * (1.f / H);
    float var = sq * (1.f / H) - mu * mu;
    float rs = rsqrtf(var + EPS);
    const float4* g4  = (const float4*)(g  + lane * 8);
    const float4* be4 = (const float4*)(be + lane * 8);
    float4 ga = g4[0], gb = g4[1], ba = be4[0], bb = be4[1];
    y[0] = (v[0] - mu) * rs * ga.x + ba.x;
    y[1] = (v[1] - mu) * rs * ga.y + ba.y;
    y[2] = (v[2] - mu) * rs * ga.z + ba.z;
    y[3] = (v[3] - mu) * rs * ga.w + ba.w;
    y[4] = (v[4] - mu) * rs * gb.x + bb.x;
    y[5] = (v[5] - mu) * rs * gb.y + bb.y;
    y[6] = (v[6] - mu) * rs * gb.z + bb.z;
    y[7] = (v[7] - mu) * rs * gb.w + bb.w;
}

__device__ __forceinline__ void store_half8(__half* p, const float* y) {
    __half2 h0 = __floats2half2_rn(y[0], y[1]);
    __half2 h1 = __floats2half2_rn(y[2], y[3]);
    __half2 h2 = __floats2half2_rn(y[4], y[5]);
    __half2 h3 = __floats2half2_rn(y[6], y[7]);
    uint4 u;
    u.x = *(uint32_t*)&h0; u.y = *(uint32_t*)&h1;
    u.z = *(uint32_t*)&h2; u.w = *(uint32_t*)&h3;
    *(uint4*)p = u;
}

// h_e init: LN(relu(h_all[src] + edge_attr@W_bond + b)) -> acat fp16 + scatter
__global__ void edge_init_kernel(const int* __restrict__ ei, const float* __restrict__ h_all,
                                 const float* __restrict__ eattr, const float* __restrict__ Wb,
                                 const float* __restrict__ bb_,
                                 const float* __restrict__ g, const float* __restrict__ be,
                                 __half* __restrict__ acat, float* __restrict__ m_in, int E)
{
    int d = blockIdx.x * 8 + (threadIdx.x >> 5);
    if (d >= 2 * E) return;
    int lane = threadIdx.x & 31;
    int src = ei[d];
    int e = (d < E) ? d : d - E;

    float ew[14];
    const float* er = eattr + (size_t)e * BOND_IN;
    #pragma unroll
    for (int k = 0; k < BOND_IN; k++) ew[k] = er[k];
    float ev[8];
    {
        const float4* b4 = (const float4*)(bb_ + lane * 8);
        float4 e0 = b4[0], e1 = b4[1];
        ev[0]=e0.x; ev[1]=e0.y; ev[2]=e0.z; ev[3]=e0.w;
        ev[4]=e1.x; ev[5]=e1.y; ev[6]=e1.z; ev[7]=e1.w;
    }
    #pragma unroll
    for (int k = 0; k < BOND_IN; k++) {
        const float4* w4 = (const float4*)(Wb + k * H + lane * 8);
        float4 w0 = w4[0], w1 = w4[1];
        ev[0] += ew[k]*w0.x; ev[1] += ew[k]*w0.y; ev[2] += ew[k]*w0.z; ev[3] += ew[k]*w0.w;
        ev[4] += ew[k]*w1.x; ev[5] += ew[k]*w1.y; ev[6] += ew[k]*w1.z; ev[7] += ew[k]*w1.w;
    }

    const float4* ha = (const float4*)(h_all + (size_t)src * H + lane * 8);
    float4 a0 = ha[0], a1 = ha[1];
    float v[8] = {
        fmaxf(a0.x + ev[0], 0.f), fmaxf(a0.y + ev[1], 0.f),
        fmaxf(a0.z + ev[2], 0.f), fmaxf(a0.w + ev[3], 0.f),
        fmaxf(a1.x + ev[4], 0.f), fmaxf(a1.y + ev[5], 0.f),
        fmaxf(a1.z + ev[6], 0.f), fmaxf(a1.w + ev[7], 0.f) };
    float y[8];
    warp_ln_8(v, lane, g, be, y);
    store_half8(acat + (size_t)d * ACAT_W + H + lane * 8, y);
    int dst = (d < E) ? ei[E + d] : ei[d - E];
    float* mb = m_in + (size_t)dst * H + lane * 8;
    red_add_v4(mb,     y[0], y[1], y[2], y[3]);
    red_add_v4(mb + 4, y[4], y[5], y[6], y[7]);
}

// LN of GRU output + scatter; W16: write acat fp16 copy; !W16 (last depth): write fp32 out
template<bool W16>
__global__ void ln_scatter_kernel(const float* __restrict__ x, const int* __restrict__ ei,
                                  const float* __restrict__ g, const float* __restrict__ be,
                                  float* __restrict__ outp, __half* __restrict__ acat,
                                  float* __restrict__ m_in, int E)
{
    int d = blockIdx.x * 8 + (threadIdx.x >> 5);
    if (d >= 2 * E) return;
    int lane = threadIdx.x & 31;
    const float4* xr = (const float4*)(x + (size_t)d * H + lane * 8);
    float4 x0 = xr[0], x1 = xr[1];
    float v[8] = {x0.x, x0.y, x0.z, x0.w, x1.x, x1.y, x1.z, x1.w};
    float y[8];
    warp_ln_8(v, lane, g, be, y);
    if (W16) {
        store_half8(acat + (size_t)d * ACAT_W + H + lane * 8, y);
    } else {
        float4* o4 = (float4*)(outp + (size_t)d * H + lane * 8);
        o4[0] = make_float4(y[0], y[1], y[2], y[3]);
        o4[1] = make_float4(y[4], y[5], y[6], y[7]);
    }
    int dst = (d < E) ? ei[E + d] : ei[d - E];
    float* mb = m_in + (size_t)dst * H + lane * 8;
    red_add_v4(mb,     y[0], y[1], y[2], y[3]);
    red_add_v4(mb + 4, y[4], y[5], y[6], y[7]);
}

// h_atom = LN(relu(x)) -> out; vector atomic into hgraph[batch[n]]
__global__ void relu_ln_graph_kernel(const float* __restrict__ x, const int* __restrict__ batch,
                                     const float* __restrict__ g, const float* __restrict__ be,
                                     float* __restrict__ out, float* __restrict__ hgraph, int N)
{
    int n = blockIdx.x * 8 + (threadIdx.x >> 5);
    if (n >= N) return;
    int lane = threadIdx.x & 31;
    const float4* xr = (const float4*)(x + (size_t)n * H + lane * 8);
    float4 x0 = xr[0], x1 = xr[1];
    float v[8] = {fmaxf(x0.x, 0.f), fmaxf(x0.y, 0.f), fmaxf(x0.z, 0.f), fmaxf(x0.w, 0.f),
                  fmaxf(x1.x, 0.f), fmaxf(x1.y, 0.f), fmaxf(x1.z, 0.f), fmaxf(x1.w, 0.f)};
    float y[8];
    warp_ln_8(v, lane, g, be, y);
    float4* o4 = (float4*)(out + (size_t)n * H + lane * 8);
    o4[0] = make_float4(y[0], y[1], y[2], y[3]);
    o4[1] = make_float4(y[4], y[5], y[6], y[7]);
    float* hb = hgraph + (size_t)batch[n] * H + lane * 8;
    red_add_v4(hb,     y[0], y[1], y[2], y[3]);
    red_add_v4(hb + 4, y[4], y[5], y[6], y[7]);
}

// ---------------- prep / misc ----------------
__global__ void build_a16_kernel(const int* __restrict__ xz, const float* __restrict__ xa,
                                 const float* __restrict__ emb,
                                 __half* __restrict__ a16, __half* __restrict__ aao, int N)
{
    size_t idx = (size_t)blockIdx.x * blockDim.x + threadIdx.x;
    size_t total = (size_t)N * AO_K;
    for (; idx < total; idx += (size_t)gridDim.x * blockDim.x) {
        int n = (int)(idx / AO_K);
        int c = (int)(idx % AO_K);
        if (c < AIN_K) {
            float v = (c < 32) ? emb[xz[n] * 32 + c]
                    : (c < 165) ? xa[(size_t)n * ATOM_IN + (c - 32)] : 0.f;
            __half h = __float2half(v);
            a16[(size_t)n * AIN_K + c] = h;
            if (c < 165) aao[(size_t)n * AO_K + c] = h;
        } else if (c >= 421) {
            aao[idx] = __float2half(0.f);
        }
    }
}

__global__ void build_wain16(const float* __restrict__ W, __half* __restrict__ O) {
    int idx = blockIdx.x * blockDim.x + threadIdx.x;
    if (idx >= AIN_K * H) return;
    int k = idx / H, c = idx % H;
    O[idx] = __float2half(k < 165 ? W[k * H + c] : 0.f);
}
__global__ void build_wmsg16(const float* __restrict__ W, __half* __restrict__ O) {
    int idx = blockIdx.x * blockDim.x + threadIdx.x;
    if (idx < H * H) O[idx] = __float2half(W[idx]);
}
__global__ void build_wao16(const float* __restrict__ W, __half* __restrict__ O) {
    int idx = blockIdx.x * blockDim.x + threadIdx.x;
    if (idx >= AO_K * H) return;
    int k = idx / H, c = idx % H;
    O[idx] = __float2half(k < 421 ? W[k * H + c] : 0.f);
}

__global__ void build_brz_kernel(const float* __restrict__ Wih, const float* __restrict__ Whh,
                                 const float* __restrict__ bih, const float* __restrict__ bhh,
                                 __half* __restrict__ Brz, float* __restrict__ rzb)
{
    int idx = blockIdx.x * blockDim.x + threadIdx.x;
    if (idx >= ACAT_W * RZ_N) return;
    int k = idx / RZ_N, c = idx % RZ_N;
    int j = c >> 1;
    int gateRow = (c & 1) ? (256 + j) : j;
    float v = (k < 256) ? Wih[gateRow * H + k] : Whh[gateRow * H + (k - 256)];
    Brz[idx] = __float2half(v);
    if (k == 0) rzb[c] = bih[gateRow] + bhh[gateRow];
}
__global__ void build_bgin_kernel(const float* __restrict__ Wih, const float* __restrict__ bih,
                                  __half* __restrict__ Bg, float* __restrict__ nb)
{
    int idx = blockIdx.x * blockDim.x + threadIdx.x;
    if (idx >= H * H) return;
    int k = idx / H, j = idx % H;
    Bg[idx] = __float2half(Wih[(512 + j) * H + k]);
    if (k == 0) nb[j] = bih[512 + j];
}
__global__ void build_bghn_kernel(const float* __restrict__ Whh, const float* __restrict__ bhh,
                                  __half* __restrict__ Bg, float* __restrict__ nb)
{
    int idx = blockIdx.x * blockDim.x + threadIdx.x;
    if (idx >= H * H) return;
    int k = idx / H, j = idx % H;
    Bg[idx] = __float2half(Whh[(512 + j) * H + k]);
    if (k == 0) nb[256 + j] = bhh[512 + j];
}

__global__ void zero_kernel(float4* __restrict__ p, size_t n4) {
    size_t i = (size_t)blockIdx.x * blockDim.x + threadIdx.x;
    for (; i < n4; i += (size_t)gridDim.x * blockDim.x)
        p[i] = make_float4(0.f, 0.f, 0.f, 0.f);
}

__global__ void convert_min_kernel(const float* __restrict__ m_in, __half* __restrict__ aao, int N)
{
    size_t idx = (size_t)blockIdx.x * blockDim.x + threadIdx.x;
    size_t total = (size_t)N * H;
    for (; idx < total; idx += (size_t)gridDim.x * blockDim.x) {
        int n = (int)(idx / H), c = (int)(idx % H);
        aao[(size_t)n * AO_K + 165 + c] = __float2half(m_in[idx]);
    }
}

__global__ void readout_kernel(const float* __restrict__ hgraph, const float* __restrict__ Wr,
                               const float* __restrict__ br, float* __restrict__ out)
{
    int gph = blockIdx.x, t = threadIdx.x;
    if (t < NUM_TASKS) {
        float s = br[t];
        const float* row = hgraph + gph * H;
        #pragma unroll 8
        for (int k = 0; k < H; k++) s += row[k] * Wr[k * NUM_TASKS + t];
        out[gph * NUM_TASKS + t] = s;
    }
}

// ---------------- host launcher ----------------
extern "C" void kernel_launch(void* const* d_in, const int* in_sizes, int n_in,
                              void* d_out, int out_size)
{
    const int*   x_z        = (const int*)  d_in[0];
    const float* x_atom     = (const float*)d_in[1];
    const int*   ei         = (const int*)  d_in[2];
    const float* edge_attr  = (const float*)d_in[3];
    const int*   batch      = (const int*)  d_in[4];
    const float* embed_z    = (const float*)d_in[5];
    const float* W_atom_in  = (const float*)d_in[6];
    const float* b_atom_in  = (const float*)d_in[7];
    const float* W_bond_in  = (const float*)d_in[8];
    const float* b_bond_in  = (const float*)d_in[9];
    const float* W_msg      = (const float*)d_in[10];
    const float* W_ih       = (const float*)d_in[11];
    const float* b_ih       = (const float*)d_in[12];
    const float* W_hh       = (const float*)d_in[13];
    const float* b_hh       = (const float*)d_in[14];
    const float* W_atom_out = (const float*)d_in[15];
    const float* b_atom_out = (const float*)d_in[16];
    const float* W_read     = (const float*)d_in[17];
    const float* b_read     = (const float*)d_in[18];
    const float* g_e        = (const float*)d_in[19];
    const float* be_e       = (const float*)d_in[20];
    const float* g_a        = (const float*)d_in[21];
    const float* be_a       = (const float*)d_in[22];

    const int N  = in_sizes[0];
    const int E  = in_sizes[2] / 2;
    const int E2 = 2 * E;

    float* out       = (float*)d_out;
    float* out_hatom = out + NUM_GRAPHS * NUM_TASKS;
    float* out_he    = out_hatom + (size_t)N * H;

    float  *h_all, *hpre, *m_in, *hgraph, *rzbias, *nbias;
    __half *a16, *aao, *acat, *Gn, *wain, *wmsg, *wao, *brz, *bgin, *bghn;
    cudaGetSymbolAddress((void**)&h_all,  g_h_all);
    cudaGetSymbolAddress((void**)&hpre,   g_hpre);
    cudaGetSymbolAddress((void**)&m_in,   g_m_in);
    cudaGetSymbolAddress((void**)&hgraph, g_hgraph);
    cudaGetSymbolAddress((void**)&rzbias, g_rzbias);
    cudaGetSymbolAddress((void**)&nbias,  g_nbias);
    cudaGetSymbolAddress((void**)&a16,    g_a16);
    cudaGetSymbolAddress((void**)&aao,    g_aao);
    cudaGetSymbolAddress((void**)&acat,   g_acat);
    cudaGetSymbolAddress((void**)&Gn,     g_Gn);
    cudaGetSymbolAddress((void**)&wain,   g_wain);
    cudaGetSymbolAddress((void**)&wmsg,   g_wmsg);
    cudaGetSymbolAddress((void**)&wao,    g_wao);
    cudaGetSymbolAddress((void**)&brz,    g_brz);
    cudaGetSymbolAddress((void**)&bgin,   g_bgin);
    cudaGetSymbolAddress((void**)&bghn,   g_bghn);

    cudaFuncSetAttribute(hgemm_kernel<0>, cudaFuncAttributeMaxDynamicSharedMemorySize, GEMM_SMEM);
    cudaFuncSetAttribute(hgemm_kernel<2>, cudaFuncAttributeMaxDynamicSharedMemorySize, GEMM_SMEM);
    cudaFuncSetAttribute(hgemm_kernel<3>, cudaFuncAttributeMaxDynamicSharedMemorySize, GEMM_SMEM);
    cudaFuncSetAttribute(msg_gemm_kernel, cudaFuncAttributeMaxDynamicSharedMemorySize, MSG_SMEM);

    const size_t minN4 = (size_t)N * H / 4;

    // prep
    zero_kernel<<<1024, 256>>>((float4*)m_in, minN4);
    build_a16_kernel<<<4096, 256>>>(x_z, x_atom, embed_z, a16, aao, N);
    build_wain16<<<cdiv(AIN_K * H, 256), 256>>>(W_atom_in, wain);
    build_wmsg16<<<cdiv(H * H, 256), 256>>>(W_msg, wmsg);
    build_wao16<<<cdiv(AO_K * H, 256), 256>>>(W_atom_out, wao);
    build_brz_kernel<<<cdiv(ACAT_W * RZ_N, 256), 256>>>(W_ih, W_hh, b_ih, b_hh, brz, rzbias);
    build_bgin_kernel<<<cdiv(H * H, 256), 256>>>(W_ih, b_ih, bgin, nbias);
    build_bghn_kernel<<<cdiv(H * H, 256), 256>>>(W_hh, b_hh, bghn, nbias);

    // h_all = a_all @ W_atom_in + b
    hgemm_kernel<0><<<dim3(cdiv(H, GBN), cdiv(N, GBM)), 256, GEMM_SMEM>>>(
        a16, wain, b_atom_in, nullptr, h_all, nullptr, nullptr, nullptr,
        N, H, AIN_K, AIN_K, H, 0);
    // h_e init (bond fused) -> acat fp16 + scatter
    edge_init_kernel<<<cdiv(E2, 8), 256>>>(ei, h_all, edge_attr, W_bond_in, b_bond_in,
                                           g_e, be_e, acat, m_in, E);

    for (int depth = 0; depth < DEPTH; depth++) {
        // fused gather + msg GEMM: h_new = relu(h_e + (m_in[src]-h_e[rev]) @ W_msg) -> acat cols 0..255
        msg_gemm_kernel<<<dim3(cdiv(H, GBN), cdiv(E2, GBM)), 256, MSG_SMEM>>>(
            m_in, wmsg, ei, acat, E);
        // gin / ghn -> Gn blocked [gin | ghn]
        hgemm_kernel<2><<<dim3(cdiv(H, GBN), cdiv(E2, GBM)), 256, GEMM_SMEM>>>(
            acat, bgin, nullptr, nullptr, nullptr, Gn, nullptr, nullptr,
            E2, H, H, ACAT_W, RZ_N, 0);
        hgemm_kernel<2><<<dim3(cdiv(H, GBN), cdiv(E2, GBM)), 256, GEMM_SMEM>>>(
            acat + H, bghn, nullptr, nullptr, nullptr, Gn, nullptr, nullptr,
            E2, H, H, ACAT_W, RZ_N, 256);
        zero_kernel<<<1024, 256>>>((float4*)m_in, minN4);
        // rz GEMM + fused GRU -> hpre  (hp read from acat fp16)
        hgemm_kernel<3><<<dim3(cdiv(RZ_N, GBN), cdiv(E2, GBM)), 256, GEMM_SMEM>>>(
            acat, brz, rzbias, nbias, hpre, nullptr, Gn, acat,
            E2, RZ_N, ACAT_W, ACAT_W, RZ_N, 0);
        // LN + scatter; intermediate depths -> acat fp16, last depth -> fp32 out_he
        if (depth < DEPTH - 1)
            ln_scatter_kernel<true><<<cdiv(E2, 8), 256>>>(hpre, ei, g_e, be_e, nullptr, acat, m_in, E);
        else
            ln_scatter_kernel<false><<<cdiv(E2, 8), 256>>>(hpre, ei, g_e, be_e, out_he, nullptr, m_in, E);
    }

    // m_to_atom accumulated by last ln_scatter
    convert_min_kernel<<<2048, 256>>>(m_in, aao, N);

    // h_atom = LN(relu([a_all | m_to_atom] @ W_atom_out + b))
    hgemm_kernel<0><<<dim3(cdiv(H, GBN), cdiv(N, GBM)), 256, GEMM_SMEM>>>(
        aao, wao, b_atom_out, nullptr, h_all, nullptr, nullptr, nullptr,
        N, H, AO_K, AO_K, H, 0);
    zero_kernel<<<64, 256>>>((float4*)hgraph, (size_t)NUM_GRAPHS * H / 4);
    relu_ln_graph_kernel<<<cdiv(N, 8), 256>>>(h_all, batch, g_a, be_a, out_hatom, hgraph, N);
    readout_kernel<<<NUM_GRAPHS, 32>>>(hgraph, W_read, b_read, out);
}

// round 15
// speedup vs baseline: 4.2653x; 1.0014x over previous
#include <cuda_runtime.h>
#include <cuda_fp16.h>
#include <stdint.h>
#include <cstdint>
#include <math.h>

// ---------------- problem constants ----------------
#define MAX_N 50000
#define MAX_E 200000
#define H 256
#define ATOM_IN 133
#define BOND_IN 14
#define NUM_TASKS 12
#define NUM_GRAPHS 256
#define DEPTH 3
#define EPS 1e-5f

#define AIN_K 192
#define AO_K  448
#define ACAT_W 512
#define RZ_N  512

// ---------------- scratch ----------------
__device__ float  g_h_all[(size_t)MAX_N * H];
__device__ float  g_hpre [(size_t)(2*MAX_E) * H];
__device__ float  g_m_in [(size_t)MAX_N * H];
__device__ float  g_hgraph[NUM_GRAPHS * H];
__device__ float  g_rzbias[RZ_N];
__device__ float  g_nbias [RZ_N];
__device__ __half g_a16  [(size_t)MAX_N * AIN_K];
__device__ __half g_aao  [(size_t)MAX_N * AO_K];
__device__ __half g_acat [(size_t)(2*MAX_E) * ACAT_W];   // [h_new | h_e] fp16
__device__ __half g_Gn   [(size_t)(2*MAX_E) * RZ_N];     // [gin(256) | ghn(256)] blocked
__device__ __half g_wain [AIN_K * H];
__device__ __half g_wmsg [H * H];
__device__ __half g_wao  [AO_K * H];
__device__ __half g_brz  [ACAT_W * RZ_N];
__device__ __half g_bgin [H * H];
__device__ __half g_bghn [H * H];

static inline int cdiv(int a, int b) { return (a + b - 1) / b; }

#define CP_ASYNC16(dst, src) asm volatile("cp.async.cg.shared.global [%0], [%1], 16;\n" :: "r"(dst), "l"(src))
#define CP_COMMIT()          asm volatile("cp.async.commit_group;\n")
#define CP_WAIT2()           asm volatile("cp.async.wait_group 2;\n")

__device__ __forceinline__ void red_add_v4(float* p, float a, float b, float c, float d) {
    asm volatile("red.global.v4.f32.add [%0], {%1,%2,%3,%4};"
                 :: "l"(p), "f"(a), "f"(b), "f"(c), "f"(d) : "memory");
}

// ---------------- mma.sync HGEMM core pieces ----------------
#define GBM 128
#define GBN 128
#define GBK 32
#define SPAD 8
#define STAGES 4
#define A_STG (GBM * (GBK + SPAD))
#define B_STG (GBK * (GBN + SPAD))
#define GEMM_SMEM (STAGES * (A_STG + B_STG) * 2)              // 75776
#define MSG_SMEM  ((2 * A_STG + STAGES * B_STG) * 2)          // 55296

__device__ __forceinline__ void ldsm_x4(uint32_t& r0, uint32_t& r1, uint32_t& r2, uint32_t& r3, uint32_t addr) {
    asm volatile("ldmatrix.sync.aligned.m8n8.x4.shared.b16 {%0,%1,%2,%3}, [%4];\n"
                 : "=r"(r0), "=r"(r1), "=r"(r2), "=r"(r3) : "r"(addr));
}
__device__ __forceinline__ void ldsm_x4t(uint32_t& r0, uint32_t& r1, uint32_t& r2, uint32_t& r3, uint32_t addr) {
    asm volatile("ldmatrix.sync.aligned.m8n8.x4.trans.shared.b16 {%0,%1,%2,%3}, [%4];\n"
                 : "=r"(r0), "=r"(r1), "=r"(r2), "=r"(r3) : "r"(addr));
}
__device__ __forceinline__ void mma_16816(float* d, const uint32_t* a, const uint32_t* b) {
    asm volatile("mma.sync.aligned.m16n8k16.row.col.f32.f16.f16.f32 "
                 "{%0,%1,%2,%3}, {%4,%5,%6,%7}, {%8,%9}, {%0,%1,%2,%3};\n"
                 : "+f"(d[0]), "+f"(d[1]), "+f"(d[2]), "+f"(d[3])
                 : "r"(a[0]), "r"(a[1]), "r"(a[2]), "r"(a[3]), "r"(b[0]), "r"(b[1]));
}

__device__ __forceinline__ void ldsm_a(const __half* as, int ks, int lane, int wm, uint32_t af[2][4]) {
    const int k0 = ks * 16;
    #pragma unroll
    for (int mi = 0; mi < 2; mi++) {
        int row = wm * 32 + mi * 16 + (lane & 15);
        int col = k0 + ((lane >> 4) << 3);
        uint32_t ad = (uint32_t)__cvta_generic_to_shared(as + row * (GBK + SPAD) + col);
        ldsm_x4(af[mi][0], af[mi][1], af[mi][2], af[mi][3], ad);
    }
}
__device__ __forceinline__ void ldsm_b(const __half* bs, int ks, int lane, int wn, uint32_t bf[8][2]) {
    const int k0 = ks * 16;
    #pragma unroll
    for (int nq = 0; nq < 4; nq++) {
        int row = k0 + (lane & 15);
        int col = wn * 64 + nq * 16 + ((lane >> 4) << 3);
        uint32_t bd = (uint32_t)__cvta_generic_to_shared(bs + row * (GBN + SPAD) + col);
        ldsm_x4t(bf[nq*2][0], bf[nq*2][1], bf[nq*2+1][0], bf[nq*2+1][1], bd);
    }
}

// compute one 32-K tile: prefetch ALL fragments (both 16-K halves), then issue 32 HMMA.
// LDS latency is paid once per tile instead of at each half boundary.
__device__ __forceinline__ void tile_mma(const __half* as, const __half* bs,
                                         int lane, int wm, int wn, float acc[2][8][4])
{
    uint32_t af[2][2][4];
    uint32_t bf[2][8][2];
    ldsm_a(as, 0, lane, wm, af[0]);
    ldsm_b(bs, 0, lane, wn, bf[0]);
    ldsm_a(as, 1, lane, wm, af[1]);
    ldsm_b(bs, 1, lane, wn, bf[1]);
    #pragma unroll
    for (int ks = 0; ks < 2; ks++)
        #pragma unroll
        for (int mi = 0; mi < 2; mi++)
            #pragma unroll
            for (int nj = 0; nj < 8; nj++)
                mma_16816(acc[mi][nj], af[ks][mi], bf[ks][nj]);
}

__device__ __forceinline__ float sigmoidf_(float x) { return 1.f / (1.f + expf(-x)); }

// ---------------- generic HGEMM (EPI 0/2/3) ----------------
// EPI 0: outF = acc + bias[col]
// EPI 2: outH[row*ldOut + colOff + col] = half2(v0,v1)   (gin/ghn -> Gn blocked)
// EPI 3: fused GRU: r,z = acc pair; gin,ghn from auxH (Gn); hp from auxH2 (acat fp16) -> outF[row*H+j]
template<int EPI>
__global__ __launch_bounds__(256, 2) void hgemm_kernel(
    const __half* __restrict__ A, const __half* __restrict__ B,
    const float* __restrict__ bias, const float* __restrict__ bias2,
    float* __restrict__ outF, __half* __restrict__ outH,
    const __half* __restrict__ auxH, const __half* __restrict__ auxH2,
    int M, int N, int K, int ldA, int ldOut, int colOff)
{
    extern __shared__ __align__(16) __half sm[];
    __half* smA = sm;
    __half* smB = sm + STAGES * A_STG;

    const int tid  = threadIdx.x;
    const int lane = tid & 31;
    const int warp = tid >> 5;
    const int wm   = warp & 3;
    const int wn   = warp >> 2;
    const int bm   = blockIdx.y * GBM;
    const int bn   = blockIdx.x * GBN;

    float acc[2][8][4];
    #pragma unroll
    for (int i = 0; i < 2; i++)
        #pragma unroll
        for (int j = 0; j < 8; j++)
            #pragma unroll
            for (int k = 0; k < 4; k++) acc[i][j][k] = 0.f;

    const int ar = tid >> 2;
    const int ac = (tid & 3) << 3;
    const int br = tid >> 4;
    const int bc = (tid & 15) << 3;
    const int KT = K / GBK;

    auto load_tile = [&](int kt, int s) {
        const int k0 = kt * GBK;
        __half* as = smA + s * A_STG;
        __half* bs = smB + s * B_STG;
        #pragma unroll
        for (int i = 0; i < 2; i++) {
            int r  = ar + i * 64;
            int gr = bm + r; if (gr >= M) gr = M - 1;
            const __half* src = A + (size_t)gr * ldA + k0 + ac;
            uint32_t dst = (uint32_t)__cvta_generic_to_shared(as + r * (GBK + SPAD) + ac);
            CP_ASYNC16(dst, src);
        }
        #pragma unroll
        for (int i = 0; i < 2; i++) {
            int r = br + i * 16;
            const __half* src = B + (size_t)(k0 + r) * N + bn + bc;
            uint32_t dst = (uint32_t)__cvta_generic_to_shared(bs + r * (GBN + SPAD) + bc);
            CP_ASYNC16(dst, src);
        }
    };

    #pragma unroll
    for (int p = 0; p < STAGES - 1; p++) {
        if (p < KT) load_tile(p, p);
        CP_COMMIT();
    }

    for (int kt = 0; kt < KT; kt++) {
        CP_WAIT2();
        __syncthreads();   // orders all warps' tile_mma(kt-1) before any overwrite of that stage below
        const int s = kt % STAGES;
        if (kt + STAGES - 1 < KT) load_tile(kt + STAGES - 1, (kt + STAGES - 1) % STAGES);
        CP_COMMIT();
        tile_mma(smA + s * A_STG, smB + s * B_STG, lane, wm, wn, acc);
        // no trailing sync: the top-of-loop barrier provides the stage-reuse ordering
    }

    const int r0 = bm + wm * 32 + (lane >> 2);
    const int c0 = bn + wn * 64 + ((lane & 3) << 1);
    #pragma unroll
    for (int mi = 0; mi < 2; mi++) {
        #pragma unroll
        for (int nj = 0; nj < 8; nj++) {
            const int col = c0 + nj * 8;
            #pragma unroll
            for (int hh = 0; hh < 2; hh++) {
                const int row = r0 + mi * 16 + hh * 8;
                if (row >= M) continue;
                float v0 = acc[mi][nj][hh * 2 + 0];
                float v1 = acc[mi][nj][hh * 2 + 1];
                if (EPI == 0) {
                    outF[(size_t)row * ldOut + col]     = v0 + bias[col];
                    outF[(size_t)row * ldOut + col + 1] = v1 + bias[col + 1];
                } else if (EPI == 2) {
                    __half2 hv = __floats2half2_rn(v0, v1);
                    *(__half2*)(outH + (size_t)row * ldOut + colOff + col) = hv;
                } else {
                    float r = sigmoidf_(v0 + bias[col]);
                    float z = sigmoidf_(v1 + bias[col + 1]);
                    int j = col >> 1;
                    float gin = __half2float(auxH[(size_t)row * ldOut + j])       + bias2[j];
                    float ghn = __half2float(auxH[(size_t)row * ldOut + 256 + j]) + bias2[256 + j];
                    float n = tanhf(gin + r * ghn);
                    float hp = __half2float(auxH2[(size_t)row * ACAT_W + H + j]);
                    outF[(size_t)row * H + j] = (1.f - z) * n + z * hp;
                }
            }
        }
    }
}

// ---------------- fused gather + msg GEMM ----------------
// A[d][k] = m_in[src[d]][k] - h_e16[rev[d]][k]   (built in-kernel)
// C = A @ W_msg ; epilogue: acat[row][col] = half(relu(C + h_e16[row][col]))
__global__ __launch_bounds__(256, 2) void msg_gemm_kernel(
    const float* __restrict__ m_in, const __half* __restrict__ Bw,
    const int* __restrict__ ei, __half* __restrict__ acat, int E)
{
    extern __shared__ __align__(16) __half sm[];
    __half* smA = sm;                    // 2 stages
    __half* smB = sm + 2 * A_STG;        // STAGES stages
    const int E2 = 2 * E;

    const int tid  = threadIdx.x;
    const int lane = tid & 31;
    const int warp = tid >> 5;
    const int wm   = warp & 3;
    const int wn   = warp >> 2;
    const int bm   = blockIdx.y * GBM;
    const int bn   = blockIdx.x * GBN;

    // A producer: thread covers row pr, 16 cols at pc within each 32-col k-tile
    const int pr = tid >> 1;
    const int pc = (tid & 1) * 16;
    int dd = bm + pr; if (dd >= E2) dd = E2 - 1;
    const int src = ei[dd];
    const int rv  = (dd < E) ? dd + E : dd - E;
    const float*  mrow  = m_in + (size_t)src * H;
    const __half* herow = acat + (size_t)rv * ACAT_W + H;

    const int br = tid >> 4;
    const int bc = (tid & 15) << 3;
    const int KT = H / GBK;   // 8

    float4 am[4]; uint4 ah[2];
    auto loadA = [&](int kt) {
        const int c0 = kt * GBK + pc;
        am[0] = *(const float4*)(mrow + c0);
        am[1] = *(const float4*)(mrow + c0 + 4);
        am[2] = *(const float4*)(mrow + c0 + 8);
        am[3] = *(const float4*)(mrow + c0 + 12);
        ah[0] = *(const uint4*)(herow + c0);
        ah[1] = *(const uint4*)(herow + c0 + 8);
    };
    auto stsA = [&](int s) {
        __half hx[16];
        const __half* hp = (const __half*)ah;
        #pragma unroll
        for (int i = 0; i < 4; i++) {
            const float* mf = (const float*)&am[i];
            #pragma unroll
            for (int j = 0; j < 4; j++)
                hx[i*4 + j] = __float2half(mf[j] - __half2float(hp[i*4 + j]));
        }
        __half* dst = smA + s * A_STG + pr * (GBK + SPAD) + pc;
        *(uint4*)dst       = *(const uint4*)hx;
        *(uint4*)(dst + 8) = *(const uint4*)(hx + 8);
    };
    auto loadB = [&](int kt, int s) {
        const int k0 = kt * GBK;
        __half* bs = smB + s * B_STG;
        #pragma unroll
        for (int i = 0; i < 2; i++) {
            int r = br + i * 16;
            const __half* srcp = Bw + (size_t)(k0 + r) * H + bn + bc;
            uint32_t dst = (uint32_t)__cvta_generic_to_shared(bs + r * (GBN + SPAD) + bc);
            CP_ASYNC16(dst, srcp);
        }
    };

    float acc[2][8][4];
    #pragma unroll
    for (int i = 0; i < 2; i++)
        #pragma unroll
        for (int j = 0; j < 8; j++)
            #pragma unroll
            for (int k = 0; k < 4; k++) acc[i][j][k] = 0.f;

    loadA(0);
    #pragma unroll
    for (int p = 0; p < STAGES - 1; p++) {
        if (p < KT) loadB(p, p);
        CP_COMMIT();
    }

    for (int kt = 0; kt < KT; kt++) {
        stsA(kt & 1);
        if (kt + 1 < KT) loadA(kt + 1);
        CP_WAIT2();
        __syncthreads();   // orders stsA writes before reads AND prior-tile readers before this stsA
        if (kt + STAGES - 1 < KT) loadB(kt + STAGES - 1, (kt + STAGES - 1) % STAGES);
        CP_COMMIT();
        tile_mma(smA + (kt & 1) * A_STG, smB + (kt % STAGES) * B_STG, lane, wm, wn, acc);
        // no trailing sync (see hgemm_kernel)
    }

    const int r0 = bm + wm * 32 + (lane >> 2);
    const int c0 = bn + wn * 64 + ((lane & 3) << 1);
    #pragma unroll
    for (int mi = 0; mi < 2; mi++) {
        #pragma unroll
        for (int nj = 0; nj < 8; nj++) {
            const int col = c0 + nj * 8;
            #pragma unroll
            for (int hh = 0; hh < 2; hh++) {
                const int row = r0 + mi * 16 + hh * 8;
                if (row >= E2) continue;
                __half2 he2 = *(const __half2*)(acat + (size_t)row * ACAT_W + H + col);
                float v0 = fmaxf(acc[mi][nj][hh*2+0] + __low2float(he2),  0.f);
                float v1 = fmaxf(acc[mi][nj][hh*2+1] + __high2float(he2), 0.f);
                *(__half2*)(acat + (size_t)row * ACAT_W + col) = __floats2half2_rn(v0, v1);
            }
        }
    }
}

// ---------------- warp-per-row helpers ----------------

__device__ __forceinline__ void warp_ln_8(float* v, int lane,
                                          const float* __restrict__ g,
                                          const float* __restrict__ be,
                                          float* y)
{
    float sum = 0.f, sq = 0.f;
    #pragma unroll
    for (int i = 0; i < 8; i++) { sum += v[i]; sq += v[i] * v[i]; }
    #pragma unroll
    for (int o = 16; o > 0; o >>= 1) {
        sum += __shfl_xor_sync(0xffffffffu, sum, o);
        sq  += __shfl_xor_sync(0xffffffffu, sq,  o);
    }
    float mu = sum * (1.f / H);
    float var = sq * (1.f / H) - mu * mu;
    float rs = rsqrtf(var + EPS);
    const float4* g4  = (const float4*)(g  + lane * 8);
    const float4* be4 = (const float4*)(be + lane * 8);
    float4 ga = g4[0], gb = g4[1], ba = be4[0], bb = be4[1];
    y[0] = (v[0] - mu) * rs * ga.x + ba.x;
    y[1] = (v[1] - mu) * rs * ga.y + ba.y;
    y[2] = (v[2] - mu) * rs * ga.z + ba.z;
    y[3] = (v[3] - mu) * rs * ga.w + ba.w;
    y[4] = (v[4] - mu) * rs * gb.x + bb.x;
    y[5] = (v[5] - mu) * rs * gb.y + bb.y;
    y[6] = (v[6] - mu) * rs * gb.z + bb.z;
    y[7] = (v[7] - mu) * rs * gb.w + bb.w;
}

__device__ __forceinline__ void store_half8(__half* p, const float* y) {
    __half2 h0 = __floats2half2_rn(y[0], y[1]);
    __half2 h1 = __floats2half2_rn(y[2], y[3]);
    __half2 h2 = __floats2half2_rn(y[4], y[5]);
    __half2 h3 = __floats2half2_rn(y[6], y[7]);
    uint4 u;
    u.x = *(uint32_t*)&h0; u.y = *(uint32_t*)&h1;
    u.z = *(uint32_t*)&h2; u.w = *(uint32_t*)&h3;
    *(uint4*)p = u;
}

// h_e init: LN(relu(h_all[src] + edge_attr@W_bond + b)) -> acat fp16 + scatter
__global__ void edge_init_kernel(const int* __restrict__ ei, const float* __restrict__ h_all,
                                 const float* __restrict__ eattr, const float* __restrict__ Wb,
                                 const float* __restrict__ bb_,
                                 const float* __restrict__ g, const float* __restrict__ be,
                                 __half* __restrict__ acat, float* __restrict__ m_in, int E)
{
    int d = blockIdx.x * 8 + (threadIdx.x >> 5);
    if (d >= 2 * E) return;
    int lane = threadIdx.x & 31;
    int src = ei[d];
    int e = (d < E) ? d : d - E;

    float ew[14];
    const float* er = eattr + (size_t)e * BOND_IN;
    #pragma unroll
    for (int k = 0; k < BOND_IN; k++) ew[k] = er[k];
    float ev[8];
    {
        const float4* b4 = (const float4*)(bb_ + lane * 8);
        float4 e0 = b4[0], e1 = b4[1];
        ev[0]=e0.x; ev[1]=e0.y; ev[2]=e0.z; ev[3]=e0.w;
        ev[4]=e1.x; ev[5]=e1.y; ev[6]=e1.z; ev[7]=e1.w;
    }
    #pragma unroll
    for (int k = 0; k < BOND_IN; k++) {
        const float4* w4 = (const float4*)(Wb + k * H + lane * 8);
        float4 w0 = w4[0], w1 = w4[1];
        ev[0] += ew[k]*w0.x; ev[1] += ew[k]*w0.y; ev[2] += ew[k]*w0.z; ev[3] += ew[k]*w0.w;
        ev[4] += ew[k]*w1.x; ev[5] += ew[k]*w1.y; ev[6] += ew[k]*w1.z; ev[7] += ew[k]*w1.w;
    }

    const float4* ha = (const float4*)(h_all + (size_t)src * H + lane * 8);
    float4 a0 = ha[0], a1 = ha[1];
    float v[8] = {
        fmaxf(a0.x + ev[0], 0.f), fmaxf(a0.y + ev[1], 0.f),
        fmaxf(a0.z + ev[2], 0.f), fmaxf(a0.w + ev[3], 0.f),
        fmaxf(a1.x + ev[4], 0.f), fmaxf(a1.y + ev[5], 0.f),
        fmaxf(a1.z + ev[6], 0.f), fmaxf(a1.w + ev[7], 0.f) };
    float y[8];
    warp_ln_8(v, lane, g, be, y);
    store_half8(acat + (size_t)d * ACAT_W + H + lane * 8, y);
    int dst = (d < E) ? ei[E + d] : ei[d - E];
    float* mb = m_in + (size_t)dst * H + lane * 8;
    red_add_v4(mb,     y[0], y[1], y[2], y[3]);
    red_add_v4(mb + 4, y[4], y[5], y[6], y[7]);
}

// LN of GRU output + scatter; W16: write acat fp16 copy; !W16 (last depth): write fp32 out
template<bool W16>
__global__ void ln_scatter_kernel(const float* __restrict__ x, const int* __restrict__ ei,
                                  const float* __restrict__ g, const float* __restrict__ be,
                                  float* __restrict__ outp, __half* __restrict__ acat,
                                  float* __restrict__ m_in, int E)
{
    int d = blockIdx.x * 8 + (threadIdx.x >> 5);
    if (d >= 2 * E) return;
    int lane = threadIdx.x & 31;
    const float4* xr = (const float4*)(x + (size_t)d * H + lane * 8);
    float4 x0 = xr[0], x1 = xr[1];
    float v[8] = {x0.x, x0.y, x0.z, x0.w, x1.x, x1.y, x1.z, x1.w};
    float y[8];
    warp_ln_8(v, lane, g, be, y);
    if (W16) {
        store_half8(acat + (size_t)d * ACAT_W + H + lane * 8, y);
    } else {
        float4* o4 = (float4*)(outp + (size_t)d * H + lane * 8);
        o4[0] = make_float4(y[0], y[1], y[2], y[3]);
        o4[1] = make_float4(y[4], y[5], y[6], y[7]);
    }
    int dst = (d < E) ? ei[E + d] : ei[d - E];
    float* mb = m_in + (size_t)dst * H + lane * 8;
    red_add_v4(mb,     y[0], y[1], y[2], y[3]);
    red_add_v4(mb + 4, y[4], y[5], y[6], y[7]);
}

// h_atom = LN(relu(x)) -> out; vector atomic into hgraph[batch[n]]
__global__ void relu_ln_graph_kernel(const float* __restrict__ x, const int* __restrict__ batch,
                                     const float* __restrict__ g, const float* __restrict__ be,
                                     float* __restrict__ out, float* __restrict__ hgraph, int N)
{
    int n = blockIdx.x * 8 + (threadIdx.x >> 5);
    if (n >= N) return;
    int lane = threadIdx.x & 31;
    const float4* xr = (const float4*)(x + (size_t)n * H + lane * 8);
    float4 x0 = xr[0], x1 = xr[1];
    float v[8] = {fmaxf(x0.x, 0.f), fmaxf(x0.y, 0.f), fmaxf(x0.z, 0.f), fmaxf(x0.w, 0.f),
                  fmaxf(x1.x, 0.f), fmaxf(x1.y, 0.f), fmaxf(x1.z, 0.f), fmaxf(x1.w, 0.f)};
    float y[8];
    warp_ln_8(v, lane, g, be, y);
    float4* o4 = (float4*)(out + (size_t)n * H + lane * 8);
    o4[0] = make_float4(y[0], y[1], y[2], y[3]);
    o4[1] = make_float4(y[4], y[5], y[6], y[7]);
    float* hb = hgraph + (size_t)batch[n] * H + lane * 8;
    red_add_v4(hb,     y[0], y[1], y[2], y[3]);
    red_add_v4(hb + 4, y[4], y[5], y[6], y[7]);
}

// ---------------- prep / misc ----------------
__global__ void build_a16_kernel(const int* __restrict__ xz, const float* __restrict__ xa,
                                 const float* __restrict__ emb,
                                 __half* __restrict__ a16, __half* __restrict__ aao, int N)
{
    size_t idx = (size_t)blockIdx.x * blockDim.x + threadIdx.x;
    size_t total = (size_t)N * AO_K;
    for (; idx < total; idx += (size_t)gridDim.x * blockDim.x) {
        int n = (int)(idx / AO_K);
        int c = (int)(idx % AO_K);
        if (c < AIN_K) {
            float v = (c < 32) ? emb[xz[n] * 32 + c]
                    : (c < 165) ? xa[(size_t)n * ATOM_IN + (c - 32)] : 0.f;
            __half h = __float2half(v);
            a16[(size_t)n * AIN_K + c] = h;
            if (c < 165) aao[(size_t)n * AO_K + c] = h;
        } else if (c >= 421) {
            aao[idx] = __float2half(0.f);
        }
    }
}

__global__ void build_wain16(const float* __restrict__ W, __half* __restrict__ O) {
    int idx = blockIdx.x * blockDim.x + threadIdx.x;
    if (idx >= AIN_K * H) return;
    int k = idx / H, c = idx % H;
    O[idx] = __float2half(k < 165 ? W[k * H + c] : 0.f);
}
__global__ void build_wmsg16(const float* __restrict__ W, __half* __restrict__ O) {
    int idx = blockIdx.x * blockDim.x + threadIdx.x;
    if (idx < H * H) O[idx] = __float2half(W[idx]);
}
__global__ void build_wao16(const float* __restrict__ W, __half* __restrict__ O) {
    int idx = blockIdx.x * blockDim.x + threadIdx.x;
    if (idx >= AO_K * H) return;
    int k = idx / H, c = idx % H;
    O[idx] = __float2half(k < 421 ? W[k * H + c] : 0.f);
}

__global__ void build_brz_kernel(const float* __restrict__ Wih, const float* __restrict__ Whh,
                                 const float* __restrict__ bih, const float* __restrict__ bhh,
                                 __half* __restrict__ Brz, float* __restrict__ rzb)
{
    int idx = blockIdx.x * blockDim.x + threadIdx.x;
    if (idx >= ACAT_W * RZ_N) return;
    int k = idx / RZ_N, c = idx % RZ_N;
    int j = c >> 1;
    int gateRow = (c & 1) ? (256 + j) : j;
    float v = (k < 256) ? Wih[gateRow * H + k] : Whh[gateRow * H + (k - 256)];
    Brz[idx] = __float2half(v);
    if (k == 0) rzb[c] = bih[gateRow] + bhh[gateRow];
}
__global__ void build_bgin_kernel(const float* __restrict__ Wih, const float* __restrict__ bih,
                                  __half* __restrict__ Bg, float* __restrict__ nb)
{
    int idx = blockIdx.x * blockDim.x + threadIdx.x;
    if (idx >= H * H) return;
    int k = idx / H, j = idx % H;
    Bg[idx] = __float2half(Wih[(512 + j) * H + k]);
    if (k == 0) nb[j] = bih[512 + j];
}
__global__ void build_bghn_kernel(const float* __restrict__ Whh, const float* __restrict__ bhh,
                                  __half* __restrict__ Bg, float* __restrict__ nb)
{
    int idx = blockIdx.x * blockDim.x + threadIdx.x;
    if (idx >= H * H) return;
    int k = idx / H, j = idx % H;
    Bg[idx] = __float2half(Whh[(512 + j) * H + k]);
    if (k == 0) nb[256 + j] = bhh[512 + j];
}

__global__ void zero_kernel(float4* __restrict__ p, size_t n4) {
    size_t i = (size_t)blockIdx.x * blockDim.x + threadIdx.x;
    for (; i < n4; i += (size_t)gridDim.x * blockDim.x)
        p[i] = make_float4(0.f, 0.f, 0.f, 0.f);
}

__global__ void convert_min_kernel(const float* __restrict__ m_in, __half* __restrict__ aao, int N)
{
    size_t idx = (size_t)blockIdx.x * blockDim.x + threadIdx.x;
    size_t total = (size_t)N * H;
    for (; idx < total; idx += (size_t)gridDim.x * blockDim.x) {
        int n = (int)(idx / H), c = (int)(idx % H);
        aao[(size_t)n * AO_K + 165 + c] = __float2half(m_in[idx]);
    }
}

__global__ void readout_kernel(const float* __restrict__ hgraph, const float* __restrict__ Wr,
                               const float* __restrict__ br, float* __restrict__ out)
{
    int gph = blockIdx.x, t = threadIdx.x;
    if (t < NUM_TASKS) {
        float s = br[t];
        const float* row = hgraph + gph * H;
        #pragma unroll 8
        for (int k = 0; k < H; k++) s += row[k] * Wr[k * NUM_TASKS + t];
        out[gph * NUM_TASKS + t] = s;
    }
}

// ---------------- host launcher ----------------
extern "C" void kernel_launch(void* const* d_in, const int* in_sizes, int n_in,
                              void* d_out, int out_size)
{
    const int*   x_z        = (const int*)  d_in[0];
    const float* x_atom     = (const float*)d_in[1];
    const int*   ei         = (const int*)  d_in[2];
    const float* edge_attr  = (const float*)d_in[3];
    const int*   batch      = (const int*)  d_in[4];
    const float* embed_z    = (const float*)d_in[5];
    const float* W_atom_in  = (const float*)d_in[6];
    const float* b_atom_in  = (const float*)d_in[7];
    const float* W_bond_in  = (const float*)d_in[8];
    const float* b_bond_in  = (const float*)d_in[9];
    const float* W_msg      = (const float*)d_in[10];
    const float* W_ih       = (const float*)d_in[11];
    const float* b_ih       = (const float*)d_in[12];
    const float* W_hh       = (const float*)d_in[13];
    const float* b_hh       = (const float*)d_in[14];
    const float* W_atom_out = (const float*)d_in[15];
    const float* b_atom_out = (const float*)d_in[16];
    const float* W_read     = (const float*)d_in[17];
    const float* b_read     = (const float*)d_in[18];
    const float* g_e        = (const float*)d_in[19];
    const float* be_e       = (const float*)d_in[20];
    const float* g_a        = (const float*)d_in[21];
    const float* be_a       = (const float*)d_in[22];

    const int N  = in_sizes[0];
    const int E  = in_sizes[2] / 2;
    const int E2 = 2 * E;

    float* out       = (float*)d_out;
    float* out_hatom = out + NUM_GRAPHS * NUM_TASKS;
    float* out_he    = out_hatom + (size_t)N * H;

    float  *h_all, *hpre, *m_in, *hgraph, *rzbias, *nbias;
    __half *a16, *aao, *acat, *Gn, *wain, *wmsg, *wao, *brz, *bgin, *bghn;
    cudaGetSymbolAddress((void**)&h_all,  g_h_all);
    cudaGetSymbolAddress((void**)&hpre,   g_hpre);
    cudaGetSymbolAddress((void**)&m_in,   g_m_in);
    cudaGetSymbolAddress((void**)&hgraph, g_hgraph);
    cudaGetSymbolAddress((void**)&rzbias, g_rzbias);
    cudaGetSymbolAddress((void**)&nbias,  g_nbias);
    cudaGetSymbolAddress((void**)&a16,    g_a16);
    cudaGetSymbolAddress((void**)&aao,    g_aao);
    cudaGetSymbolAddress((void**)&acat,   g_acat);
    cudaGetSymbolAddress((void**)&Gn,     g_Gn);
    cudaGetSymbolAddress((void**)&wain,   g_wain);
    cudaGetSymbolAddress((void**)&wmsg,   g_wmsg);
    cudaGetSymbolAddress((void**)&wao,    g_wao);
    cudaGetSymbolAddress((void**)&brz,    g_brz);
    cudaGetSymbolAddress((void**)&bgin,   g_bgin);
    cudaGetSymbolAddress((void**)&bghn,   g_bghn);

    cudaFuncSetAttribute(hgemm_kernel<0>, cudaFuncAttributeMaxDynamicSharedMemorySize, GEMM_SMEM);
    cudaFuncSetAttribute(hgemm_kernel<2>, cudaFuncAttributeMaxDynamicSharedMemorySize, GEMM_SMEM);
    cudaFuncSetAttribute(hgemm_kernel<3>, cudaFuncAttributeMaxDynamicSharedMemorySize, GEMM_SMEM);
    cudaFuncSetAttribute(msg_gemm_kernel, cudaFuncAttributeMaxDynamicSharedMemorySize, MSG_SMEM);

    const size_t minN4 = (size_t)N * H / 4;

    // prep
    zero_kernel<<<1024, 256>>>((float4*)m_in, minN4);
    build_a16_kernel<<<4096, 256>>>(x_z, x_atom, embed_z, a16, aao, N);
    build_wain16<<<cdiv(AIN_K * H, 256), 256>>>(W_atom_in, wain);
    build_wmsg16<<<cdiv(H * H, 256), 256>>>(W_msg, wmsg);
    build_wao16<<<cdiv(AO_K * H, 256), 256>>>(W_atom_out, wao);
    build_brz_kernel<<<cdiv(ACAT_W * RZ_N, 256), 256>>>(W_ih, W_hh, b_ih, b_hh, brz, rzbias);
    build_bgin_kernel<<<cdiv(H * H, 256), 256>>>(W_ih, b_ih, bgin, nbias);
    build_bghn_kernel<<<cdiv(H * H, 256), 256>>>(W_hh, b_hh, bghn, nbias);

    // h_all = a_all @ W_atom_in + b
    hgemm_kernel<0><<<dim3(cdiv(H, GBN), cdiv(N, GBM)), 256, GEMM_SMEM>>>(
        a16, wain, b_atom_in, nullptr, h_all, nullptr, nullptr, nullptr,
        N, H, AIN_K, AIN_K, H, 0);
    // h_e init (bond fused) -> acat fp16 + scatter
    edge_init_kernel<<<cdiv(E2, 8), 256>>>(ei, h_all, edge_attr, W_bond_in, b_bond_in,
                                           g_e, be_e, acat, m_in, E);

    for (int depth = 0; depth < DEPTH; depth++) {
        // fused gather + msg GEMM: h_new = relu(h_e + (m_in[src]-h_e[rev]) @ W_msg) -> acat cols 0..255
        msg_gemm_kernel<<<dim3(cdiv(H, GBN), cdiv(E2, GBM)), 256, MSG_SMEM>>>(
            m_in, wmsg, ei, acat, E);
        // gin / ghn -> Gn blocked [gin | ghn]
        hgemm_kernel<2><<<dim3(cdiv(H, GBN), cdiv(E2, GBM)), 256, GEMM_SMEM>>>(
            acat, bgin, nullptr, nullptr, nullptr, Gn, nullptr, nullptr,
            E2, H, H, ACAT_W, RZ_N, 0);
        hgemm_kernel<2><<<dim3(cdiv(H, GBN), cdiv(E2, GBM)), 256, GEMM_SMEM>>>(
            acat + H, bghn, nullptr, nullptr, nullptr, Gn, nullptr, nullptr,
            E2, H, H, ACAT_W, RZ_N, 256);
        zero_kernel<<<1024, 256>>>((float4*)m_in, minN4);
        // rz GEMM + fused GRU -> hpre  (hp read from acat fp16)
        hgemm_kernel<3><<<dim3(cdiv(RZ_N, GBN), cdiv(E2, GBM)), 256, GEMM_SMEM>>>(
            acat, brz, rzbias, nbias, hpre, nullptr, Gn, acat,
            E2, RZ_N, ACAT_W, ACAT_W, RZ_N, 0);
        // LN + scatter; intermediate depths -> acat fp16, last depth -> fp32 out_he
        if (depth < DEPTH - 1)
            ln_scatter_kernel<true><<<cdiv(E2, 8), 256>>>(hpre, ei, g_e, be_e, nullptr, acat, m_in, E);
        else
            ln_scatter_kernel<false><<<cdiv(E2, 8), 256>>>(hpre, ei, g_e, be_e, out_he, nullptr, m_in, E);
    }

    // m_to_atom accumulated by last ln_scatter
    convert_min_kernel<<<2048, 256>>>(m_in, aao, N);

    // h_atom = LN(relu([a_all | m_to_atom] @ W_atom_out + b))
    hgemm_kernel<0><<<dim3(cdiv(H, GBN), cdiv(N, GBM)), 256, GEMM_SMEM>>>(
        aao, wao, b_atom_out, nullptr, h_all, nullptr, nullptr, nullptr,
        N, H, AO_K, AO_K, H, 0);
    zero_kernel<<<64, 256>>>((float4*)hgraph, (size_t)NUM_GRAPHS * H / 4);
    relu_ln_graph_kernel<<<cdiv(N, 8), 256>>>(h_all, batch, g_a, be_a, out_hatom, hgraph, N);
    readout_kernel<<<NUM_GRAPHS, 32>>>(hgraph, W_read, b_read, out);
}

// round 16
// speedup vs baseline: 4.3329x; 1.0159x over previous
#include <cuda_runtime.h>
#include <cuda_fp16.h>
#include <stdint.h>
#include <cstdint>
#include <math.h>

// ---------------- problem constants ----------------
#define MAX_N 50000
#define MAX_E 200000
#define H 256
#define ATOM_IN 133
#define BOND_IN 14
#define NUM_TASKS 12
#define NUM_GRAPHS 256
#define DEPTH 3
#define EPS 1e-5f

#define AIN_K 192
#define AO_K  448
#define ACAT_W 512
#define RZ_N  512

// ---------------- scratch ----------------
__device__ float  g_h_all[(size_t)MAX_N * H];
__device__ __half g_hpre [(size_t)(2*MAX_E) * H];        // GRU out pre-LN (fp16)
__device__ float  g_m_in [(size_t)MAX_N * H];
__device__ float  g_hgraph[NUM_GRAPHS * H];
__device__ float  g_rzbias[RZ_N];
__device__ float  g_nbias [RZ_N];
__device__ __half g_a16  [(size_t)MAX_N * AIN_K];
__device__ __half g_aao  [(size_t)MAX_N * AO_K];
__device__ __half g_acat [(size_t)(2*MAX_E) * ACAT_W];   // [h_new | h_e] fp16
__device__ __half g_Gn   [(size_t)(2*MAX_E) * RZ_N];     // [gin(256) | ghn(256)] blocked
__device__ __half g_wain [AIN_K * H];
__device__ __half g_wmsg [H * H];
__device__ __half g_wao  [AO_K * H];
__device__ __half g_brz  [ACAT_W * RZ_N];
__device__ __half g_bgin [H * H];
__device__ __half g_bghn [H * H];

static inline int cdiv(int a, int b) { return (a + b - 1) / b; }

#define CP_ASYNC16(dst, src) asm volatile("cp.async.cg.shared.global [%0], [%1], 16;\n" :: "r"(dst), "l"(src))
#define CP_COMMIT()          asm volatile("cp.async.commit_group;\n")
#define CP_WAIT2()           asm volatile("cp.async.wait_group 2;\n")

__device__ __forceinline__ void red_add_v4(float* p, float a, float b, float c, float d) {
    asm volatile("red.global.v4.f32.add [%0], {%1,%2,%3,%4};"
                 :: "l"(p), "f"(a), "f"(b), "f"(c), "f"(d) : "memory");
}

// ---------------- mma.sync HGEMM core pieces ----------------
#define GBM 128
#define GBN 128
#define GBK 32
#define SPAD 8
#define STAGES 4
#define A_STG (GBM * (GBK + SPAD))
#define B_STG (GBK * (GBN + SPAD))
#define GEMM_SMEM (STAGES * (A_STG + B_STG) * 2)              // 75776
#define MSG_SMEM  ((2 * A_STG + STAGES * B_STG) * 2)          // 55296

__device__ __forceinline__ void ldsm_x4(uint32_t& r0, uint32_t& r1, uint32_t& r2, uint32_t& r3, uint32_t addr) {
    asm volatile("ldmatrix.sync.aligned.m8n8.x4.shared.b16 {%0,%1,%2,%3}, [%4];\n"
                 : "=r"(r0), "=r"(r1), "=r"(r2), "=r"(r3) : "r"(addr));
}
__device__ __forceinline__ void ldsm_x4t(uint32_t& r0, uint32_t& r1, uint32_t& r2, uint32_t& r3, uint32_t addr) {
    asm volatile("ldmatrix.sync.aligned.m8n8.x4.trans.shared.b16 {%0,%1,%2,%3}, [%4];\n"
                 : "=r"(r0), "=r"(r1), "=r"(r2), "=r"(r3) : "r"(addr));
}
__device__ __forceinline__ void mma_16816(float* d, const uint32_t* a, const uint32_t* b) {
    asm volatile("mma.sync.aligned.m16n8k16.row.col.f32.f16.f16.f32 "
                 "{%0,%1,%2,%3}, {%4,%5,%6,%7}, {%8,%9}, {%0,%1,%2,%3};\n"
                 : "+f"(d[0]), "+f"(d[1]), "+f"(d[2]), "+f"(d[3])
                 : "r"(a[0]), "r"(a[1]), "r"(a[2]), "r"(a[3]), "r"(b[0]), "r"(b[1]));
}

__device__ __forceinline__ void ldsm_a(const __half* as, int ks, int lane, int wm, uint32_t af[2][4]) {
    const int k0 = ks * 16;
    #pragma unroll
    for (int mi = 0; mi < 2; mi++) {
        int row = wm * 32 + mi * 16 + (lane & 15);
        int col = k0 + ((lane >> 4) << 3);
        uint32_t ad = (uint32_t)__cvta_generic_to_shared(as + row * (GBK + SPAD) + col);
        ldsm_x4(af[mi][0], af[mi][1], af[mi][2], af[mi][3], ad);
    }
}
__device__ __forceinline__ void ldsm_b(const __half* bs, int ks, int lane, int wn, uint32_t bf[8][2]) {
    const int k0 = ks * 16;
    #pragma unroll
    for (int nq = 0; nq < 4; nq++) {
        int row = k0 + (lane & 15);
        int col = wn * 64 + nq * 16 + ((lane >> 4) << 3);
        uint32_t bd = (uint32_t)__cvta_generic_to_shared(bs + row * (GBN + SPAD) + col);
        ldsm_x4t(bf[nq*2][0], bf[nq*2][1], bf[nq*2+1][0], bf[nq*2+1][1], bd);
    }
}

// one 32-K tile: prefetch all fragments, then 32 HMMA
__device__ __forceinline__ void tile_mma(const __half* as, const __half* bs,
                                         int lane, int wm, int wn, float acc[2][8][4])
{
    uint32_t af[2][2][4];
    uint32_t bf[2][8][2];
    ldsm_a(as, 0, lane, wm, af[0]);
    ldsm_b(bs, 0, lane, wn, bf[0]);
    ldsm_a(as, 1, lane, wm, af[1]);
    ldsm_b(bs, 1, lane, wn, bf[1]);
    #pragma unroll
    for (int ks = 0; ks < 2; ks++)
        #pragma unroll
        for (int mi = 0; mi < 2; mi++)
            #pragma unroll
            for (int nj = 0; nj < 8; nj++)
                mma_16816(acc[mi][nj], af[ks][mi], bf[ks][nj]);
}

__device__ __forceinline__ float sigmoidf_(float x) { return 1.f / (1.f + expf(-x)); }

// ---------------- generic HGEMM (EPI 0/2/3) ----------------
// EPI 0: outF = acc + bias[col]
// EPI 2: outH[row*ldOut + colOff + col] = half2(v0,v1)   (gin/ghn -> Gn blocked)
// EPI 3: fused GRU: r,z = acc pair; gin,ghn from auxH (Gn); hp from auxH2 (acat) -> outH[row*H+j] fp16
template<int EPI>
__global__ __launch_bounds__(256, 2) void hgemm_kernel(
    const __half* __restrict__ A, const __half* __restrict__ B,
    const float* __restrict__ bias, const float* __restrict__ bias2,
    float* __restrict__ outF, __half* __restrict__ outH,
    const __half* __restrict__ auxH, const __half* __restrict__ auxH2,
    int M, int N, int K, int ldA, int ldOut, int colOff)
{
    extern __shared__ __align__(16) __half sm[];
    __half* smA = sm;
    __half* smB = sm + STAGES * A_STG;

    const int tid  = threadIdx.x;
    const int lane = tid & 31;
    const int warp = tid >> 5;
    const int wm   = warp & 3;
    const int wn   = warp >> 2;
    const int bm   = blockIdx.y * GBM;
    const int bn   = blockIdx.x * GBN;

    float acc[2][8][4];
    #pragma unroll
    for (int i = 0; i < 2; i++)
        #pragma unroll
        for (int j = 0; j < 8; j++)
            #pragma unroll
            for (int k = 0; k < 4; k++) acc[i][j][k] = 0.f;

    const int ar = tid >> 2;
    const int ac = (tid & 3) << 3;
    const int br = tid >> 4;
    const int bc = (tid & 15) << 3;
    const int KT = K / GBK;

    auto load_tile = [&](int kt, int s) {
        const int k0 = kt * GBK;
        __half* as = smA + s * A_STG;
        __half* bs = smB + s * B_STG;
        #pragma unroll
        for (int i = 0; i < 2; i++) {
            int r  = ar + i * 64;
            int gr = bm + r; if (gr >= M) gr = M - 1;
            const __half* src = A + (size_t)gr * ldA + k0 + ac;
            uint32_t dst = (uint32_t)__cvta_generic_to_shared(as + r * (GBK + SPAD) + ac);
            CP_ASYNC16(dst, src);
        }
        #pragma unroll
        for (int i = 0; i < 2; i++) {
            int r = br + i * 16;
            const __half* src = B + (size_t)(k0 + r) * N + bn + bc;
            uint32_t dst = (uint32_t)__cvta_generic_to_shared(bs + r * (GBN + SPAD) + bc);
            CP_ASYNC16(dst, src);
        }
    };

    #pragma unroll
    for (int p = 0; p < STAGES - 1; p++) {
        if (p < KT) load_tile(p, p);
        CP_COMMIT();
    }

    for (int kt = 0; kt < KT; kt++) {
        CP_WAIT2();
        __syncthreads();
        const int s = kt % STAGES;
        if (kt + STAGES - 1 < KT) load_tile(kt + STAGES - 1, (kt + STAGES - 1) % STAGES);
        CP_COMMIT();
        tile_mma(smA + s * A_STG, smB + s * B_STG, lane, wm, wn, acc);
    }

    const int r0 = bm + wm * 32 + (lane >> 2);
    const int c0 = bn + wn * 64 + ((lane & 3) << 1);
    #pragma unroll
    for (int mi = 0; mi < 2; mi++) {
        #pragma unroll
        for (int nj = 0; nj < 8; nj++) {
            const int col = c0 + nj * 8;
            #pragma unroll
            for (int hh = 0; hh < 2; hh++) {
                const int row = r0 + mi * 16 + hh * 8;
                if (row >= M) continue;
                float v0 = acc[mi][nj][hh * 2 + 0];
                float v1 = acc[mi][nj][hh * 2 + 1];
                if (EPI == 0) {
                    outF[(size_t)row * ldOut + col]     = v0 + bias[col];
                    outF[(size_t)row * ldOut + col + 1] = v1 + bias[col + 1];
                } else if (EPI == 2) {
                    __half2 hv = __floats2half2_rn(v0, v1);
                    *(__half2*)(outH + (size_t)row * ldOut + colOff + col) = hv;
                } else {
                    float r = sigmoidf_(v0 + bias[col]);
                    float z = sigmoidf_(v1 + bias[col + 1]);
                    int j = col >> 1;
                    float gin = __half2float(auxH[(size_t)row * ldOut + j])       + bias2[j];
                    float ghn = __half2float(auxH[(size_t)row * ldOut + 256 + j]) + bias2[256 + j];
                    float n = tanhf(gin + r * ghn);
                    float hp = __half2float(auxH2[(size_t)row * ACAT_W + H + j]);
                    outH[(size_t)row * H + j] = __float2half((1.f - z) * n + z * hp);
                }
            }
        }
    }
}

// ---------------- fused gather + msg GEMM ----------------
__global__ __launch_bounds__(256, 2) void msg_gemm_kernel(
    const float* __restrict__ m_in, const __half* __restrict__ Bw,
    const int* __restrict__ ei, __half* __restrict__ acat, int E)
{
    extern __shared__ __align__(16) __half sm[];
    __half* smA = sm;                    // 2 stages
    __half* smB = sm + 2 * A_STG;        // STAGES stages
    const int E2 = 2 * E;

    const int tid  = threadIdx.x;
    const int lane = tid & 31;
    const int warp = tid >> 5;
    const int wm   = warp & 3;
    const int wn   = warp >> 2;
    const int bm   = blockIdx.y * GBM;
    const int bn   = blockIdx.x * GBN;

    const int pr = tid >> 1;
    const int pc = (tid & 1) * 16;
    int dd = bm + pr; if (dd >= E2) dd = E2 - 1;
    const int src = ei[dd];
    const int rv  = (dd < E) ? dd + E : dd - E;
    const float*  mrow  = m_in + (size_t)src * H;
    const __half* herow = acat + (size_t)rv * ACAT_W + H;

    const int br = tid >> 4;
    const int bc = (tid & 15) << 3;
    const int KT = H / GBK;   // 8

    float4 am[4]; uint4 ah[2];
    auto loadA = [&](int kt) {
        const int c0 = kt * GBK + pc;
        am[0] = *(const float4*)(mrow + c0);
        am[1] = *(const float4*)(mrow + c0 + 4);
        am[2] = *(const float4*)(mrow + c0 + 8);
        am[3] = *(const float4*)(mrow + c0 + 12);
        ah[0] = *(const uint4*)(herow + c0);
        ah[1] = *(const uint4*)(herow + c0 + 8);
    };
    auto stsA = [&](int s) {
        __half hx[16];
        const __half* hp = (const __half*)ah;
        #pragma unroll
        for (int i = 0; i < 4; i++) {
            const float* mf = (const float*)&am[i];
            #pragma unroll
            for (int j = 0; j < 4; j++)
                hx[i*4 + j] = __float2half(mf[j] - __half2float(hp[i*4 + j]));
        }
        __half* dst = smA + s * A_STG + pr * (GBK + SPAD) + pc;
        *(uint4*)dst       = *(const uint4*)hx;
        *(uint4*)(dst + 8) = *(const uint4*)(hx + 8);
    };
    auto loadB = [&](int kt, int s) {
        const int k0 = kt * GBK;
        __half* bs = smB + s * B_STG;
        #pragma unroll
        for (int i = 0; i < 2; i++) {
            int r = br + i * 16;
            const __half* srcp = Bw + (size_t)(k0 + r) * H + bn + bc;
            uint32_t dst = (uint32_t)__cvta_generic_to_shared(bs + r * (GBN + SPAD) + bc);
            CP_ASYNC16(dst, srcp);
        }
    };

    float acc[2][8][4];
    #pragma unroll
    for (int i = 0; i < 2; i++)
        #pragma unroll
        for (int j = 0; j < 8; j++)
            #pragma unroll
            for (int k = 0; k < 4; k++) acc[i][j][k] = 0.f;

    loadA(0);
    #pragma unroll
    for (int p = 0; p < STAGES - 1; p++) {
        if (p < KT) loadB(p, p);
        CP_COMMIT();
    }

    for (int kt = 0; kt < KT; kt++) {
        stsA(kt & 1);
        if (kt + 1 < KT) loadA(kt + 1);
        CP_WAIT2();
        __syncthreads();
        if (kt + STAGES - 1 < KT) loadB(kt + STAGES - 1, (kt + STAGES - 1) % STAGES);
        CP_COMMIT();
        tile_mma(smA + (kt & 1) * A_STG, smB + (kt % STAGES) * B_STG, lane, wm, wn, acc);
    }

    const int r0 = bm + wm * 32 + (lane >> 2);
    const int c0 = bn + wn * 64 + ((lane & 3) << 1);
    #pragma unroll
    for (int mi = 0; mi < 2; mi++) {
        #pragma unroll
        for (int nj = 0; nj < 8; nj++) {
            const int col = c0 + nj * 8;
            #pragma unroll
            for (int hh = 0; hh < 2; hh++) {
                const int row = r0 + mi * 16 + hh * 8;
                if (row >= E2) continue;
                __half2 he2 = *(const __half2*)(acat + (size_t)row * ACAT_W + H + col);
                float v0 = fmaxf(acc[mi][nj][hh*2+0] + __low2float(he2),  0.f);
                float v1 = fmaxf(acc[mi][nj][hh*2+1] + __high2float(he2), 0.f);
                *(__half2*)(acat + (size_t)row * ACAT_W + col) = __floats2half2_rn(v0, v1);
            }
        }
    }
}

// ---------------- warp-per-row helpers ----------------

__device__ __forceinline__ void warp_ln_8(float* v, int lane,
                                          const float* __restrict__ g,
                                          const float* __restrict__ be,
                                          float* y)
{
    float sum = 0.f, sq = 0.f;
    #pragma unroll
    for (int i = 0; i < 8; i++) { sum += v[i]; sq += v[i] * v[i]; }
    #pragma unroll
    for (int o = 16; o > 0; o >>= 1) {
        sum += __shfl_xor_sync(0xffffffffu, sum, o);
        sq  += __shfl_xor_sync(0xffffffffu, sq,  o);
    }
    float mu = sum * (1.f / H);
    float var = sq * (1.f / H) - mu * mu;
    float rs = rsqrtf(var + EPS);
    const float4* g4  = (const float4*)(g  + lane * 8);
    const float4* be4 = (const float4*)(be + lane * 8);
    float4 ga = g4[0], gb = g4[1], ba = be4[0], bb = be4[1];
    y[0] = (v[0] - mu) * rs * ga.x + ba.x;
    y[1] = (v[1] - mu) * rs * ga.y + ba.y;
    y[2] = (v[2] - mu) * rs * ga.z + ba.z;
    y[3] = (v[3] - mu) * rs * ga.w + ba.w;
    y[4] = (v[4] - mu) * rs * gb.x + bb.x;
    y[5] = (v[5] - mu) * rs * gb.y + bb.y;
    y[6] = (v[6] - mu) * rs * gb.z + bb.z;
    y[7] = (v[7] - mu) * rs * gb.w + bb.w;
}

__device__ __forceinline__ void store_half8(__half* p, const float* y) {
    __half2 h0 = __floats2half2_rn(y[0], y[1]);
    __half2 h1 = __floats2half2_rn(y[2], y[3]);
    __half2 h2 = __floats2half2_rn(y[4], y[5]);
    __half2 h3 = __floats2half2_rn(y[6], y[7]);
    uint4 u;
    u.x = *(uint32_t*)&h0; u.y = *(uint32_t*)&h1;
    u.z = *(uint32_t*)&h2; u.w = *(uint32_t*)&h3;
    *(uint4*)p = u;
}

// h_e init: LN(relu(h_all[src] + edge_attr@W_bond + b)) -> acat fp16 + scatter
__global__ void edge_init_kernel(const int* __restrict__ ei, const float* __restrict__ h_all,
                                 const float* __restrict__ eattr, const float* __restrict__ Wb,
                                 const float* __restrict__ bb_,
                                 const float* __restrict__ g, const float* __restrict__ be,
                                 __half* __restrict__ acat, float* __restrict__ m_in, int E)
{
    int d = blockIdx.x * 8 + (threadIdx.x >> 5);
    if (d >= 2 * E) return;
    int lane = threadIdx.x & 31;
    int src = ei[d];
    int e = (d < E) ? d : d - E;

    float ew[14];
    const float* er = eattr + (size_t)e * BOND_IN;
    #pragma unroll
    for (int k = 0; k < BOND_IN; k++) ew[k] = er[k];
    float ev[8];
    {
        const float4* b4 = (const float4*)(bb_ + lane * 8);
        float4 e0 = b4[0], e1 = b4[1];
        ev[0]=e0.x; ev[1]=e0.y; ev[2]=e0.z; ev[3]=e0.w;
        ev[4]=e1.x; ev[5]=e1.y; ev[6]=e1.z; ev[7]=e1.w;
    }
    #pragma unroll
    for (int k = 0; k < BOND_IN; k++) {
        const float4* w4 = (const float4*)(Wb + k * H + lane * 8);
        float4 w0 = w4[0], w1 = w4[1];
        ev[0] += ew[k]*w0.x; ev[1] += ew[k]*w0.y; ev[2] += ew[k]*w0.z; ev[3] += ew[k]*w0.w;
        ev[4] += ew[k]*w1.x; ev[5] += ew[k]*w1.y; ev[6] += ew[k]*w1.z; ev[7] += ew[k]*w1.w;
    }

    const float4* ha = (const float4*)(h_all + (size_t)src * H + lane * 8);
    float4 a0 = ha[0], a1 = ha[1];
    float v[8] = {
        fmaxf(a0.x + ev[0], 0.f), fmaxf(a0.y + ev[1], 0.f),
        fmaxf(a0.z + ev[2], 0.f), fmaxf(a0.w + ev[3], 0.f),
        fmaxf(a1.x + ev[4], 0.f), fmaxf(a1.y + ev[5], 0.f),
        fmaxf(a1.z + ev[6], 0.f), fmaxf(a1.w + ev[7], 0.f) };
    float y[8];
    warp_ln_8(v, lane, g, be, y);
    store_half8(acat + (size_t)d * ACAT_W + H + lane * 8, y);
    int dst = (d < E) ? ei[E + d] : ei[d - E];
    float* mb = m_in + (size_t)dst * H + lane * 8;
    red_add_v4(mb,     y[0], y[1], y[2], y[3]);
    red_add_v4(mb + 4, y[4], y[5], y[6], y[7]);
}

// LN of fp16 GRU output + scatter; W16: write acat fp16; !W16 (last depth): write fp32 out
template<bool W16>
__global__ void ln_scatter_kernel(const __half* __restrict__ x, const int* __restrict__ ei,
                                  const float* __restrict__ g, const float* __restrict__ be,
                                  float* __restrict__ outp, __half* __restrict__ acat,
                                  float* __restrict__ m_in, int E)
{
    int d = blockIdx.x * 8 + (threadIdx.x >> 5);
    if (d >= 2 * E) return;
    int lane = threadIdx.x & 31;
    uint4 u = *(const uint4*)(x + (size_t)d * H + lane * 8);
    const __half* hx = (const __half*)&u;
    float v[8];
    #pragma unroll
    for (int i = 0; i < 8; i++) v[i] = __half2float(hx[i]);
    float y[8];
    warp_ln_8(v, lane, g, be, y);
    if (W16) {
        store_half8(acat + (size_t)d * ACAT_W + H + lane * 8, y);
    } else {
        float4* o4 = (float4*)(outp + (size_t)d * H + lane * 8);
        o4[0] = make_float4(y[0], y[1], y[2], y[3]);
        o4[1] = make_float4(y[4], y[5], y[6], y[7]);
    }
    int dst = (d < E) ? ei[E + d] : ei[d - E];
    float* mb = m_in + (size_t)dst * H + lane * 8;
    red_add_v4(mb,     y[0], y[1], y[2], y[3]);
    red_add_v4(mb + 4, y[4], y[5], y[6], y[7]);
}

// h_atom = LN(relu(x)) -> out; vector atomic into hgraph[batch[n]]
__global__ void relu_ln_graph_kernel(const float* __restrict__ x, const int* __restrict__ batch,
                                     const float* __restrict__ g, const float* __restrict__ be,
                                     float* __restrict__ out, float* __restrict__ hgraph, int N)
{
    int n = blockIdx.x * 8 + (threadIdx.x >> 5);
    if (n >= N) return;
    int lane = threadIdx.x & 31;
    const float4* xr = (const float4*)(x + (size_t)n * H + lane * 8);
    float4 x0 = xr[0], x1 = xr[1];
    float v[8] = {fmaxf(x0.x, 0.f), fmaxf(x0.y, 0.f), fmaxf(x0.z, 0.f), fmaxf(x0.w, 0.f),
                  fmaxf(x1.x, 0.f), fmaxf(x1.y, 0.f), fmaxf(x1.z, 0.f), fmaxf(x1.w, 0.f)};
    float y[8];
    warp_ln_8(v, lane, g, be, y);
    float4* o4 = (float4*)(out + (size_t)n * H + lane * 8);
    o4[0] = make_float4(y[0], y[1], y[2], y[3]);
    o4[1] = make_float4(y[4], y[5], y[6], y[7]);
    float* hb = hgraph + (size_t)batch[n] * H + lane * 8;
    red_add_v4(hb,     y[0], y[1], y[2], y[3]);
    red_add_v4(hb + 4, y[4], y[5], y[6], y[7]);
}

// ---------------- single merged prep kernel ----------------
// zero m_in; build a16/aao; fp16 weights (wain/wmsg/wao); brz/rzbias; bgin/bghn/nbias
__global__ void prep_kernel(
    const int* __restrict__ xz, const float* __restrict__ xa, const float* __restrict__ emb,
    const float* __restrict__ W_ain, const float* __restrict__ W_m, const float* __restrict__ W_ao,
    const float* __restrict__ Wih, const float* __restrict__ Whh,
    const float* __restrict__ bih, const float* __restrict__ bhh,
    __half* __restrict__ a16, __half* __restrict__ aao,
    __half* __restrict__ wain, __half* __restrict__ wmsg, __half* __restrict__ wao,
    __half* __restrict__ Brz, __half* __restrict__ Bgin, __half* __restrict__ Bghn,
    float* __restrict__ rzb, float* __restrict__ nb,
    float4* __restrict__ m_in4, int N)
{
    const size_t stride = (size_t)gridDim.x * blockDim.x;
    const size_t t0 = (size_t)blockIdx.x * blockDim.x + threadIdx.x;

    for (size_t i = t0; i < (size_t)N * H / 4; i += stride)
        m_in4[i] = make_float4(0.f, 0.f, 0.f, 0.f);

    for (size_t idx = t0; idx < (size_t)N * AO_K; idx += stride) {
        int n = (int)(idx / AO_K);
        int c = (int)(idx % AO_K);
        if (c < AIN_K) {
            float v = (c < 32) ? emb[xz[n] * 32 + c]
                    : (c < 165) ? xa[(size_t)n * ATOM_IN + (c - 32)] : 0.f;
            __half h = __float2half(v);
            a16[(size_t)n * AIN_K + c] = h;
            if (c < 165) aao[(size_t)n * AO_K + c] = h;
        } else if (c >= 421) {
            aao[idx] = __float2half(0.f);
        }
    }

    for (size_t idx = t0; idx < (size_t)AIN_K * H; idx += stride) {
        int k = (int)(idx / H), c = (int)(idx % H);
        wain[idx] = __float2half(k < 165 ? W_ain[k * H + c] : 0.f);
    }
    for (size_t idx = t0; idx < (size_t)H * H; idx += stride)
        wmsg[idx] = __float2half(W_m[idx]);
    for (size_t idx = t0; idx < (size_t)AO_K * H; idx += stride) {
        int k = (int)(idx / H), c = (int)(idx % H);
        wao[idx] = __float2half(k < 421 ? W_ao[k * H + c] : 0.f);
    }
    for (size_t idx = t0; idx < (size_t)ACAT_W * RZ_N; idx += stride) {
        int k = (int)(idx / RZ_N), c = (int)(idx % RZ_N);
        int j = c >> 1;
        int gateRow = (c & 1) ? (256 + j) : j;
        float v = (k < 256) ? Wih[gateRow * H + k] : Whh[gateRow * H + (k - 256)];
        Brz[idx] = __float2half(v);
        if (k == 0) rzb[c] = bih[gateRow] + bhh[gateRow];
    }
    for (size_t idx = t0; idx < (size_t)H * H; idx += stride) {
        int k = (int)(idx / H), j = (int)(idx % H);
        Bgin[idx] = __float2half(Wih[(512 + j) * H + k]);
        Bghn[idx] = __float2half(Whh[(512 + j) * H + k]);
        if (k == 0) { nb[j] = bih[512 + j]; nb[256 + j] = bhh[512 + j]; }
    }
}

__global__ void zero_kernel(float4* __restrict__ p, size_t n4) {
    size_t i = (size_t)blockIdx.x * blockDim.x + threadIdx.x;
    for (; i < n4; i += (size_t)gridDim.x * blockDim.x)
        p[i] = make_float4(0.f, 0.f, 0.f, 0.f);
}

__global__ void convert_min_kernel(const float* __restrict__ m_in, __half* __restrict__ aao, int N)
{
    size_t idx = (size_t)blockIdx.x * blockDim.x + threadIdx.x;
    size_t total = (size_t)N * H;
    for (; idx < total; idx += (size_t)gridDim.x * blockDim.x) {
        int n = (int)(idx / H), c = (int)(idx % H);
        aao[(size_t)n * AO_K + 165 + c] = __float2half(m_in[idx]);
    }
}

__global__ void readout_kernel(const float* __restrict__ hgraph, const float* __restrict__ Wr,
                               const float* __restrict__ br, float* __restrict__ out)
{
    int gph = blockIdx.x, t = threadIdx.x;
    if (t < NUM_TASKS) {
        float s = br[t];
        const float* row = hgraph + gph * H;
        #pragma unroll 8
        for (int k = 0; k < H; k++) s += row[k] * Wr[k * NUM_TASKS + t];
        out[gph * NUM_TASKS + t] = s;
    }
}

// ---------------- host launcher ----------------
extern "C" void kernel_launch(void* const* d_in, const int* in_sizes, int n_in,
                              void* d_out, int out_size)
{
    const int*   x_z        = (const int*)  d_in[0];
    const float* x_atom     = (const float*)d_in[1];
    const int*   ei         = (const int*)  d_in[2];
    const float* edge_attr  = (const float*)d_in[3];
    const int*   batch      = (const int*)  d_in[4];
    const float* embed_z    = (const float*)d_in[5];
    const float* W_atom_in  = (const float*)d_in[6];
    const float* b_atom_in  = (const float*)d_in[7];
    const float* W_bond_in  = (const float*)d_in[8];
    const float* b_bond_in  = (const float*)d_in[9];
    const float* W_msg      = (const float*)d_in[10];
    const float* W_ih       = (const float*)d_in[11];
    const float* b_ih       = (const float*)d_in[12];
    const float* W_hh       = (const float*)d_in[13];
    const float* b_hh       = (const float*)d_in[14];
    const float* W_atom_out = (const float*)d_in[15];
    const float* b_atom_out = (const float*)d_in[16];
    const float* W_read     = (const float*)d_in[17];
    const float* b_read     = (const float*)d_in[18];
    const float* g_e        = (const float*)d_in[19];
    const float* be_e       = (const float*)d_in[20];
    const float* g_a        = (const float*)d_in[21];
    const float* be_a       = (const float*)d_in[22];

    const int N  = in_sizes[0];
    const int E  = in_sizes[2] / 2;
    const int E2 = 2 * E;

    float* out       = (float*)d_out;
    float* out_hatom = out + NUM_GRAPHS * NUM_TASKS;
    float* out_he    = out_hatom + (size_t)N * H;

    float  *h_all, *m_in, *hgraph, *rzbias, *nbias;
    __half *hpre, *a16, *aao, *acat, *Gn, *wain, *wmsg, *wao, *brz, *bgin, *bghn;
    cudaGetSymbolAddress((void**)&h_all,  g_h_all);
    cudaGetSymbolAddress((void**)&hpre,   g_hpre);
    cudaGetSymbolAddress((void**)&m_in,   g_m_in);
    cudaGetSymbolAddress((void**)&hgraph, g_hgraph);
    cudaGetSymbolAddress((void**)&rzbias, g_rzbias);
    cudaGetSymbolAddress((void**)&nbias,  g_nbias);
    cudaGetSymbolAddress((void**)&a16,    g_a16);
    cudaGetSymbolAddress((void**)&aao,    g_aao);
    cudaGetSymbolAddress((void**)&acat,   g_acat);
    cudaGetSymbolAddress((void**)&Gn,     g_Gn);
    cudaGetSymbolAddress((void**)&wain,   g_wain);
    cudaGetSymbolAddress((void**)&wmsg,   g_wmsg);
    cudaGetSymbolAddress((void**)&wao,    g_wao);
    cudaGetSymbolAddress((void**)&brz,    g_brz);
    cudaGetSymbolAddress((void**)&bgin,   g_bgin);
    cudaGetSymbolAddress((void**)&bghn,   g_bghn);

    cudaFuncSetAttribute(hgemm_kernel<0>, cudaFuncAttributeMaxDynamicSharedMemorySize, GEMM_SMEM);
    cudaFuncSetAttribute(hgemm_kernel<2>, cudaFuncAttributeMaxDynamicSharedMemorySize, GEMM_SMEM);
    cudaFuncSetAttribute(hgemm_kernel<3>, cudaFuncAttributeMaxDynamicSharedMemorySize, GEMM_SMEM);
    cudaFuncSetAttribute(msg_gemm_kernel, cudaFuncAttributeMaxDynamicSharedMemorySize, MSG_SMEM);

    const size_t minN4 = (size_t)N * H / 4;

    // single merged prep launch
    prep_kernel<<<2048, 256>>>(x_z, x_atom, embed_z,
                               W_atom_in, W_msg, W_atom_out,
                               W_ih, W_hh, b_ih, b_hh,
                               a16, aao, wain, wmsg, wao,
                               brz, bgin, bghn, rzbias, nbias,
                               (float4*)m_in, N);

    // h_all = a_all @ W_atom_in + b
    hgemm_kernel<0><<<dim3(cdiv(H, GBN), cdiv(N, GBM)), 256, GEMM_SMEM>>>(
        a16, wain, b_atom_in, nullptr, h_all, nullptr, nullptr, nullptr,
        N, H, AIN_K, AIN_K, H, 0);
    // h_e init (bond fused) -> acat fp16 + scatter
    edge_init_kernel<<<cdiv(E2, 8), 256>>>(ei, h_all, edge_attr, W_bond_in, b_bond_in,
                                           g_e, be_e, acat, m_in, E);

    for (int depth = 0; depth < DEPTH; depth++) {
        // fused gather + msg GEMM -> acat cols 0..255
        msg_gemm_kernel<<<dim3(cdiv(H, GBN), cdiv(E2, GBM)), 256, MSG_SMEM>>>(
            m_in, wmsg, ei, acat, E);
        // gin / ghn -> Gn blocked [gin | ghn]
        hgemm_kernel<2><<<dim3(cdiv(H, GBN), cdiv(E2, GBM)), 256, GEMM_SMEM>>>(
            acat, bgin, nullptr, nullptr, nullptr, Gn, nullptr, nullptr,
            E2, H, H, ACAT_W, RZ_N, 0);
        hgemm_kernel<2><<<dim3(cdiv(H, GBN), cdiv(E2, GBM)), 256, GEMM_SMEM>>>(
            acat + H, bghn, nullptr, nullptr, nullptr, Gn, nullptr, nullptr,
            E2, H, H, ACAT_W, RZ_N, 256);
        zero_kernel<<<1024, 256>>>((float4*)m_in, minN4);
        // rz GEMM + fused GRU -> hpre fp16
        hgemm_kernel<3><<<dim3(cdiv(RZ_N, GBN), cdiv(E2, GBM)), 256, GEMM_SMEM>>>(
            acat, brz, rzbias, nbias, nullptr, hpre, Gn, acat,
            E2, RZ_N, ACAT_W, ACAT_W, RZ_N, 0);
        // LN + scatter; intermediate -> acat fp16, last depth -> fp32 out_he
        if (depth < DEPTH - 1)
            ln_scatter_kernel<true><<<cdiv(E2, 8), 256>>>(hpre, ei, g_e, be_e, nullptr, acat, m_in, E);
        else
            ln_scatter_kernel<false><<<cdiv(E2, 8), 256>>>(hpre, ei, g_e, be_e, out_he, nullptr, m_in, E);
    }

    // m_to_atom accumulated by last ln_scatter
    convert_min_kernel<<<2048, 256>>>(m_in, aao, N);

    // h_atom = LN(relu([a_all | m_to_atom] @ W_atom_out + b))
    hgemm_kernel<0><<<dim3(cdiv(H, GBN), cdiv(N, GBM)), 256, GEMM_SMEM>>>(
        aao, wao, b_atom_out, nullptr, h_all, nullptr, nullptr, nullptr,
        N, H, AO_K, AO_K, H, 0);
    zero_kernel<<<64, 256>>>((float4*)hgraph, (size_t)NUM_GRAPHS * H / 4);
    relu_ln_graph_kernel<<<cdiv(N, 8), 256>>>(h_all, batch, g_a, be_a, out_hatom, hgraph, N);
    readout_kernel<<<NUM_GRAPHS, 32>>>(hgraph, W_read, b_read, out);
}